// round 2
// baseline (speedup 1.0000x reference)
#include <cuda_runtime.h>
#include <math.h>

// Problem constants
#define BB 2
#define TT 2048
#define HH 16
#define DD 64      // HEAD
#define MM 1024    // D_MODEL

// Scratch (device globals; no allocation allowed)
__device__ float g_A[HH * DD * DD];          // A_h = Wq_h Wk_h^T / 8   [h][d][d']
__device__ float g_U[MM * MM];               // U[h*64+d][n] = sum_m Wv[h][d][m] Wo[h*M+m][n]
__device__ float g_y[BB * HH * TT * DD];     // y[bh][t][d'] = xh @ A_h
__device__ float g_z[BB * TT * MM];          // z[b][t][h*64+d] = softmax(y xh^T) @ xh

// ---------------------------------------------------------------------------
// Kernel 1: A_h = (Wq_h @ Wk_h^T) * 0.125     (16 GEMMs 64x64x1024)
// grid: 16 (h), block: 256
// ---------------------------------------------------------------------------
__global__ void __launch_bounds__(256) computeA(const float* __restrict__ Wq,
                                                const float* __restrict__ Wk) {
    const int h = blockIdx.x;
    const int tid = threadIdx.x;
    const int tx = tid & 15;   // j group
    const int ty = tid >> 4;   // i group

    __shared__ float wqs[64 * 65];
    __shared__ float wks[64 * 65];

    float acc[4][4];
#pragma unroll
    for (int i = 0; i < 4; i++)
#pragma unroll
        for (int j = 0; j < 4; j++) acc[i][j] = 0.f;

    const float* wqh = Wq + (size_t)h * DD * MM;
    const float* wkh = Wk + (size_t)h * DD * MM;

    for (int m0 = 0; m0 < MM; m0 += 64) {
        __syncthreads();
#pragma unroll
        for (int c = 0; c < 4; c++) {
            int fi = tid + c * 256;      // 0..1023 float4 index
            int i = fi >> 4;             // 0..63
            int q = fi & 15;             // 0..15
            float4 a = *(const float4*)(wqh + i * MM + m0 + q * 4);
            wqs[i * 65 + q * 4 + 0] = a.x;
            wqs[i * 65 + q * 4 + 1] = a.y;
            wqs[i * 65 + q * 4 + 2] = a.z;
            wqs[i * 65 + q * 4 + 3] = a.w;
            float4 b = *(const float4*)(wkh + i * MM + m0 + q * 4);
            wks[i * 65 + q * 4 + 0] = b.x;
            wks[i * 65 + q * 4 + 1] = b.y;
            wks[i * 65 + q * 4 + 2] = b.z;
            wks[i * 65 + q * 4 + 3] = b.w;
        }
        __syncthreads();

        for (int m = 0; m < 64; m++) {
            float a[4], b[4];
#pragma unroll
            for (int i = 0; i < 4; i++) a[i] = wqs[(ty * 4 + i) * 65 + m];
#pragma unroll
            for (int j = 0; j < 4; j++) b[j] = wks[(tx * 4 + j) * 65 + m];
#pragma unroll
            for (int i = 0; i < 4; i++)
#pragma unroll
                for (int j = 0; j < 4; j++) acc[i][j] += a[i] * b[j];
        }
    }

    float* out = g_A + h * DD * DD;
#pragma unroll
    for (int i = 0; i < 4; i++)
#pragma unroll
        for (int j = 0; j < 4; j++)
            out[(ty * 4 + i) * DD + tx * 4 + j] = acc[i][j] * 0.125f;
}

// ---------------------------------------------------------------------------
// Kernel 2: U[h*64+d][n] = sum_m Wv[h][d][m] * Wo[h*M+m][n]
// grid: (8 col-tiles of 128, 16 h), block: 256; tile 64 rows x 128 cols
// ---------------------------------------------------------------------------
__global__ void __launch_bounds__(256) computeU(const float* __restrict__ Wv,
                                                const float* __restrict__ Wo) {
    const int h = blockIdx.y;
    const int col0 = blockIdx.x * 128;
    const int tid = threadIdx.x;
    const int tx = tid & 31;   // cols tx + 32*j
    const int ty = tid >> 5;   // rows ty*8 + i

    __shared__ float at[32 * 66];    // at[k][i]  (Wv chunk transposed)
    __shared__ float bs[32 * 128];   // bs[k][j]

    float acc[8][4];
#pragma unroll
    for (int i = 0; i < 8; i++)
#pragma unroll
        for (int j = 0; j < 4; j++) acc[i][j] = 0.f;

    const float* wvh = Wv + (size_t)h * DD * MM;
    const float* woh = Wo + (size_t)h * MM * MM;

    for (int m0 = 0; m0 < MM; m0 += 32) {
        __syncthreads();
#pragma unroll
        for (int c = 0; c < 2; c++) {
            int fi = tid + c * 256;      // 0..511
            int i = fi >> 3;             // 0..63
            int kq = fi & 7;             // 0..7
            float4 a = *(const float4*)(wvh + i * MM + m0 + kq * 4);
            at[(kq * 4 + 0) * 66 + i] = a.x;
            at[(kq * 4 + 1) * 66 + i] = a.y;
            at[(kq * 4 + 2) * 66 + i] = a.z;
            at[(kq * 4 + 3) * 66 + i] = a.w;
        }
#pragma unroll
        for (int c = 0; c < 4; c++) {
            int fi = tid + c * 256;      // 0..1023
            int kk = fi >> 5;            // 0..31
            int q = fi & 31;             // 0..31
            float4 b = *(const float4*)(woh + (size_t)(m0 + kk) * MM + col0 + q * 4);
            *(float4*)(bs + kk * 128 + q * 4) = b;
        }
        __syncthreads();

        for (int k = 0; k < 32; k++) {
            float a[8], b[4];
#pragma unroll
            for (int i = 0; i < 8; i++) a[i] = at[k * 66 + ty * 8 + i];
#pragma unroll
            for (int j = 0; j < 4; j++) b[j] = bs[k * 128 + tx + 32 * j];
#pragma unroll
            for (int i = 0; i < 8; i++)
#pragma unroll
                for (int j = 0; j < 4; j++) acc[i][j] += a[i] * b[j];
        }
    }

#pragma unroll
    for (int i = 0; i < 8; i++)
#pragma unroll
        for (int j = 0; j < 4; j++)
            g_U[(size_t)(h * 64 + ty * 8 + i) * MM + col0 + tx + 32 * j] = acc[i][j];
}

// ---------------------------------------------------------------------------
// Kernel 3: y[bh][t][d'] = sum_d x[b][t][h*64+d] * A[h][d][d']
// grid: (T/64 = 32, B*H = 32), block 256; tile 64 rows x 64 cols
// ---------------------------------------------------------------------------
__global__ void __launch_bounds__(256) computeY(const float* __restrict__ x) {
    const int t0 = blockIdx.x * 64;
    const int bh = blockIdx.y;
    const int b = bh >> 4;
    const int h = bh & 15;
    const int tid = threadIdx.x;
    const int tx = tid & 15;   // cols tx*4 + c
    const int ty = tid >> 4;   // rows ty*4 + i

    __shared__ float As[64 * 66];   // As[d][d']
    __shared__ float xs[64 * 65];   // xs[r][d]

    const float* ah = g_A + h * DD * DD;
#pragma unroll
    for (int c = 0; c < 4; c++) {
        int fi = tid + c * 256;   // 0..1023
        int d = fi >> 4;
        int q = fi & 15;
        float4 a = *(const float4*)(ah + d * 64 + q * 4);
        As[d * 66 + q * 4 + 0] = a.x;
        As[d * 66 + q * 4 + 1] = a.y;
        As[d * 66 + q * 4 + 2] = a.z;
        As[d * 66 + q * 4 + 3] = a.w;
    }
    const float* xb = x + ((size_t)b * TT + t0) * MM + h * 64;
#pragma unroll
    for (int c = 0; c < 4; c++) {
        int fi = tid + c * 256;   // 0..1023
        int r = fi >> 4;          // 0..63
        int q = fi & 15;
        float4 v = *(const float4*)(xb + (size_t)r * MM + q * 4);
        xs[r * 65 + q * 4 + 0] = v.x;
        xs[r * 65 + q * 4 + 1] = v.y;
        xs[r * 65 + q * 4 + 2] = v.z;
        xs[r * 65 + q * 4 + 3] = v.w;
    }
    __syncthreads();

    float acc[4][4];
#pragma unroll
    for (int i = 0; i < 4; i++)
#pragma unroll
        for (int c = 0; c < 4; c++) acc[i][c] = 0.f;

    for (int d = 0; d < 64; d++) {
        float a[4], bfr[4];
#pragma unroll
        for (int i = 0; i < 4; i++) a[i] = xs[(ty * 4 + i) * 65 + d];
#pragma unroll
        for (int c = 0; c < 4; c++) bfr[c] = As[d * 66 + tx * 4 + c];
#pragma unroll
        for (int i = 0; i < 4; i++)
#pragma unroll
            for (int c = 0; c < 4; c++) acc[i][c] += a[i] * bfr[c];
    }

    float* yb = g_y + ((size_t)bh * TT + t0) * DD;
#pragma unroll
    for (int i = 0; i < 4; i++) {
        float4 o = make_float4(acc[i][0], acc[i][1], acc[i][2], acc[i][3]);
        *(float4*)(yb + (size_t)(ty * 4 + i) * DD + tx * 4) = o;
    }
}

// ---------------------------------------------------------------------------
// Kernel 4: flash attention, K = V = xh_h, Q = y.  z[b][t][h*64+d]
// grid: (T/128 = 16, B*H = 32), block 256, dynamic smem 166400 B
// ---------------------------------------------------------------------------
#define FLASH_SMEM (size_t)((2 * 64 * 129 + 128 * 68 + 128 * 128) * 4)

__global__ void __launch_bounds__(256, 1) flashKernel(const float* __restrict__ x) {
    const int tid = threadIdx.x;
    const int tx = tid & 15;   // S cols tx + 16*j ; acc cols tx*4 + c
    const int ty = tid >> 4;   // rows ty*8 + i
    const int t0 = blockIdx.x * 128;
    const int bh = blockIdx.y;
    const int b = bh >> 4;
    const int h = bh & 15;

    extern __shared__ float sm[];
    float* Qt = sm;                       // [64][129]  Qt[d][t]
    float* Kt = sm + 64 * 129;            // [64][129]  Kt[d][s]
    float* Vs = sm + 2 * 64 * 129;        // [128][68]  Vs[s][d]
    float* Ps = sm + 2 * 64 * 129 + 128 * 68;  // [128][128]

    // Load Q tile (transposed) from g_y
    const float* yb = g_y + ((size_t)bh * TT + t0) * DD;
#pragma unroll
    for (int c = 0; c < 8; c++) {
        int fi = tid + c * 256;   // 0..2047
        int tl = fi >> 4;         // 0..127
        int q = fi & 15;
        float4 v = *(const float4*)(yb + (size_t)tl * DD + q * 4);
        Qt[(q * 4 + 0) * 129 + tl] = v.x;
        Qt[(q * 4 + 1) * 129 + tl] = v.y;
        Qt[(q * 4 + 2) * 129 + tl] = v.z;
        Qt[(q * 4 + 3) * 129 + tl] = v.w;
    }

    float acc[8][4];
    float mrow[8], lrow[8];
#pragma unroll
    for (int i = 0; i < 8; i++) {
        mrow[i] = -INFINITY;
        lrow[i] = 0.f;
#pragma unroll
        for (int c = 0; c < 4; c++) acc[i][c] = 0.f;
    }

    const float* xb = x + (size_t)b * TT * MM + h * 64;

    for (int s0 = 0; s0 < TT; s0 += 128) {
        __syncthreads();   // previous gemm2 done; also covers Q-load on iter 0
        // Load K/V tile (K transposed, V row-major)
#pragma unroll
        for (int c = 0; c < 8; c++) {
            int fi = tid + c * 256;
            int sl = fi >> 4;
            int q = fi & 15;
            float4 v = *(const float4*)(xb + (size_t)(s0 + sl) * MM + q * 4);
            Kt[(q * 4 + 0) * 129 + sl] = v.x;
            Kt[(q * 4 + 1) * 129 + sl] = v.y;
            Kt[(q * 4 + 2) * 129 + sl] = v.z;
            Kt[(q * 4 + 3) * 129 + sl] = v.w;
            *(float4*)(Vs + sl * 68 + q * 4) = v;
        }
        __syncthreads();

        // GEMM1: S = Q @ K^T (inner dim 64)
        float sfrag[8][8];
#pragma unroll
        for (int i = 0; i < 8; i++)
#pragma unroll
            for (int j = 0; j < 8; j++) sfrag[i][j] = 0.f;

        for (int d = 0; d < 64; d++) {
            float a[8], bfr[8];
#pragma unroll
            for (int i = 0; i < 8; i++) a[i] = Qt[d * 129 + ty * 8 + i];
#pragma unroll
            for (int j = 0; j < 8; j++) bfr[j] = Kt[d * 129 + tx + 16 * j];
#pragma unroll
            for (int i = 0; i < 8; i++)
#pragma unroll
                for (int j = 0; j < 8; j++) sfrag[i][j] += a[i] * bfr[j];
        }

        // Online softmax update (row groups of 16 lanes share rows)
#pragma unroll
        for (int i = 0; i < 8; i++) {
            float mx = sfrag[i][0];
#pragma unroll
            for (int j = 1; j < 8; j++) mx = fmaxf(mx, sfrag[i][j]);
#pragma unroll
            for (int o = 8; o >= 1; o >>= 1)
                mx = fmaxf(mx, __shfl_xor_sync(0xffffffffu, mx, o));
            float mnew = fmaxf(mrow[i], mx);
            float scale = __expf(mrow[i] - mnew);
            mrow[i] = mnew;
            float rs = 0.f;
#pragma unroll
            for (int j = 0; j < 8; j++) {
                float p = __expf(sfrag[i][j] - mnew);
                sfrag[i][j] = p;
                rs += p;
            }
#pragma unroll
            for (int o = 8; o >= 1; o >>= 1)
                rs += __shfl_xor_sync(0xffffffffu, rs, o);
            lrow[i] = lrow[i] * scale + rs;
#pragma unroll
            for (int c = 0; c < 4; c++) acc[i][c] *= scale;
        }

        // Write P to SMEM
#pragma unroll
        for (int i = 0; i < 8; i++)
#pragma unroll
            for (int j = 0; j < 8; j++)
                Ps[(ty * 8 + i) * 128 + tx + 16 * j] = sfrag[i][j];
        __syncthreads();

        // GEMM2: acc += P @ V  (V = K tile)
        for (int s = 0; s < 128; s++) {
            float4 v = *(const float4*)(Vs + s * 68 + tx * 4);
#pragma unroll
            for (int i = 0; i < 8; i++) {
                float p = Ps[(ty * 8 + i) * 128 + s];
                acc[i][0] += p * v.x;
                acc[i][1] += p * v.y;
                acc[i][2] += p * v.z;
                acc[i][3] += p * v.w;
            }
        }
    }

    // Write z (normalized), laid out [b][t][h*64+d] for the epilogue GEMM
    float* zb = g_z + ((size_t)b * TT + t0) * MM + h * 64;
#pragma unroll
    for (int i = 0; i < 8; i++) {
        float inv = 1.f / lrow[i];
        float4 o = make_float4(acc[i][0] * inv, acc[i][1] * inv,
                               acc[i][2] * inv, acc[i][3] * inv);
        *(float4*)(zb + (size_t)(ty * 8 + i) * MM + tx * 4) = o;
    }
}

// ---------------------------------------------------------------------------
// Kernel 5: out = z @ U + bo    (4096 x 1024 x 1024)
// grid: (8 col-tiles, 32 row-tiles), block 256; tile 128x128, micro 8x8
// ---------------------------------------------------------------------------
__global__ void __launch_bounds__(256) gemmOut(const float* __restrict__ bo,
                                               float* __restrict__ out) {
    const int col0 = blockIdx.x * 128;
    const int row0 = blockIdx.y * 128;
    const int tid = threadIdx.x;
    const int tx = tid & 15;   // cols tx + 16*j
    const int ty = tid >> 4;   // rows ty*8 + i

    __shared__ float zt[32 * 132];   // zt[k][r]
    __shared__ float us[32 * 128];   // us[k][col]

    float acc[8][8];
#pragma unroll
    for (int i = 0; i < 8; i++)
#pragma unroll
        for (int j = 0; j < 8; j++) acc[i][j] = 0.f;

    for (int k0 = 0; k0 < MM; k0 += 32) {
        __syncthreads();
#pragma unroll
        for (int c = 0; c < 4; c++) {
            int fi = tid + c * 256;   // 0..1023
            int r = fi >> 3;          // 0..127
            int kq = fi & 7;          // 0..7
            float4 a = *(const float4*)(g_z + (size_t)(row0 + r) * MM + k0 + kq * 4);
            zt[(kq * 4 + 0) * 132 + r] = a.x;
            zt[(kq * 4 + 1) * 132 + r] = a.y;
            zt[(kq * 4 + 2) * 132 + r] = a.z;
            zt[(kq * 4 + 3) * 132 + r] = a.w;
        }
#pragma unroll
        for (int c = 0; c < 4; c++) {
            int fi = tid + c * 256;
            int kk = fi >> 5;         // 0..31
            int q = fi & 31;          // 0..31
            float4 u = *(const float4*)(g_U + (size_t)(k0 + kk) * MM + col0 + q * 4);
            *(float4*)(us + kk * 128 + q * 4) = u;
        }
        __syncthreads();

        for (int k = 0; k < 32; k++) {
            float a[8], bfr[8];
#pragma unroll
            for (int i = 0; i < 8; i++) a[i] = zt[k * 132 + ty * 8 + i];
#pragma unroll
            for (int j = 0; j < 8; j++) bfr[j] = us[k * 128 + tx + 16 * j];
#pragma unroll
            for (int i = 0; i < 8; i++)
#pragma unroll
                for (int j = 0; j < 8; j++) acc[i][j] += a[i] * bfr[j];
        }
    }

    float bj[8];
#pragma unroll
    for (int j = 0; j < 8; j++) bj[j] = bo[col0 + tx + 16 * j];
#pragma unroll
    for (int i = 0; i < 8; i++)
#pragma unroll
        for (int j = 0; j < 8; j++)
            out[(size_t)(row0 + ty * 8 + i) * MM + col0 + tx + 16 * j] = acc[i][j] + bj[j];
}

// ---------------------------------------------------------------------------
extern "C" void kernel_launch(void* const* d_in, const int* in_sizes, int n_in,
                              void* d_out, int out_size) {
    const float* x  = (const float*)d_in[0];
    const float* Wq = (const float*)d_in[1];
    const float* Wk = (const float*)d_in[2];
    const float* Wv = (const float*)d_in[3];
    const float* Wo = (const float*)d_in[4];
    const float* bo = (const float*)d_in[5];
    float* out = (float*)d_out;

    cudaFuncSetAttribute(flashKernel, cudaFuncAttributeMaxDynamicSharedMemorySize,
                         (int)FLASH_SMEM);

    computeA<<<16, 256>>>(Wq, Wk);
    computeU<<<dim3(8, 16), 256>>>(Wv, Wo);
    computeY<<<dim3(TT / 64, BB * HH), 256>>>(x);
    flashKernel<<<dim3(TT / 128, BB * HH), 256, FLASH_SMEM>>>(x);
    gemmOut<<<dim3(MM / 128, (BB * TT) / 128), 256>>>(bo, out);
}

// round 3
// speedup vs baseline: 2.5540x; 2.5540x over previous
#include <cuda_runtime.h>
#include <cuda_bf16.h>
#include <math.h>
#include <stdint.h>

#define BB 2
#define TT 2048
#define HH 16
#define DD 64
#define MM 1024

__device__ float g_A[HH * DD * DD];
__device__ float g_U[MM * MM];
__device__ float g_y[BB * HH * TT * DD];
__device__ float g_z[BB * TT * MM];

__device__ __forceinline__ uint32_t pk(float a, float b) {
    __nv_bfloat162 t = __floats2bfloat162_rn(a, b);
    return *reinterpret_cast<uint32_t*>(&t);
}
__device__ __forceinline__ float bfh(float x) {
    return __bfloat162float(__float2bfloat16_rn(x));
}

#define LDSM4(R, A) asm volatile( \
    "ldmatrix.sync.aligned.m8n8.x4.shared.b16 {%0,%1,%2,%3},[%4];" \
    : "=r"((R)[0]), "=r"((R)[1]), "=r"((R)[2]), "=r"((R)[3]) : "r"(A))
#define LDSM4T(R, A) asm volatile( \
    "ldmatrix.sync.aligned.m8n8.x4.trans.shared.b16 {%0,%1,%2,%3},[%4];" \
    : "=r"((R)[0]), "=r"((R)[1]), "=r"((R)[2]), "=r"((R)[3]) : "r"(A))
#define MMAB(D, A, B0, B1) asm volatile( \
    "mma.sync.aligned.m16n8k16.row.col.f32.bf16.bf16.f32 " \
    "{%0,%1,%2,%3},{%4,%5,%6,%7},{%8,%9},{%0,%1,%2,%3};" \
    : "+f"((D)[0]), "+f"((D)[1]), "+f"((D)[2]), "+f"((D)[3]) \
    : "r"((A)[0]), "r"((A)[1]), "r"((A)[2]), "r"((A)[3]), "r"(B0), "r"(B1))

// ---------------------------------------------------------------------------
// Kernel 1: A_h = (Wq_h @ Wk_h^T) * 0.125
// ---------------------------------------------------------------------------
__global__ void __launch_bounds__(256) computeA(const float* __restrict__ Wq,
                                                const float* __restrict__ Wk) {
    const int h = blockIdx.x, tid = threadIdx.x;
    const int tx = tid & 15, ty = tid >> 4;
    __shared__ float wqs[64 * 65];
    __shared__ float wks[64 * 65];
    float acc[4][4];
#pragma unroll
    for (int i = 0; i < 4; i++)
#pragma unroll
        for (int j = 0; j < 4; j++) acc[i][j] = 0.f;
    const float* wqh = Wq + (size_t)h * DD * MM;
    const float* wkh = Wk + (size_t)h * DD * MM;
    for (int m0 = 0; m0 < MM; m0 += 64) {
        __syncthreads();
#pragma unroll
        for (int c = 0; c < 4; c++) {
            int fi = tid + c * 256, i = fi >> 4, q = fi & 15;
            float4 a = *(const float4*)(wqh + i * MM + m0 + q * 4);
            wqs[i * 65 + q * 4 + 0] = a.x; wqs[i * 65 + q * 4 + 1] = a.y;
            wqs[i * 65 + q * 4 + 2] = a.z; wqs[i * 65 + q * 4 + 3] = a.w;
            float4 b = *(const float4*)(wkh + i * MM + m0 + q * 4);
            wks[i * 65 + q * 4 + 0] = b.x; wks[i * 65 + q * 4 + 1] = b.y;
            wks[i * 65 + q * 4 + 2] = b.z; wks[i * 65 + q * 4 + 3] = b.w;
        }
        __syncthreads();
        for (int m = 0; m < 64; m++) {
            float a[4], b[4];
#pragma unroll
            for (int i = 0; i < 4; i++) a[i] = wqs[(ty * 4 + i) * 65 + m];
#pragma unroll
            for (int j = 0; j < 4; j++) b[j] = wks[(tx * 4 + j) * 65 + m];
#pragma unroll
            for (int i = 0; i < 4; i++)
#pragma unroll
                for (int j = 0; j < 4; j++) acc[i][j] += a[i] * b[j];
        }
    }
    float* o = g_A + h * DD * DD;
#pragma unroll
    for (int i = 0; i < 4; i++)
#pragma unroll
        for (int j = 0; j < 4; j++)
            o[(ty * 4 + i) * DD + tx * 4 + j] = acc[i][j] * 0.125f;
}

// ---------------------------------------------------------------------------
// Kernel 2: U[h*64+d][n] = sum_m Wv[h][d][m] * Wo[h*M+m][n]
// ---------------------------------------------------------------------------
__global__ void __launch_bounds__(256) computeU(const float* __restrict__ Wv,
                                                const float* __restrict__ Wo) {
    const int h = blockIdx.y, col0 = blockIdx.x * 128, tid = threadIdx.x;
    const int tx = tid & 31, ty = tid >> 5;
    __shared__ float at[32 * 66];
    __shared__ float bs[32 * 128];
    float acc[8][4];
#pragma unroll
    for (int i = 0; i < 8; i++)
#pragma unroll
        for (int j = 0; j < 4; j++) acc[i][j] = 0.f;
    const float* wvh = Wv + (size_t)h * DD * MM;
    const float* woh = Wo + (size_t)h * MM * MM;
    for (int m0 = 0; m0 < MM; m0 += 32) {
        __syncthreads();
#pragma unroll
        for (int c = 0; c < 2; c++) {
            int fi = tid + c * 256, i = fi >> 3, kq = fi & 7;
            float4 a = *(const float4*)(wvh + i * MM + m0 + kq * 4);
            at[(kq * 4 + 0) * 66 + i] = a.x; at[(kq * 4 + 1) * 66 + i] = a.y;
            at[(kq * 4 + 2) * 66 + i] = a.z; at[(kq * 4 + 3) * 66 + i] = a.w;
        }
#pragma unroll
        for (int c = 0; c < 4; c++) {
            int fi = tid + c * 256, kk = fi >> 5, q = fi & 31;
            float4 b = *(const float4*)(woh + (size_t)(m0 + kk) * MM + col0 + q * 4);
            *(float4*)(bs + kk * 128 + q * 4) = b;
        }
        __syncthreads();
        for (int k = 0; k < 32; k++) {
            float a[8], b[4];
#pragma unroll
            for (int i = 0; i < 8; i++) a[i] = at[k * 66 + ty * 8 + i];
#pragma unroll
            for (int j = 0; j < 4; j++) b[j] = bs[k * 128 + tx + 32 * j];
#pragma unroll
            for (int i = 0; i < 8; i++)
#pragma unroll
                for (int j = 0; j < 4; j++) acc[i][j] += a[i] * b[j];
        }
    }
#pragma unroll
    for (int i = 0; i < 8; i++)
#pragma unroll
        for (int j = 0; j < 4; j++)
            g_U[(size_t)(h * 64 + ty * 8 + i) * MM + col0 + tx + 32 * j] = acc[i][j];
}

// ---------------------------------------------------------------------------
// Kernel 3: y = xh @ A_h
// ---------------------------------------------------------------------------
__global__ void __launch_bounds__(256) computeY(const float* __restrict__ x) {
    const int t0 = blockIdx.x * 64, bh = blockIdx.y;
    const int b = bh >> 4, h = bh & 15, tid = threadIdx.x;
    const int tx = tid & 15, ty = tid >> 4;
    __shared__ float As[64 * 66];
    __shared__ float xs[64 * 65];
    const float* ah = g_A + h * DD * DD;
#pragma unroll
    for (int c = 0; c < 4; c++) {
        int fi = tid + c * 256, d = fi >> 4, q = fi & 15;
        float4 a = *(const float4*)(ah + d * 64 + q * 4);
        As[d * 66 + q * 4 + 0] = a.x; As[d * 66 + q * 4 + 1] = a.y;
        As[d * 66 + q * 4 + 2] = a.z; As[d * 66 + q * 4 + 3] = a.w;
    }
    const float* xb = x + ((size_t)b * TT + t0) * MM + h * 64;
#pragma unroll
    for (int c = 0; c < 4; c++) {
        int fi = tid + c * 256, r = fi >> 4, q = fi & 15;
        float4 v = *(const float4*)(xb + (size_t)r * MM + q * 4);
        xs[r * 65 + q * 4 + 0] = v.x; xs[r * 65 + q * 4 + 1] = v.y;
        xs[r * 65 + q * 4 + 2] = v.z; xs[r * 65 + q * 4 + 3] = v.w;
    }
    __syncthreads();
    float acc[4][4];
#pragma unroll
    for (int i = 0; i < 4; i++)
#pragma unroll
        for (int c = 0; c < 4; c++) acc[i][c] = 0.f;
    for (int d = 0; d < 64; d++) {
        float a[4], bfr[4];
#pragma unroll
        for (int i = 0; i < 4; i++) a[i] = xs[(ty * 4 + i) * 65 + d];
#pragma unroll
        for (int c = 0; c < 4; c++) bfr[c] = As[d * 66 + tx * 4 + c];
#pragma unroll
        for (int i = 0; i < 4; i++)
#pragma unroll
            for (int c = 0; c < 4; c++) acc[i][c] += a[i] * bfr[c];
    }
    float* yb = g_y + ((size_t)bh * TT + t0) * DD;
#pragma unroll
    for (int i = 0; i < 4; i++)
        *(float4*)(yb + (size_t)(ty * 4 + i) * DD + tx * 4) =
            make_float4(acc[i][0], acc[i][1], acc[i][2], acc[i][3]);
}

// ---------------------------------------------------------------------------
// Kernel 4: tensor-core flash attention (bf16 hi/lo split), K = V = xh
// block 256 (8 warps), warp w owns q-rows 16w..16w+15 of the 128-row tile
// smem: K hi/lo double-buffered [128][72]bf16 + Q hi/lo [128][72]bf16
// ---------------------------------------------------------------------------
#define FL_SMEM 110592

__global__ void __launch_bounds__(256, 1) flashTC(const float* __restrict__ x) {
    extern __shared__ __align__(16) char sm[];
    const uint32_t sb = (uint32_t)__cvta_generic_to_shared(sm);
    const uint32_t KH0 = 0u, KL0 = 18432u, KH1 = 36864u, KL1 = 55296u;
    const uint32_t QH = 73728u, QL = 92160u;
    const int tid = threadIdx.x, lane = tid & 31, w = tid >> 5;
    const int t0 = blockIdx.x * 128, bh = blockIdx.y;
    const int b = bh >> 4, h = bh & 15;
    const float* xb = x + (size_t)b * TT * MM + h * 64;

    // stage Q hi/lo from g_y
    const float* yb = g_y + ((size_t)bh * TT + t0) * DD;
#pragma unroll
    for (int c = 0; c < 8; c++) {
        int fi = tid + c * 256, r = fi >> 4, q = fi & 15;
        float4 v = *(const float4*)(yb + (size_t)r * DD + q * 4);
        float hx = bfh(v.x), hy = bfh(v.y), hz = bfh(v.z), hw = bfh(v.w);
        uint32_t o = (uint32_t)(r * 144 + q * 8);
        *(uint32_t*)(sm + QH + o) = pk(hx, hy);
        *(uint32_t*)(sm + QH + o + 4) = pk(hz, hw);
        *(uint32_t*)(sm + QL + o) = pk(v.x - hx, v.y - hy);
        *(uint32_t*)(sm + QL + o + 4) = pk(v.z - hz, v.w - hw);
    }
    // stage K tile 0
#pragma unroll
    for (int c = 0; c < 8; c++) {
        int fi = tid + c * 256, r = fi >> 4, q = fi & 15;
        float4 v = *(const float4*)(xb + (size_t)r * MM + q * 4);
        float hx = bfh(v.x), hy = bfh(v.y), hz = bfh(v.z), hw = bfh(v.w);
        uint32_t o = (uint32_t)(r * 144 + q * 8);
        *(uint32_t*)(sm + KH0 + o) = pk(hx, hy);
        *(uint32_t*)(sm + KH0 + o + 4) = pk(hz, hw);
        *(uint32_t*)(sm + KL0 + o) = pk(v.x - hx, v.y - hy);
        *(uint32_t*)(sm + KL0 + o + 4) = pk(v.z - hz, v.w - hw);
    }
    __syncthreads();

    // Q fragments (loop-invariant)
    uint32_t qh[4][4], ql[4][4];
    {
        uint32_t ro = (uint32_t)((16 * w + (lane & 15)) * 144 + ((lane >> 4) << 3) * 2);
#pragma unroll
        for (int kk = 0; kk < 4; kk++) {
            LDSM4(qh[kk], sb + QH + ro + kk * 32);
            LDSM4(ql[kk], sb + QL + ro + kk * 32);
        }
    }

    float acc[8][4];
    float mrow0 = -INFINITY, mrow1 = -INFINITY, lrow0 = 0.f, lrow1 = 0.f;
#pragma unroll
    for (int j = 0; j < 8; j++) { acc[j][0] = acc[j][1] = acc[j][2] = acc[j][3] = 0.f; }

    for (int it = 0; it < 16; it++) {
        const uint32_t curH = (it & 1) ? KH1 : KH0;
        const uint32_t curL = (it & 1) ? KL1 : KL0;
        const uint32_t nxtH = (it & 1) ? KH0 : KH1;
        const uint32_t nxtL = (it & 1) ? KL0 : KL1;

        // GEMM1: S = Q @ K^T  (16 n-blocks of 8 keys)
        float S[16][4];
#pragma unroll
        for (int j = 0; j < 16; j++) { S[j][0] = S[j][1] = S[j][2] = S[j][3] = 0.f; }
        {
            uint32_t rbase = sb + (uint32_t)(((lane & 7) + ((lane >> 4) << 3)) * 144 +
                                             (((lane >> 3) & 1) << 3) * 2);
#pragma unroll
            for (int jp = 0; jp < 8; jp++) {
#pragma unroll
                for (int kk = 0; kk < 4; kk++) {
                    uint32_t off = (uint32_t)(jp * 2304 + kk * 32);
                    uint32_t bh4[4], bl4[4];
                    LDSM4(bh4, rbase + curH + off);
                    LDSM4(bl4, rbase + curL + off);
                    MMAB(S[2 * jp], qh[kk], bh4[0], bh4[1]);
                    MMAB(S[2 * jp], qh[kk], bl4[0], bl4[1]);
                    MMAB(S[2 * jp], ql[kk], bh4[0], bh4[1]);
                    MMAB(S[2 * jp + 1], qh[kk], bh4[2], bh4[3]);
                    MMAB(S[2 * jp + 1], qh[kk], bl4[2], bl4[3]);
                    MMAB(S[2 * jp + 1], ql[kk], bh4[2], bh4[3]);
                }
            }
        }

        // prefetch next K tile (overlap with softmax)
        float4 pf[8];
        if (it < 15) {
#pragma unroll
            for (int c = 0; c < 8; c++) {
                int fi = tid + c * 256, r = fi >> 4, q = fi & 15;
                pf[c] = *(const float4*)(xb + (size_t)((it + 1) * 128 + r) * MM + q * 4);
            }
        }

        // online softmax (rows lane/4 and lane/4+8 within warp's 16)
        float mx0 = -INFINITY, mx1 = -INFINITY;
#pragma unroll
        for (int j = 0; j < 16; j++) {
            mx0 = fmaxf(mx0, fmaxf(S[j][0], S[j][1]));
            mx1 = fmaxf(mx1, fmaxf(S[j][2], S[j][3]));
        }
        mx0 = fmaxf(mx0, __shfl_xor_sync(0xffffffffu, mx0, 1));
        mx0 = fmaxf(mx0, __shfl_xor_sync(0xffffffffu, mx0, 2));
        mx1 = fmaxf(mx1, __shfl_xor_sync(0xffffffffu, mx1, 1));
        mx1 = fmaxf(mx1, __shfl_xor_sync(0xffffffffu, mx1, 2));
        float mn0 = fmaxf(mrow0, mx0), mn1 = fmaxf(mrow1, mx1);
        float sc0 = __expf(mrow0 - mn0), sc1 = __expf(mrow1 - mn1);
        mrow0 = mn0; mrow1 = mn1;

        uint32_t php[8][4], plp[8][4];
        float rs0 = 0.f, rs1 = 0.f;
#pragma unroll
        for (int j = 0; j < 16; j++) {
            float p0 = __expf(S[j][0] - mn0), p1 = __expf(S[j][1] - mn0);
            float p2 = __expf(S[j][2] - mn1), p3 = __expf(S[j][3] - mn1);
            rs0 += p0 + p1; rs1 += p2 + p3;
            float h0 = bfh(p0), h1 = bfh(p1), h2 = bfh(p2), h3 = bfh(p3);
            int ss = j >> 1, ps = (j & 1) << 1;
            php[ss][ps] = pk(h0, h1);
            php[ss][ps + 1] = pk(h2, h3);
            plp[ss][ps] = pk(p0 - h0, p1 - h1);
            plp[ss][ps + 1] = pk(p2 - h2, p3 - h3);
        }
        rs0 += __shfl_xor_sync(0xffffffffu, rs0, 1);
        rs0 += __shfl_xor_sync(0xffffffffu, rs0, 2);
        rs1 += __shfl_xor_sync(0xffffffffu, rs1, 1);
        rs1 += __shfl_xor_sync(0xffffffffu, rs1, 2);
        lrow0 = lrow0 * sc0 + rs0;
        lrow1 = lrow1 * sc1 + rs1;
#pragma unroll
        for (int j = 0; j < 8; j++) {
            acc[j][0] *= sc0; acc[j][1] *= sc0; acc[j][2] *= sc1; acc[j][3] *= sc1;
        }

        // store next K tile hi/lo
        if (it < 15) {
#pragma unroll
            for (int c = 0; c < 8; c++) {
                int fi = tid + c * 256, r = fi >> 4, q = fi & 15;
                float4 v = pf[c];
                float hx = bfh(v.x), hy = bfh(v.y), hz = bfh(v.z), hw = bfh(v.w);
                uint32_t o = (uint32_t)(r * 144 + q * 8);
                *(uint32_t*)(sm + nxtH + o) = pk(hx, hy);
                *(uint32_t*)(sm + nxtH + o + 4) = pk(hz, hw);
                *(uint32_t*)(sm + nxtL + o) = pk(v.x - hx, v.y - hy);
                *(uint32_t*)(sm + nxtL + o + 4) = pk(v.z - hz, v.w - hw);
            }
        }

        // GEMM2: acc += P @ V  (V = K tile, ldmatrix.trans)
        {
            uint32_t rbase = sb + (uint32_t)((lane & 15) * 144 + ((lane >> 4) << 3) * 2);
#pragma unroll
            for (int ss = 0; ss < 8; ss++) {
#pragma unroll
                for (int jp = 0; jp < 4; jp++) {
                    uint32_t off = (uint32_t)(ss * 2304 + jp * 32);
                    uint32_t bh4[4], bl4[4];
                    LDSM4T(bh4, rbase + curH + off);
                    LDSM4T(bl4, rbase + curL + off);
                    MMAB(acc[2 * jp], php[ss], bh4[0], bh4[1]);
                    MMAB(acc[2 * jp], php[ss], bl4[0], bl4[1]);
                    MMAB(acc[2 * jp], plp[ss], bh4[0], bh4[1]);
                    MMAB(acc[2 * jp + 1], php[ss], bh4[2], bh4[3]);
                    MMAB(acc[2 * jp + 1], php[ss], bl4[2], bl4[3]);
                    MMAB(acc[2 * jp + 1], plp[ss], bh4[2], bh4[3]);
                }
            }
        }
        __syncthreads();
    }

    // write z normalized: [b][t][h*64+d]
    float inv0 = 1.f / lrow0, inv1 = 1.f / lrow1;
    float* zb = g_z + ((size_t)b * TT + t0 + 16 * w) * MM + h * 64;
    int r0 = lane >> 2, c0 = (lane & 3) * 2;
#pragma unroll
    for (int j = 0; j < 8; j++) {
        *(float2*)(zb + (size_t)r0 * MM + 8 * j + c0) =
            make_float2(acc[j][0] * inv0, acc[j][1] * inv0);
        *(float2*)(zb + (size_t)(r0 + 8) * MM + 8 * j + c0) =
            make_float2(acc[j][2] * inv1, acc[j][3] * inv1);
    }
}

// ---------------------------------------------------------------------------
// Kernel 5: out = z @ U + bo  — tensor core bf16x3, 128x128 tile, k-chunk 32
// warp w: rows 32*(w&3) (2 rb of 16), cols 64*(w>>2) (8 n-blocks)
// ---------------------------------------------------------------------------
#define GO_SMEM 75776

__global__ void __launch_bounds__(256, 1) gemmOutTC(const float* __restrict__ bo,
                                                    float* __restrict__ out) {
    extern __shared__ __align__(16) char sm[];
    const uint32_t sb = (uint32_t)__cvta_generic_to_shared(sm);
    const uint32_t ZH[2] = {0u, 37888u}, ZL[2] = {10240u, 48128u};
    const uint32_t UH[2] = {20480u, 58368u}, UL[2] = {29184u, 67072u};
    const int tid = threadIdx.x, lane = tid & 31, w = tid >> 5;
    const int col0 = blockIdx.x * 128, row0 = blockIdx.y * 128;
    const int wr = (w & 3) * 32, wc = (w >> 2) * 64;

    // stage chunk 0
#pragma unroll
    for (int c = 0; c < 4; c++) {
        int fi = tid + c * 256, r = fi >> 3, q = fi & 7;
        float4 v = *(const float4*)(g_z + (size_t)(row0 + r) * MM + q * 4);
        float hx = bfh(v.x), hy = bfh(v.y), hz = bfh(v.z), hw = bfh(v.w);
        uint32_t o = (uint32_t)(r * 80 + q * 8);
        *(uint32_t*)(sm + ZH[0] + o) = pk(hx, hy);
        *(uint32_t*)(sm + ZH[0] + o + 4) = pk(hz, hw);
        *(uint32_t*)(sm + ZL[0] + o) = pk(v.x - hx, v.y - hy);
        *(uint32_t*)(sm + ZL[0] + o + 4) = pk(v.z - hz, v.w - hw);
    }
#pragma unroll
    for (int c = 0; c < 4; c++) {
        int fi = tid + c * 256, kk = fi >> 5, q = fi & 31;
        float4 v = *(const float4*)(g_U + (size_t)kk * MM + col0 + q * 4);
        float hx = bfh(v.x), hy = bfh(v.y), hz = bfh(v.z), hw = bfh(v.w);
        uint32_t o = (uint32_t)(kk * 272 + q * 8);
        *(uint32_t*)(sm + UH[0] + o) = pk(hx, hy);
        *(uint32_t*)(sm + UH[0] + o + 4) = pk(hz, hw);
        *(uint32_t*)(sm + UL[0] + o) = pk(v.x - hx, v.y - hy);
        *(uint32_t*)(sm + UL[0] + o + 4) = pk(v.z - hz, v.w - hw);
    }
    __syncthreads();

    float acc[2][8][4];
#pragma unroll
    for (int rb = 0; rb < 2; rb++)
#pragma unroll
        for (int j = 0; j < 8; j++)
            acc[rb][j][0] = acc[rb][j][1] = acc[rb][j][2] = acc[rb][j][3] = 0.f;

    for (int it = 0; it < 32; it++) {
        const int cur = it & 1, nx = cur ^ 1;
        // prefetch next chunk
        float4 pz[4], pu[4];
        if (it < 31) {
            int k0 = (it + 1) * 32;
#pragma unroll
            for (int c = 0; c < 4; c++) {
                int fi = tid + c * 256, r = fi >> 3, q = fi & 7;
                pz[c] = *(const float4*)(g_z + (size_t)(row0 + r) * MM + k0 + q * 4);
            }
#pragma unroll
            for (int c = 0; c < 4; c++) {
                int fi = tid + c * 256, kk = fi >> 5, q = fi & 31;
                pu[c] = *(const float4*)(g_U + (size_t)(k0 + kk) * MM + col0 + q * 4);
            }
        }

        uint32_t abase = sb + (uint32_t)((wr + (lane & 15)) * 80 + ((lane >> 4) << 3) * 2);
        uint32_t bbase = sb + (uint32_t)((lane & 15) * 272 + (wc + ((lane >> 4) << 3)) * 2);
#pragma unroll
        for (int kk = 0; kk < 2; kk++) {
            uint32_t ah0[4], al0[4], ah1[4], al1[4];
            LDSM4(ah0, abase + ZH[cur] + kk * 32);
            LDSM4(al0, abase + ZL[cur] + kk * 32);
            LDSM4(ah1, abase + ZH[cur] + 1280 + kk * 32);
            LDSM4(al1, abase + ZL[cur] + 1280 + kk * 32);
#pragma unroll
            for (int jp = 0; jp < 4; jp++) {
                uint32_t off = (uint32_t)(kk * 4352 + jp * 32);
                uint32_t bh4[4], bl4[4];
                LDSM4T(bh4, bbase + UH[cur] + off);
                LDSM4T(bl4, bbase + UL[cur] + off);
                MMAB(acc[0][2 * jp], ah0, bh4[0], bh4[1]);
                MMAB(acc[0][2 * jp], ah0, bl4[0], bl4[1]);
                MMAB(acc[0][2 * jp], al0, bh4[0], bh4[1]);
                MMAB(acc[0][2 * jp + 1], ah0, bh4[2], bh4[3]);
                MMAB(acc[0][2 * jp + 1], ah0, bl4[2], bl4[3]);
                MMAB(acc[0][2 * jp + 1], al0, bh4[2], bh4[3]);
                MMAB(acc[1][2 * jp], ah1, bh4[0], bh4[1]);
                MMAB(acc[1][2 * jp], ah1, bl4[0], bl4[1]);
                MMAB(acc[1][2 * jp], al1, bh4[0], bh4[1]);
                MMAB(acc[1][2 * jp + 1], ah1, bh4[2], bh4[3]);
                MMAB(acc[1][2 * jp + 1], ah1, bl4[2], bl4[3]);
                MMAB(acc[1][2 * jp + 1], al1, bh4[2], bh4[3]);
            }
        }

        if (it < 31) {
#pragma unroll
            for (int c = 0; c < 4; c++) {
                int fi = tid + c * 256, r = fi >> 3, q = fi & 7;
                float4 v = pz[c];
                float hx = bfh(v.x), hy = bfh(v.y), hz = bfh(v.z), hw = bfh(v.w);
                uint32_t o = (uint32_t)(r * 80 + q * 8);
                *(uint32_t*)(sm + ZH[nx] + o) = pk(hx, hy);
                *(uint32_t*)(sm + ZH[nx] + o + 4) = pk(hz, hw);
                *(uint32_t*)(sm + ZL[nx] + o) = pk(v.x - hx, v.y - hy);
                *(uint32_t*)(sm + ZL[nx] + o + 4) = pk(v.z - hz, v.w - hw);
            }
#pragma unroll
            for (int c = 0; c < 4; c++) {
                int fi = tid + c * 256, kk = fi >> 5, q = fi & 31;
                float4 v = pu[c];
                float hx = bfh(v.x), hy = bfh(v.y), hz = bfh(v.z), hw = bfh(v.w);
                uint32_t o = (uint32_t)(kk * 272 + q * 8);
                *(uint32_t*)(sm + UH[nx] + o) = pk(hx, hy);
                *(uint32_t*)(sm + UH[nx] + o + 4) = pk(hz, hw);
                *(uint32_t*)(sm + UL[nx] + o) = pk(v.x - hx, v.y - hy);
                *(uint32_t*)(sm + UL[nx] + o + 4) = pk(v.z - hz, v.w - hw);
            }
        }
        __syncthreads();
    }

    int r = lane >> 2, cc = (lane & 3) * 2;
#pragma unroll
    for (int rb = 0; rb < 2; rb++) {
        int gr = row0 + wr + rb * 16 + r;
#pragma unroll
        for (int j = 0; j < 8; j++) {
            int gc = col0 + wc + 8 * j + cc;
            float b0v = bo[gc], b1v = bo[gc + 1];
            *(float2*)(out + (size_t)gr * MM + gc) =
                make_float2(acc[rb][j][0] + b0v, acc[rb][j][1] + b1v);
            *(float2*)(out + (size_t)(gr + 8) * MM + gc) =
                make_float2(acc[rb][j][2] + b0v, acc[rb][j][3] + b1v);
        }
    }
}

// ---------------------------------------------------------------------------
extern "C" void kernel_launch(void* const* d_in, const int* in_sizes, int n_in,
                              void* d_out, int out_size) {
    const float* x  = (const float*)d_in[0];
    const float* Wq = (const float*)d_in[1];
    const float* Wk = (const float*)d_in[2];
    const float* Wv = (const float*)d_in[3];
    const float* Wo = (const float*)d_in[4];
    const float* bo = (const float*)d_in[5];
    float* out = (float*)d_out;

    cudaFuncSetAttribute(flashTC, cudaFuncAttributeMaxDynamicSharedMemorySize, FL_SMEM);
    cudaFuncSetAttribute(gemmOutTC, cudaFuncAttributeMaxDynamicSharedMemorySize, GO_SMEM);

    computeA<<<16, 256>>>(Wq, Wk);
    computeU<<<dim3(8, 16), 256>>>(Wv, Wo);
    computeY<<<dim3(TT / 64, BB * HH), 256>>>(x);
    flashTC<<<dim3(TT / 128, BB * HH), 256, FL_SMEM>>>(x);
    gemmOutTC<<<dim3(MM / 128, (BB * TT) / 128), 256, GO_SMEM>>>(bo, out);
}

// round 4
// speedup vs baseline: 2.7075x; 1.0601x over previous
#include <cuda_runtime.h>
#include <cuda_bf16.h>
#include <math.h>
#include <stdint.h>

#define BB 2
#define TT 2048
#define HH 16
#define DD 64
#define MM 1024

// Persistent scratch (device globals)
__device__ float g_A[HH * DD * DD];                    // A_h = Wq Wk^T /8 * log2e
__device__ __nv_bfloat16 g_xh[BB * HH * TT * DD];      // x per-head, bf16 hi  [bh][t][64]
__device__ __nv_bfloat16 g_xl[BB * HH * TT * DD];      // x per-head, bf16 lo
__device__ __nv_bfloat16 g_yh[BB * HH * TT * DD];      // Q = xh@A, bf16 hi    [bh][t][64]
__device__ __nv_bfloat16 g_yl[BB * HH * TT * DD];
__device__ __nv_bfloat16 g_zh[BB * TT * MM];           // attn out, bf16 hi    [b][t][1024]
__device__ __nv_bfloat16 g_zl[BB * TT * MM];
__device__ __nv_bfloat16 g_Uh[MM * MM];                // U = Wv@Wo, bf16 hi   [1024][1024]
__device__ __nv_bfloat16 g_Ul[MM * MM];

__device__ __forceinline__ uint32_t pk(float a, float b) {
    __nv_bfloat162 t = __floats2bfloat162_rn(a, b);
    return *reinterpret_cast<uint32_t*>(&t);
}
__device__ __forceinline__ float bfh(float x) {
    return __bfloat162float(__float2bfloat16_rn(x));
}
__device__ __forceinline__ void cpa(uint32_t d, const void* s) {
    asm volatile("cp.async.cg.shared.global [%0], [%1], 16;" :: "r"(d), "l"(s));
}
#define CPCOMMIT() asm volatile("cp.async.commit_group;")
#define CPWAIT1() asm volatile("cp.async.wait_group 1;")
#define CPWAIT0() asm volatile("cp.async.wait_group 0;")

#define LDSM4(R, A) asm volatile( \
    "ldmatrix.sync.aligned.m8n8.x4.shared.b16 {%0,%1,%2,%3},[%4];" \
    : "=r"((R)[0]), "=r"((R)[1]), "=r"((R)[2]), "=r"((R)[3]) : "r"(A))
#define LDSM4T(R, A) asm volatile( \
    "ldmatrix.sync.aligned.m8n8.x4.trans.shared.b16 {%0,%1,%2,%3},[%4];" \
    : "=r"((R)[0]), "=r"((R)[1]), "=r"((R)[2]), "=r"((R)[3]) : "r"(A))
#define MMAB(D, A, B0, B1) asm volatile( \
    "mma.sync.aligned.m16n8k16.row.col.f32.bf16.bf16.f32 " \
    "{%0,%1,%2,%3},{%4,%5,%6,%7},{%8,%9},{%0,%1,%2,%3};" \
    : "+f"((D)[0]), "+f"((D)[1]), "+f"((D)[2]), "+f"((D)[3]) \
    : "r"((A)[0]), "r"((A)[1]), "r"((A)[2]), "r"((A)[3]), "r"(B0), "r"(B1))

// ---------------------------------------------------------------------------
// Kernel 0: split x into per-head bf16 hi/lo, layout [bh][t][64]
// grid 4096, block 256 — each thread handles one float4
// ---------------------------------------------------------------------------
__global__ void __launch_bounds__(256) splitX(const float* __restrict__ x) {
    int fi = blockIdx.x * 256 + threadIdx.x;     // 0 .. 1048575
    size_t e = (size_t)fi * 4;
    int b = (int)(e / ((size_t)TT * MM));
    size_t rem = e % ((size_t)TT * MM);
    int t = (int)(rem / MM);
    int col = (int)(rem % MM);
    int h = col >> 6, c = col & 63;
    float4 v = *(const float4*)(x + e);
    float hx = bfh(v.x), hy = bfh(v.y), hz = bfh(v.z), hw = bfh(v.w);
    size_t di = (((size_t)(b * 16 + h) * TT + t) * 64 + c);
    *(uint32_t*)((char*)g_xh + di * 2) = pk(hx, hy);
    *(uint32_t*)((char*)g_xh + di * 2 + 4) = pk(hz, hw);
    *(uint32_t*)((char*)g_xl + di * 2) = pk(v.x - hx, v.y - hy);
    *(uint32_t*)((char*)g_xl + di * 2 + 4) = pk(v.z - hz, v.w - hw);
}

// ---------------------------------------------------------------------------
// Kernel 1: A_h = (Wq_h @ Wk_h^T) * 0.125 * log2(e)
// ---------------------------------------------------------------------------
__global__ void __launch_bounds__(256) computeA(const float* __restrict__ Wq,
                                                const float* __restrict__ Wk) {
    const int h = blockIdx.x, tid = threadIdx.x;
    const int tx = tid & 15, ty = tid >> 4;
    __shared__ float wqs[64 * 65];
    __shared__ float wks[64 * 65];
    float acc[4][4];
#pragma unroll
    for (int i = 0; i < 4; i++)
#pragma unroll
        for (int j = 0; j < 4; j++) acc[i][j] = 0.f;
    const float* wqh = Wq + (size_t)h * DD * MM;
    const float* wkh = Wk + (size_t)h * DD * MM;
    for (int m0 = 0; m0 < MM; m0 += 64) {
        __syncthreads();
#pragma unroll
        for (int c = 0; c < 4; c++) {
            int fi = tid + c * 256, i = fi >> 4, q = fi & 15;
            float4 a = *(const float4*)(wqh + i * MM + m0 + q * 4);
            wqs[i * 65 + q * 4 + 0] = a.x; wqs[i * 65 + q * 4 + 1] = a.y;
            wqs[i * 65 + q * 4 + 2] = a.z; wqs[i * 65 + q * 4 + 3] = a.w;
            float4 b = *(const float4*)(wkh + i * MM + m0 + q * 4);
            wks[i * 65 + q * 4 + 0] = b.x; wks[i * 65 + q * 4 + 1] = b.y;
            wks[i * 65 + q * 4 + 2] = b.z; wks[i * 65 + q * 4 + 3] = b.w;
        }
        __syncthreads();
        for (int m = 0; m < 64; m++) {
            float a[4], b[4];
#pragma unroll
            for (int i = 0; i < 4; i++) a[i] = wqs[(ty * 4 + i) * 65 + m];
#pragma unroll
            for (int j = 0; j < 4; j++) b[j] = wks[(tx * 4 + j) * 65 + m];
#pragma unroll
            for (int i = 0; i < 4; i++)
#pragma unroll
                for (int j = 0; j < 4; j++) acc[i][j] += a[i] * b[j];
        }
    }
    float* o = g_A + h * DD * DD;
    const float sc = 0.125f * 1.4426950408889634f;
#pragma unroll
    for (int i = 0; i < 4; i++)
#pragma unroll
        for (int j = 0; j < 4; j++)
            o[(ty * 4 + i) * DD + tx * 4 + j] = acc[i][j] * sc;
}

// ---------------------------------------------------------------------------
// Kernel 2: U = Wv_h @ Wo_h, output bf16 hi/lo
// ---------------------------------------------------------------------------
__global__ void __launch_bounds__(256) computeU(const float* __restrict__ Wv,
                                                const float* __restrict__ Wo) {
    const int h = blockIdx.y, col0 = blockIdx.x * 128, tid = threadIdx.x;
    const int tx = tid & 31, ty = tid >> 5;
    __shared__ float at[32 * 66];
    __shared__ float bs[32 * 128];
    float acc[8][4];
#pragma unroll
    for (int i = 0; i < 8; i++)
#pragma unroll
        for (int j = 0; j < 4; j++) acc[i][j] = 0.f;
    const float* wvh = Wv + (size_t)h * DD * MM;
    const float* woh = Wo + (size_t)h * MM * MM;
    for (int m0 = 0; m0 < MM; m0 += 32) {
        __syncthreads();
#pragma unroll
        for (int c = 0; c < 2; c++) {
            int fi = tid + c * 256, i = fi >> 3, kq = fi & 7;
            float4 a = *(const float4*)(wvh + i * MM + m0 + kq * 4);
            at[(kq * 4 + 0) * 66 + i] = a.x; at[(kq * 4 + 1) * 66 + i] = a.y;
            at[(kq * 4 + 2) * 66 + i] = a.z; at[(kq * 4 + 3) * 66 + i] = a.w;
        }
#pragma unroll
        for (int c = 0; c < 4; c++) {
            int fi = tid + c * 256, kk = fi >> 5, q = fi & 31;
            float4 b = *(const float4*)(woh + (size_t)(m0 + kk) * MM + col0 + q * 4);
            *(float4*)(bs + kk * 128 + q * 4) = b;
        }
        __syncthreads();
        for (int k = 0; k < 32; k++) {
            float a[8], b[4];
#pragma unroll
            for (int i = 0; i < 8; i++) a[i] = at[k * 66 + ty * 8 + i];
#pragma unroll
            for (int j = 0; j < 4; j++) b[j] = bs[k * 128 + tx + 32 * j];
#pragma unroll
            for (int i = 0; i < 8; i++)
#pragma unroll
                for (int j = 0; j < 4; j++) acc[i][j] += a[i] * b[j];
        }
    }
#pragma unroll
    for (int i = 0; i < 8; i++)
#pragma unroll
        for (int j = 0; j < 4; j++) {
            size_t idx = (size_t)(h * 64 + ty * 8 + i) * MM + col0 + tx + 32 * j;
            float v = acc[i][j];
            float hv = bfh(v);
            g_Uh[idx] = __float2bfloat16_rn(v);
            g_Ul[idx] = __float2bfloat16_rn(v - hv);
        }
}

// ---------------------------------------------------------------------------
// Kernel 3: y = xh @ A_h, output bf16 hi/lo  [bh][t][64]
// ---------------------------------------------------------------------------
__global__ void __launch_bounds__(256) computeY(const float* __restrict__ x) {
    const int t0 = blockIdx.x * 64, bh = blockIdx.y;
    const int b = bh >> 4, h = bh & 15, tid = threadIdx.x;
    const int tx = tid & 15, ty = tid >> 4;
    __shared__ float As[64 * 66];
    __shared__ float xs[64 * 65];
    const float* ah = g_A + h * DD * DD;
#pragma unroll
    for (int c = 0; c < 4; c++) {
        int fi = tid + c * 256, d = fi >> 4, q = fi & 15;
        float4 a = *(const float4*)(ah + d * 64 + q * 4);
        As[d * 66 + q * 4 + 0] = a.x; As[d * 66 + q * 4 + 1] = a.y;
        As[d * 66 + q * 4 + 2] = a.z; As[d * 66 + q * 4 + 3] = a.w;
    }
    const float* xb = x + ((size_t)b * TT + t0) * MM + h * 64;
#pragma unroll
    for (int c = 0; c < 4; c++) {
        int fi = tid + c * 256, r = fi >> 4, q = fi & 15;
        float4 v = *(const float4*)(xb + (size_t)r * MM + q * 4);
        xs[r * 65 + q * 4 + 0] = v.x; xs[r * 65 + q * 4 + 1] = v.y;
        xs[r * 65 + q * 4 + 2] = v.z; xs[r * 65 + q * 4 + 3] = v.w;
    }
    __syncthreads();
    float acc[4][4];
#pragma unroll
    for (int i = 0; i < 4; i++)
#pragma unroll
        for (int c = 0; c < 4; c++) acc[i][c] = 0.f;
    for (int d = 0; d < 64; d++) {
        float a[4], bfr[4];
#pragma unroll
        for (int i = 0; i < 4; i++) a[i] = xs[(ty * 4 + i) * 65 + d];
#pragma unroll
        for (int c = 0; c < 4; c++) bfr[c] = As[d * 66 + tx * 4 + c];
#pragma unroll
        for (int i = 0; i < 4; i++)
#pragma unroll
            for (int c = 0; c < 4; c++) acc[i][c] += a[i] * bfr[c];
    }
    size_t base = ((size_t)bh * TT + t0) * 64;
#pragma unroll
    for (int i = 0; i < 4; i++) {
        size_t di = base + (size_t)(ty * 4 + i) * 64 + tx * 4;
        float h0 = bfh(acc[i][0]), h1 = bfh(acc[i][1]);
        float h2 = bfh(acc[i][2]), h3 = bfh(acc[i][3]);
        *(uint32_t*)((char*)g_yh + di * 2) = pk(h0, h1);
        *(uint32_t*)((char*)g_yh + di * 2 + 4) = pk(h2, h3);
        *(uint32_t*)((char*)g_yl + di * 2) = pk(acc[i][0] - h0, acc[i][1] - h1);
        *(uint32_t*)((char*)g_yl + di * 2 + 4) = pk(acc[i][2] - h2, acc[i][3] - h3);
    }
}

// ---------------------------------------------------------------------------
// Kernel 4: tensor-core flash attention, cp.async staging from pre-split bf16
// ---------------------------------------------------------------------------
#define FL_SMEM 110592

__global__ void __launch_bounds__(256, 1) flashTC() {
    extern __shared__ __align__(16) char sm[];
    const uint32_t sb = (uint32_t)__cvta_generic_to_shared(sm);
    const uint32_t KH0 = 0u, KL0 = 18432u, KH1 = 36864u, KL1 = 55296u;
    const uint32_t QH = 73728u, QL = 92160u;
    const int tid = threadIdx.x, lane = tid & 31, w = tid >> 5;
    const int t0 = blockIdx.x * 128, bh = blockIdx.y;
    const int b = bh >> 4, h = bh & 15;

    const __nv_bfloat16* xh = g_xh + (size_t)bh * TT * 64;
    const __nv_bfloat16* xl = g_xl + (size_t)bh * TT * 64;

    // Prologue: stage Q (hi/lo) + K tile 0 via cp.async
    {
        const __nv_bfloat16* yh = g_yh + ((size_t)bh * TT + t0) * 64;
        const __nv_bfloat16* yl = g_yl + ((size_t)bh * TT + t0) * 64;
#pragma unroll
        for (int c = 0; c < 4; c++) {
            int idx = tid + c * 256;       // 0..1023
            int r = idx >> 3, ch = idx & 7;
            cpa(sb + QH + r * 144 + ch * 16, yh + (size_t)r * 64 + ch * 8);
            cpa(sb + QL + r * 144 + ch * 16, yl + (size_t)r * 64 + ch * 8);
            cpa(sb + KH0 + r * 144 + ch * 16, xh + (size_t)r * 64 + ch * 8);
            cpa(sb + KL0 + r * 144 + ch * 16, xl + (size_t)r * 64 + ch * 8);
        }
        CPCOMMIT();
    }

    uint32_t qh[4][4], ql[4][4];
    float acc[8][4];
    float mrow0 = -INFINITY, mrow1 = -INFINITY, lrow0 = 0.f, lrow1 = 0.f;
#pragma unroll
    for (int j = 0; j < 8; j++) { acc[j][0] = acc[j][1] = acc[j][2] = acc[j][3] = 0.f; }

    for (int it = 0; it < 16; it++) {
        const uint32_t curH = (it & 1) ? KH1 : KH0;
        const uint32_t curL = (it & 1) ? KL1 : KL0;
        const uint32_t nxtH = (it & 1) ? KH0 : KH1;
        const uint32_t nxtL = (it & 1) ? KL0 : KL1;

        __syncthreads();   // prev iter reads of nxt-buffer done
        if (it < 15) {
            int s0 = (it + 1) * 128;
#pragma unroll
            for (int c = 0; c < 4; c++) {
                int idx = tid + c * 256;
                int r = idx >> 3, ch = idx & 7;
                cpa(sb + nxtH + r * 144 + ch * 16, xh + (size_t)(s0 + r) * 64 + ch * 8);
                cpa(sb + nxtL + r * 144 + ch * 16, xl + (size_t)(s0 + r) * 64 + ch * 8);
            }
            CPCOMMIT();
            CPWAIT1();
        } else {
            CPWAIT0();
        }
        __syncthreads();   // cur tile visible to all warps

        if (it == 0) {
            uint32_t ro = (uint32_t)((16 * w + (lane & 15)) * 144 + ((lane >> 4) << 3) * 2);
#pragma unroll
            for (int kk = 0; kk < 4; kk++) {
                LDSM4(qh[kk], sb + QH + ro + kk * 32);
                LDSM4(ql[kk], sb + QL + ro + kk * 32);
            }
        }

        // GEMM1: S = Q @ K^T (logits already in log2 domain via A scale)
        float S[16][4];
#pragma unroll
        for (int j = 0; j < 16; j++) { S[j][0] = S[j][1] = S[j][2] = S[j][3] = 0.f; }
        {
            uint32_t rbase = sb + (uint32_t)(((lane & 7) + ((lane >> 4) << 3)) * 144 +
                                             (((lane >> 3) & 1) << 3) * 2);
#pragma unroll
            for (int jp = 0; jp < 8; jp++) {
#pragma unroll
                for (int kk = 0; kk < 4; kk++) {
                    uint32_t off = (uint32_t)(jp * 2304 + kk * 32);
                    uint32_t bh4[4], bl4[4];
                    LDSM4(bh4, rbase + curH + off);
                    LDSM4(bl4, rbase + curL + off);
                    MMAB(S[2 * jp], qh[kk], bh4[0], bh4[1]);
                    MMAB(S[2 * jp], qh[kk], bl4[0], bl4[1]);
                    MMAB(S[2 * jp], ql[kk], bh4[0], bh4[1]);
                    MMAB(S[2 * jp + 1], qh[kk], bh4[2], bh4[3]);
                    MMAB(S[2 * jp + 1], qh[kk], bl4[2], bl4[3]);
                    MMAB(S[2 * jp + 1], ql[kk], bh4[2], bh4[3]);
                }
            }
        }

        // online softmax (base-2)
        float mx0 = -INFINITY, mx1 = -INFINITY;
#pragma unroll
        for (int j = 0; j < 16; j++) {
            mx0 = fmaxf(mx0, fmaxf(S[j][0], S[j][1]));
            mx1 = fmaxf(mx1, fmaxf(S[j][2], S[j][3]));
        }
        mx0 = fmaxf(mx0, __shfl_xor_sync(0xffffffffu, mx0, 1));
        mx0 = fmaxf(mx0, __shfl_xor_sync(0xffffffffu, mx0, 2));
        mx1 = fmaxf(mx1, __shfl_xor_sync(0xffffffffu, mx1, 1));
        mx1 = fmaxf(mx1, __shfl_xor_sync(0xffffffffu, mx1, 2));
        float mn0 = fmaxf(mrow0, mx0), mn1 = fmaxf(mrow1, mx1);
        float sc0 = exp2f(mrow0 - mn0), sc1 = exp2f(mrow1 - mn1);
        mrow0 = mn0; mrow1 = mn1;

        uint32_t php[8][4], plp[8][4];
        float rs0 = 0.f, rs1 = 0.f;
#pragma unroll
        for (int j = 0; j < 16; j++) {
            float p0 = exp2f(S[j][0] - mn0), p1 = exp2f(S[j][1] - mn0);
            float p2 = exp2f(S[j][2] - mn1), p3 = exp2f(S[j][3] - mn1);
            rs0 += p0 + p1; rs1 += p2 + p3;
            float h0 = bfh(p0), h1 = bfh(p1), h2 = bfh(p2), h3 = bfh(p3);
            int ss = j >> 1, ps = (j & 1) << 1;
            php[ss][ps] = pk(h0, h1);
            php[ss][ps + 1] = pk(h2, h3);
            plp[ss][ps] = pk(p0 - h0, p1 - h1);
            plp[ss][ps + 1] = pk(p2 - h2, p3 - h3);
        }
        rs0 += __shfl_xor_sync(0xffffffffu, rs0, 1);
        rs0 += __shfl_xor_sync(0xffffffffu, rs0, 2);
        rs1 += __shfl_xor_sync(0xffffffffu, rs1, 1);
        rs1 += __shfl_xor_sync(0xffffffffu, rs1, 2);
        lrow0 = lrow0 * sc0 + rs0;
        lrow1 = lrow1 * sc1 + rs1;
#pragma unroll
        for (int j = 0; j < 8; j++) {
            acc[j][0] *= sc0; acc[j][1] *= sc0; acc[j][2] *= sc1; acc[j][3] *= sc1;
        }

        // GEMM2: acc += P @ V  (V = K tile via ldmatrix.trans)
        {
            uint32_t rbase = sb + (uint32_t)((lane & 15) * 144 + ((lane >> 4) << 3) * 2);
#pragma unroll
            for (int ss = 0; ss < 8; ss++) {
#pragma unroll
                for (int jp = 0; jp < 4; jp++) {
                    uint32_t off = (uint32_t)(ss * 2304 + jp * 32);
                    uint32_t bh4[4], bl4[4];
                    LDSM4T(bh4, rbase + curH + off);
                    LDSM4T(bl4, rbase + curL + off);
                    MMAB(acc[2 * jp], php[ss], bh4[0], bh4[1]);
                    MMAB(acc[2 * jp], php[ss], bl4[0], bl4[1]);
                    MMAB(acc[2 * jp], plp[ss], bh4[0], bh4[1]);
                    MMAB(acc[2 * jp + 1], php[ss], bh4[2], bh4[3]);
                    MMAB(acc[2 * jp + 1], php[ss], bl4[2], bl4[3]);
                    MMAB(acc[2 * jp + 1], plp[ss], bh4[2], bh4[3]);
                }
            }
        }
    }

    // write z normalized as bf16 hi/lo: [b][t][h*64+d]
    float inv0 = 1.f / lrow0, inv1 = 1.f / lrow1;
    int r0 = lane >> 2, c0 = (lane & 3) * 2;
    size_t rowA = ((size_t)b * TT + t0 + 16 * w + r0) * MM + h * 64;
    size_t rowB = rowA + 8 * MM;
#pragma unroll
    for (int j = 0; j < 8; j++) {
        float o0 = acc[j][0] * inv0, o1 = acc[j][1] * inv0;
        float o2 = acc[j][2] * inv1, o3 = acc[j][3] * inv1;
        float h0 = bfh(o0), h1 = bfh(o1), h2 = bfh(o2), h3 = bfh(o3);
        size_t ia = rowA + 8 * j + c0, ib = rowB + 8 * j + c0;
        *(uint32_t*)((char*)g_zh + ia * 2) = pk(h0, h1);
        *(uint32_t*)((char*)g_zl + ia * 2) = pk(o0 - h0, o1 - h1);
        *(uint32_t*)((char*)g_zh + ib * 2) = pk(h2, h3);
        *(uint32_t*)((char*)g_zl + ib * 2) = pk(o2 - h2, o3 - h3);
    }
}

// ---------------------------------------------------------------------------
// Kernel 5: out = z @ U + bo — bf16x3 tensor core, cp.async staging
// ---------------------------------------------------------------------------
#define GO_SMEM 75776

__global__ void __launch_bounds__(256, 1) gemmOutTC(const float* __restrict__ bo,
                                                    float* __restrict__ out) {
    extern __shared__ __align__(16) char sm[];
    const uint32_t sb = (uint32_t)__cvta_generic_to_shared(sm);
    const uint32_t ZH[2] = {0u, 37888u}, ZL[2] = {10240u, 48128u};
    const uint32_t UH[2] = {20480u, 58368u}, UL[2] = {29184u, 67072u};
    const int tid = threadIdx.x, lane = tid & 31, w = tid >> 5;
    const int col0 = blockIdx.x * 128, row0 = blockIdx.y * 128;
    const int wr = (w & 3) * 32, wc = (w >> 2) * 64;

    // stage chunk 0
#pragma unroll
    for (int c = 0; c < 2; c++) {
        int idx = tid + c * 256;           // 0..511
        int r = idx >> 2, ch = idx & 3;
        cpa(sb + ZH[0] + r * 80 + ch * 16, g_zh + (size_t)(row0 + r) * MM + ch * 8);
        cpa(sb + ZL[0] + r * 80 + ch * 16, g_zl + (size_t)(row0 + r) * MM + ch * 8);
        int kk = idx >> 4, q = idx & 15;
        cpa(sb + UH[0] + kk * 272 + q * 16, g_Uh + (size_t)kk * MM + col0 + q * 8);
        cpa(sb + UL[0] + kk * 272 + q * 16, g_Ul + (size_t)kk * MM + col0 + q * 8);
    }
    CPCOMMIT();

    float acc[2][8][4];
#pragma unroll
    for (int rb = 0; rb < 2; rb++)
#pragma unroll
        for (int j = 0; j < 8; j++)
            acc[rb][j][0] = acc[rb][j][1] = acc[rb][j][2] = acc[rb][j][3] = 0.f;

    for (int it = 0; it < 32; it++) {
        const int cur = it & 1, nx = cur ^ 1;
        __syncthreads();
        if (it < 31) {
            int k0 = (it + 1) * 32;
#pragma unroll
            for (int c = 0; c < 2; c++) {
                int idx = tid + c * 256;
                int r = idx >> 2, ch = idx & 3;
                cpa(sb + ZH[nx] + r * 80 + ch * 16,
                    g_zh + (size_t)(row0 + r) * MM + k0 + ch * 8);
                cpa(sb + ZL[nx] + r * 80 + ch * 16,
                    g_zl + (size_t)(row0 + r) * MM + k0 + ch * 8);
                int kk = idx >> 4, q = idx & 15;
                cpa(sb + UH[nx] + kk * 272 + q * 16,
                    g_Uh + (size_t)(k0 + kk) * MM + col0 + q * 8);
                cpa(sb + UL[nx] + kk * 272 + q * 16,
                    g_Ul + (size_t)(k0 + kk) * MM + col0 + q * 8);
            }
            CPCOMMIT();
            CPWAIT1();
        } else {
            CPWAIT0();
        }
        __syncthreads();

        uint32_t abase = sb + (uint32_t)((wr + (lane & 15)) * 80 + ((lane >> 4) << 3) * 2);
        uint32_t bbase = sb + (uint32_t)((lane & 15) * 272 + (wc + ((lane >> 4) << 3)) * 2);
#pragma unroll
        for (int kk = 0; kk < 2; kk++) {
            uint32_t ah0[4], al0[4], ah1[4], al1[4];
            LDSM4(ah0, abase + ZH[cur] + kk * 32);
            LDSM4(al0, abase + ZL[cur] + kk * 32);
            LDSM4(ah1, abase + ZH[cur] + 1280 + kk * 32);
            LDSM4(al1, abase + ZL[cur] + 1280 + kk * 32);
#pragma unroll
            for (int jp = 0; jp < 4; jp++) {
                uint32_t off = (uint32_t)(kk * 4352 + jp * 32);
                uint32_t bh4[4], bl4[4];
                LDSM4T(bh4, bbase + UH[cur] + off);
                LDSM4T(bl4, bbase + UL[cur] + off);
                MMAB(acc[0][2 * jp], ah0, bh4[0], bh4[1]);
                MMAB(acc[0][2 * jp], ah0, bl4[0], bl4[1]);
                MMAB(acc[0][2 * jp], al0, bh4[0], bh4[1]);
                MMAB(acc[0][2 * jp + 1], ah0, bh4[2], bh4[3]);
                MMAB(acc[0][2 * jp + 1], ah0, bl4[2], bl4[3]);
                MMAB(acc[0][2 * jp + 1], al0, bh4[2], bh4[3]);
                MMAB(acc[1][2 * jp], ah1, bh4[0], bh4[1]);
                MMAB(acc[1][2 * jp], ah1, bl4[0], bl4[1]);
                MMAB(acc[1][2 * jp], al1, bh4[0], bh4[1]);
                MMAB(acc[1][2 * jp + 1], ah1, bh4[2], bh4[3]);
                MMAB(acc[1][2 * jp + 1], ah1, bl4[2], bl4[3]);
                MMAB(acc[1][2 * jp + 1], al1, bh4[2], bh4[3]);
            }
        }
    }

    int r = lane >> 2, cc = (lane & 3) * 2;
#pragma unroll
    for (int rb = 0; rb < 2; rb++) {
        int gr = row0 + wr + rb * 16 + r;
#pragma unroll
        for (int j = 0; j < 8; j++) {
            int gc = col0 + wc + 8 * j + cc;
            float b0v = bo[gc], b1v = bo[gc + 1];
            *(float2*)(out + (size_t)gr * MM + gc) =
                make_float2(acc[rb][j][0] + b0v, acc[rb][j][1] + b1v);
            *(float2*)(out + (size_t)(gr + 8) * MM + gc) =
                make_float2(acc[rb][j][2] + b0v, acc[rb][j][3] + b1v);
        }
    }
}

// ---------------------------------------------------------------------------
extern "C" void kernel_launch(void* const* d_in, const int* in_sizes, int n_in,
                              void* d_out, int out_size) {
    const float* x  = (const float*)d_in[0];
    const float* Wq = (const float*)d_in[1];
    const float* Wk = (const float*)d_in[2];
    const float* Wv = (const float*)d_in[3];
    const float* Wo = (const float*)d_in[4];
    const float* bo = (const float*)d_in[5];
    float* out = (float*)d_out;

    cudaFuncSetAttribute(flashTC, cudaFuncAttributeMaxDynamicSharedMemorySize, FL_SMEM);
    cudaFuncSetAttribute(gemmOutTC, cudaFuncAttributeMaxDynamicSharedMemorySize, GO_SMEM);

    splitX<<<4096, 256>>>(x);
    computeA<<<16, 256>>>(Wq, Wk);
    computeU<<<dim3(8, 16), 256>>>(Wv, Wo);
    computeY<<<dim3(TT / 64, BB * HH), 256>>>(x);
    flashTC<<<dim3(TT / 128, BB * HH), 256, FL_SMEM>>>();
    gemmOutTC<<<dim3(MM / 128, (BB * TT) / 128), 256, GO_SMEM>>>(bo, out);
}

// round 5
// speedup vs baseline: 2.9439x; 1.0873x over previous
#include <cuda_runtime.h>
#include <cuda_bf16.h>
#include <math.h>
#include <stdint.h>

#define BB 2
#define TT 2048
#define HH 16
#define DD 64
#define MM 1024

// Persistent scratch (device globals)
__device__ float g_A[HH * DD * DD];                    // A_h = Wq Wk^T /8 * log2e
__device__ __nv_bfloat16 g_xh[BB * HH * TT * DD];      // x per-head, bf16 hi  [bh][t][64]
__device__ __nv_bfloat16 g_xl[BB * HH * TT * DD];      // x per-head, bf16 lo
__device__ __nv_bfloat16 g_yh[BB * HH * TT * DD];      // Q = xh@A, bf16 hi    [bh][t][64]
__device__ __nv_bfloat16 g_yl[BB * HH * TT * DD];
__device__ __nv_bfloat16 g_zh[BB * TT * MM];           // attn out, bf16 hi    [b][t][1024]
__device__ __nv_bfloat16 g_zl[BB * TT * MM];
__device__ __nv_bfloat16 g_Uh[MM * MM];                // U = Wv@Wo, bf16 hi   [1024][1024]
__device__ __nv_bfloat16 g_Ul[MM * MM];

__device__ __forceinline__ uint32_t pk(float a, float b) {
    __nv_bfloat162 t = __floats2bfloat162_rn(a, b);
    return *reinterpret_cast<uint32_t*>(&t);
}
__device__ __forceinline__ float bfh(float x) {
    return __bfloat162float(__float2bfloat16_rn(x));
}
__device__ __forceinline__ void cpa(uint32_t d, const void* s) {
    asm volatile("cp.async.cg.shared.global [%0], [%1], 16;" :: "r"(d), "l"(s));
}
#define CPCOMMIT() asm volatile("cp.async.commit_group;")
#define CPWAIT1() asm volatile("cp.async.wait_group 1;")
#define CPWAIT0() asm volatile("cp.async.wait_group 0;")

#define LDSM4(R, A) asm volatile( \
    "ldmatrix.sync.aligned.m8n8.x4.shared.b16 {%0,%1,%2,%3},[%4];" \
    : "=r"((R)[0]), "=r"((R)[1]), "=r"((R)[2]), "=r"((R)[3]) : "r"(A))
#define LDSM4T(R, A) asm volatile( \
    "ldmatrix.sync.aligned.m8n8.x4.trans.shared.b16 {%0,%1,%2,%3},[%4];" \
    : "=r"((R)[0]), "=r"((R)[1]), "=r"((R)[2]), "=r"((R)[3]) : "r"(A))
#define MMAB(D, A, B0, B1) asm volatile( \
    "mma.sync.aligned.m16n8k16.row.col.f32.bf16.bf16.f32 " \
    "{%0,%1,%2,%3},{%4,%5,%6,%7},{%8,%9},{%0,%1,%2,%3};" \
    : "+f"((D)[0]), "+f"((D)[1]), "+f"((D)[2]), "+f"((D)[3]) \
    : "r"((A)[0]), "r"((A)[1]), "r"((A)[2]), "r"((A)[3]), "r"(B0), "r"(B1))

// ---------------------------------------------------------------------------
// Kernel 0: split x into per-head bf16 hi/lo, layout [bh][t][64]
// ---------------------------------------------------------------------------
__global__ void __launch_bounds__(256) splitX(const float* __restrict__ x) {
    int fi = blockIdx.x * 256 + threadIdx.x;
    size_t e = (size_t)fi * 4;
    int b = (int)(e / ((size_t)TT * MM));
    size_t rem = e % ((size_t)TT * MM);
    int t = (int)(rem / MM);
    int col = (int)(rem % MM);
    int h = col >> 6, c = col & 63;
    float4 v = *(const float4*)(x + e);
    float hx = bfh(v.x), hy = bfh(v.y), hz = bfh(v.z), hw = bfh(v.w);
    size_t di = (((size_t)(b * 16 + h) * TT + t) * 64 + c);
    *(uint32_t*)((char*)g_xh + di * 2) = pk(hx, hy);
    *(uint32_t*)((char*)g_xh + di * 2 + 4) = pk(hz, hw);
    *(uint32_t*)((char*)g_xl + di * 2) = pk(v.x - hx, v.y - hy);
    *(uint32_t*)((char*)g_xl + di * 2 + 4) = pk(v.z - hz, v.w - hw);
}

// ---------------------------------------------------------------------------
// Kernel 1: A_h = (Wq_h @ Wk_h^T) * 0.125 * log2(e)
// ---------------------------------------------------------------------------
__global__ void __launch_bounds__(256) computeA(const float* __restrict__ Wq,
                                                const float* __restrict__ Wk) {
    const int h = blockIdx.x, tid = threadIdx.x;
    const int tx = tid & 15, ty = tid >> 4;
    __shared__ float wqs[64 * 65];
    __shared__ float wks[64 * 65];
    float acc[4][4];
#pragma unroll
    for (int i = 0; i < 4; i++)
#pragma unroll
        for (int j = 0; j < 4; j++) acc[i][j] = 0.f;
    const float* wqh = Wq + (size_t)h * DD * MM;
    const float* wkh = Wk + (size_t)h * DD * MM;
    for (int m0 = 0; m0 < MM; m0 += 64) {
        __syncthreads();
#pragma unroll
        for (int c = 0; c < 4; c++) {
            int fi = tid + c * 256, i = fi >> 4, q = fi & 15;
            float4 a = *(const float4*)(wqh + i * MM + m0 + q * 4);
            wqs[i * 65 + q * 4 + 0] = a.x; wqs[i * 65 + q * 4 + 1] = a.y;
            wqs[i * 65 + q * 4 + 2] = a.z; wqs[i * 65 + q * 4 + 3] = a.w;
            float4 b = *(const float4*)(wkh + i * MM + m0 + q * 4);
            wks[i * 65 + q * 4 + 0] = b.x; wks[i * 65 + q * 4 + 1] = b.y;
            wks[i * 65 + q * 4 + 2] = b.z; wks[i * 65 + q * 4 + 3] = b.w;
        }
        __syncthreads();
        for (int m = 0; m < 64; m++) {
            float a[4], b[4];
#pragma unroll
            for (int i = 0; i < 4; i++) a[i] = wqs[(ty * 4 + i) * 65 + m];
#pragma unroll
            for (int j = 0; j < 4; j++) b[j] = wks[(tx * 4 + j) * 65 + m];
#pragma unroll
            for (int i = 0; i < 4; i++)
#pragma unroll
                for (int j = 0; j < 4; j++) acc[i][j] += a[i] * b[j];
        }
    }
    float* o = g_A + h * DD * DD;
    const float sc = 0.125f * 1.4426950408889634f;
#pragma unroll
    for (int i = 0; i < 4; i++)
#pragma unroll
        for (int j = 0; j < 4; j++)
            o[(ty * 4 + i) * DD + tx * 4 + j] = acc[i][j] * sc;
}

// ---------------------------------------------------------------------------
// Kernel 2: U = Wv_h @ Wo_h, output bf16 hi/lo
// ---------------------------------------------------------------------------
__global__ void __launch_bounds__(256) computeU(const float* __restrict__ Wv,
                                                const float* __restrict__ Wo) {
    const int h = blockIdx.y, col0 = blockIdx.x * 128, tid = threadIdx.x;
    const int tx = tid & 31, ty = tid >> 5;
    __shared__ float at[32 * 66];
    __shared__ float bs[32 * 128];
    float acc[8][4];
#pragma unroll
    for (int i = 0; i < 8; i++)
#pragma unroll
        for (int j = 0; j < 4; j++) acc[i][j] = 0.f;
    const float* wvh = Wv + (size_t)h * DD * MM;
    const float* woh = Wo + (size_t)h * MM * MM;
    for (int m0 = 0; m0 < MM; m0 += 32) {
        __syncthreads();
#pragma unroll
        for (int c = 0; c < 2; c++) {
            int fi = tid + c * 256, i = fi >> 3, kq = fi & 7;
            float4 a = *(const float4*)(wvh + i * MM + m0 + kq * 4);
            at[(kq * 4 + 0) * 66 + i] = a.x; at[(kq * 4 + 1) * 66 + i] = a.y;
            at[(kq * 4 + 2) * 66 + i] = a.z; at[(kq * 4 + 3) * 66 + i] = a.w;
        }
#pragma unroll
        for (int c = 0; c < 4; c++) {
            int fi = tid + c * 256, kk = fi >> 5, q = fi & 31;
            float4 b = *(const float4*)(woh + (size_t)(m0 + kk) * MM + col0 + q * 4);
            *(float4*)(bs + kk * 128 + q * 4) = b;
        }
        __syncthreads();
        for (int k = 0; k < 32; k++) {
            float a[8], b[4];
#pragma unroll
            for (int i = 0; i < 8; i++) a[i] = at[k * 66 + ty * 8 + i];
#pragma unroll
            for (int j = 0; j < 4; j++) b[j] = bs[k * 128 + tx + 32 * j];
#pragma unroll
            for (int i = 0; i < 8; i++)
#pragma unroll
                for (int j = 0; j < 4; j++) acc[i][j] += a[i] * b[j];
        }
    }
#pragma unroll
    for (int i = 0; i < 8; i++)
#pragma unroll
        for (int j = 0; j < 4; j++) {
            size_t idx = (size_t)(h * 64 + ty * 8 + i) * MM + col0 + tx + 32 * j;
            float v = acc[i][j];
            float hv = bfh(v);
            g_Uh[idx] = __float2bfloat16_rn(v);
            g_Ul[idx] = __float2bfloat16_rn(v - hv);
        }
}

// ---------------------------------------------------------------------------
// Kernel 3: y = xh @ A_h, output bf16 hi/lo  [bh][t][64]
// ---------------------------------------------------------------------------
__global__ void __launch_bounds__(256) computeY(const float* __restrict__ x) {
    const int t0 = blockIdx.x * 64, bh = blockIdx.y;
    const int b = bh >> 4, h = bh & 15, tid = threadIdx.x;
    const int tx = tid & 15, ty = tid >> 4;
    __shared__ float As[64 * 66];
    __shared__ float xs[64 * 65];
    const float* ah = g_A + h * DD * DD;
#pragma unroll
    for (int c = 0; c < 4; c++) {
        int fi = tid + c * 256, d = fi >> 4, q = fi & 15;
        float4 a = *(const float4*)(ah + d * 64 + q * 4);
        As[d * 66 + q * 4 + 0] = a.x; As[d * 66 + q * 4 + 1] = a.y;
        As[d * 66 + q * 4 + 2] = a.z; As[d * 66 + q * 4 + 3] = a.w;
    }
    const float* xb = x + ((size_t)b * TT + t0) * MM + h * 64;
#pragma unroll
    for (int c = 0; c < 4; c++) {
        int fi = tid + c * 256, r = fi >> 4, q = fi & 15;
        float4 v = *(const float4*)(xb + (size_t)r * MM + q * 4);
        xs[r * 65 + q * 4 + 0] = v.x; xs[r * 65 + q * 4 + 1] = v.y;
        xs[r * 65 + q * 4 + 2] = v.z; xs[r * 65 + q * 4 + 3] = v.w;
    }
    __syncthreads();
    float acc[4][4];
#pragma unroll
    for (int i = 0; i < 4; i++)
#pragma unroll
        for (int c = 0; c < 4; c++) acc[i][c] = 0.f;
    for (int d = 0; d < 64; d++) {
        float a[4], bfr[4];
#pragma unroll
        for (int i = 0; i < 4; i++) a[i] = xs[(ty * 4 + i) * 65 + d];
#pragma unroll
        for (int c = 0; c < 4; c++) bfr[c] = As[d * 66 + tx * 4 + c];
#pragma unroll
        for (int i = 0; i < 4; i++)
#pragma unroll
            for (int c = 0; c < 4; c++) acc[i][c] += a[i] * bfr[c];
    }
    size_t base = ((size_t)bh * TT + t0) * 64;
#pragma unroll
    for (int i = 0; i < 4; i++) {
        size_t di = base + (size_t)(ty * 4 + i) * 64 + tx * 4;
        float h0 = bfh(acc[i][0]), h1 = bfh(acc[i][1]);
        float h2 = bfh(acc[i][2]), h3 = bfh(acc[i][3]);
        *(uint32_t*)((char*)g_yh + di * 2) = pk(h0, h1);
        *(uint32_t*)((char*)g_yh + di * 2 + 4) = pk(h2, h3);
        *(uint32_t*)((char*)g_yl + di * 2) = pk(acc[i][0] - h0, acc[i][1] - h1);
        *(uint32_t*)((char*)g_yl + di * 2 + 4) = pk(acc[i][2] - h2, acc[i][3] - h3);
    }
}

// ---------------------------------------------------------------------------
// Kernel 4: flash attention — 128 threads (4 warps), 64-row Q tiles, 2 CTA/SM
// smem: buf0 = K tiles (even), buf1 = Q staging then K tiles (odd). 72KB.
// ---------------------------------------------------------------------------
#define FL_SMEM 73728

__global__ void __launch_bounds__(128, 2) flashTC() {
    extern __shared__ __align__(16) char sm[];
    const uint32_t sb = (uint32_t)__cvta_generic_to_shared(sm);
    const uint32_t KH0 = 0u, KL0 = 18432u, KH1 = 36864u, KL1 = 55296u;
    const uint32_t QH = KH1, QL = KL1;   // Q overlays K buffer 1
    const int tid = threadIdx.x, lane = tid & 31, w = tid >> 5;
    const int t0 = blockIdx.x * 64, bh = blockIdx.y;
    const int b = bh >> 4, h = bh & 15;

    const __nv_bfloat16* xh = g_xh + (size_t)bh * TT * 64;
    const __nv_bfloat16* xl = g_xl + (size_t)bh * TT * 64;

    // Prologue: Q (64 rows) -> buf1, K tile 0 (128 rows) -> buf0
    {
        const __nv_bfloat16* yh = g_yh + ((size_t)bh * TT + t0) * 64;
        const __nv_bfloat16* yl = g_yl + ((size_t)bh * TT + t0) * 64;
#pragma unroll
        for (int c = 0; c < 4; c++) {
            int idx = tid + c * 128;       // 0..511
            int r = idx >> 3, ch = idx & 7;
            cpa(sb + QH + r * 144 + ch * 16, yh + (size_t)r * 64 + ch * 8);
            cpa(sb + QL + r * 144 + ch * 16, yl + (size_t)r * 64 + ch * 8);
        }
#pragma unroll
        for (int c = 0; c < 8; c++) {
            int idx = tid + c * 128;       // 0..1023
            int r = idx >> 3, ch = idx & 7;
            cpa(sb + KH0 + r * 144 + ch * 16, xh + (size_t)r * 64 + ch * 8);
            cpa(sb + KL0 + r * 144 + ch * 16, xl + (size_t)r * 64 + ch * 8);
        }
        CPCOMMIT();
        CPWAIT0();
        __syncthreads();
    }

    // Q fragments (registers; buf1 free for K after loop-top barrier)
    uint32_t qh[4][4], ql[4][4];
    {
        uint32_t ro = (uint32_t)((16 * w + (lane & 15)) * 144 + ((lane >> 4) << 3) * 2);
#pragma unroll
        for (int kk = 0; kk < 4; kk++) {
            LDSM4(qh[kk], sb + QH + ro + kk * 32);
            LDSM4(ql[kk], sb + QL + ro + kk * 32);
        }
    }

    float acc[8][4];
    float mrow0 = -INFINITY, mrow1 = -INFINITY, lrow0 = 0.f, lrow1 = 0.f;
#pragma unroll
    for (int j = 0; j < 8; j++) { acc[j][0] = acc[j][1] = acc[j][2] = acc[j][3] = 0.f; }

    for (int it = 0; it < 16; it++) {
        const uint32_t curH = (it & 1) ? KH1 : KH0;
        const uint32_t curL = (it & 1) ? KL1 : KL0;
        const uint32_t nxtH = (it & 1) ? KH0 : KH1;
        const uint32_t nxtL = (it & 1) ? KL0 : KL1;

        __syncthreads();   // all warps done reading nxt buffer (Q frags on it=0)
        if (it < 15) {
            int s0 = (it + 1) * 128;
#pragma unroll
            for (int c = 0; c < 8; c++) {
                int idx = tid + c * 128;
                int r = idx >> 3, ch = idx & 7;
                cpa(sb + nxtH + r * 144 + ch * 16, xh + (size_t)(s0 + r) * 64 + ch * 8);
                cpa(sb + nxtL + r * 144 + ch * 16, xl + (size_t)(s0 + r) * 64 + ch * 8);
            }
            CPCOMMIT();
            CPWAIT1();
        } else {
            CPWAIT0();
        }
        __syncthreads();   // cur tile visible to all warps

        // GEMM1: S = Q @ K^T (logits in log2 domain via A scale)
        float S[16][4];
#pragma unroll
        for (int j = 0; j < 16; j++) { S[j][0] = S[j][1] = S[j][2] = S[j][3] = 0.f; }
        {
            uint32_t rbase = sb + (uint32_t)(((lane & 7) + ((lane >> 4) << 3)) * 144 +
                                             (((lane >> 3) & 1) << 3) * 2);
#pragma unroll
            for (int jp = 0; jp < 8; jp++) {
#pragma unroll
                for (int kk = 0; kk < 4; kk++) {
                    uint32_t off = (uint32_t)(jp * 2304 + kk * 32);
                    uint32_t bh4[4], bl4[4];
                    LDSM4(bh4, rbase + curH + off);
                    LDSM4(bl4, rbase + curL + off);
                    MMAB(S[2 * jp], qh[kk], bh4[0], bh4[1]);
                    MMAB(S[2 * jp], qh[kk], bl4[0], bl4[1]);
                    MMAB(S[2 * jp], ql[kk], bh4[0], bh4[1]);
                    MMAB(S[2 * jp + 1], qh[kk], bh4[2], bh4[3]);
                    MMAB(S[2 * jp + 1], qh[kk], bl4[2], bl4[3]);
                    MMAB(S[2 * jp + 1], ql[kk], bh4[2], bh4[3]);
                }
            }
        }

        // online softmax (base-2)
        float mx0 = -INFINITY, mx1 = -INFINITY;
#pragma unroll
        for (int j = 0; j < 16; j++) {
            mx0 = fmaxf(mx0, fmaxf(S[j][0], S[j][1]));
            mx1 = fmaxf(mx1, fmaxf(S[j][2], S[j][3]));
        }
        mx0 = fmaxf(mx0, __shfl_xor_sync(0xffffffffu, mx0, 1));
        mx0 = fmaxf(mx0, __shfl_xor_sync(0xffffffffu, mx0, 2));
        mx1 = fmaxf(mx1, __shfl_xor_sync(0xffffffffu, mx1, 1));
        mx1 = fmaxf(mx1, __shfl_xor_sync(0xffffffffu, mx1, 2));
        float mn0 = fmaxf(mrow0, mx0), mn1 = fmaxf(mrow1, mx1);
        float sc0 = exp2f(mrow0 - mn0), sc1 = exp2f(mrow1 - mn1);
        mrow0 = mn0; mrow1 = mn1;

        uint32_t php[8][4], plp[8][4];
        float rs0 = 0.f, rs1 = 0.f;
#pragma unroll
        for (int j = 0; j < 16; j++) {
            float p0 = exp2f(S[j][0] - mn0), p1 = exp2f(S[j][1] - mn0);
            float p2 = exp2f(S[j][2] - mn1), p3 = exp2f(S[j][3] - mn1);
            rs0 += p0 + p1; rs1 += p2 + p3;
            float h0 = bfh(p0), h1 = bfh(p1), h2 = bfh(p2), h3 = bfh(p3);
            int ss = j >> 1, ps = (j & 1) << 1;
            php[ss][ps] = pk(h0, h1);
            php[ss][ps + 1] = pk(h2, h3);
            plp[ss][ps] = pk(p0 - h0, p1 - h1);
            plp[ss][ps + 1] = pk(p2 - h2, p3 - h3);
        }
        rs0 += __shfl_xor_sync(0xffffffffu, rs0, 1);
        rs0 += __shfl_xor_sync(0xffffffffu, rs0, 2);
        rs1 += __shfl_xor_sync(0xffffffffu, rs1, 1);
        rs1 += __shfl_xor_sync(0xffffffffu, rs1, 2);
        lrow0 = lrow0 * sc0 + rs0;
        lrow1 = lrow1 * sc1 + rs1;
#pragma unroll
        for (int j = 0; j < 8; j++) {
            acc[j][0] *= sc0; acc[j][1] *= sc0; acc[j][2] *= sc1; acc[j][3] *= sc1;
        }

        // GEMM2: acc += P @ V  (V = K tile via ldmatrix.trans)
        {
            uint32_t rbase = sb + (uint32_t)((lane & 15) * 144 + ((lane >> 4) << 3) * 2);
#pragma unroll
            for (int ss = 0; ss < 8; ss++) {
#pragma unroll
                for (int jp = 0; jp < 4; jp++) {
                    uint32_t off = (uint32_t)(ss * 2304 + jp * 32);
                    uint32_t bh4[4], bl4[4];
                    LDSM4T(bh4, rbase + curH + off);
                    LDSM4T(bl4, rbase + curL + off);
                    MMAB(acc[2 * jp], php[ss], bh4[0], bh4[1]);
                    MMAB(acc[2 * jp], php[ss], bl4[0], bl4[1]);
                    MMAB(acc[2 * jp], plp[ss], bh4[0], bh4[1]);
                    MMAB(acc[2 * jp + 1], php[ss], bh4[2], bh4[3]);
                    MMAB(acc[2 * jp + 1], php[ss], bl4[2], bl4[3]);
                    MMAB(acc[2 * jp + 1], plp[ss], bh4[2], bh4[3]);
                }
            }
        }
    }

    // write z normalized as bf16 hi/lo: [b][t][h*64+d]
    float inv0 = 1.f / lrow0, inv1 = 1.f / lrow1;
    int r0 = lane >> 2, c0 = (lane & 3) * 2;
    size_t rowA = ((size_t)b * TT + t0 + 16 * w + r0) * MM + h * 64;
    size_t rowB = rowA + 8 * MM;
#pragma unroll
    for (int j = 0; j < 8; j++) {
        float o0 = acc[j][0] * inv0, o1 = acc[j][1] * inv0;
        float o2 = acc[j][2] * inv1, o3 = acc[j][3] * inv1;
        float h0 = bfh(o0), h1 = bfh(o1), h2 = bfh(o2), h3 = bfh(o3);
        size_t ia = rowA + 8 * j + c0, ib = rowB + 8 * j + c0;
        *(uint32_t*)((char*)g_zh + ia * 2) = pk(h0, h1);
        *(uint32_t*)((char*)g_zl + ia * 2) = pk(o0 - h0, o1 - h1);
        *(uint32_t*)((char*)g_zh + ib * 2) = pk(h2, h3);
        *(uint32_t*)((char*)g_zl + ib * 2) = pk(o2 - h2, o3 - h3);
    }
}

// ---------------------------------------------------------------------------
// Kernel 5: out = z @ U + bo — 128 threads (4 warps), 128x64 tile, 2 CTA/SM
// warp w: rows 32w..32w+31 (2 row-blocks of 16), all 64 cols (8 n-blocks)
// ---------------------------------------------------------------------------
#define GO_SMEM 59392

__global__ void __launch_bounds__(128, 2) gemmOutTC(const float* __restrict__ bo,
                                                    float* __restrict__ out) {
    extern __shared__ __align__(16) char sm[];
    const uint32_t sb = (uint32_t)__cvta_generic_to_shared(sm);
    const uint32_t ZH[2] = {0u, 29696u}, ZL[2] = {10240u, 39936u};
    const uint32_t UH[2] = {20480u, 50176u}, UL[2] = {25088u, 54784u};
    const int tid = threadIdx.x, lane = tid & 31, w = tid >> 5;
    const int col0 = blockIdx.x * 64, row0 = blockIdx.y * 128;
    const int wr = w * 32;

    // stage chunk 0
#pragma unroll
    for (int c = 0; c < 4; c++) {
        int idx = tid + c * 128;           // 0..511
        int r = idx >> 2, ch = idx & 3;
        cpa(sb + ZH[0] + r * 80 + ch * 16, g_zh + (size_t)(row0 + r) * MM + ch * 8);
        cpa(sb + ZL[0] + r * 80 + ch * 16, g_zl + (size_t)(row0 + r) * MM + ch * 8);
    }
#pragma unroll
    for (int c = 0; c < 2; c++) {
        int idx = tid + c * 128;           // 0..255
        int kk = idx >> 3, q = idx & 7;
        cpa(sb + UH[0] + kk * 144 + q * 16, g_Uh + (size_t)kk * MM + col0 + q * 8);
        cpa(sb + UL[0] + kk * 144 + q * 16, g_Ul + (size_t)kk * MM + col0 + q * 8);
    }
    CPCOMMIT();

    float acc[2][8][4];
#pragma unroll
    for (int rb = 0; rb < 2; rb++)
#pragma unroll
        for (int j = 0; j < 8; j++)
            acc[rb][j][0] = acc[rb][j][1] = acc[rb][j][2] = acc[rb][j][3] = 0.f;

    for (int it = 0; it < 32; it++) {
        const int cur = it & 1, nx = cur ^ 1;
        __syncthreads();
        if (it < 31) {
            int k0 = (it + 1) * 32;
#pragma unroll
            for (int c = 0; c < 4; c++) {
                int idx = tid + c * 128;
                int r = idx >> 2, ch = idx & 3;
                cpa(sb + ZH[nx] + r * 80 + ch * 16,
                    g_zh + (size_t)(row0 + r) * MM + k0 + ch * 8);
                cpa(sb + ZL[nx] + r * 80 + ch * 16,
                    g_zl + (size_t)(row0 + r) * MM + k0 + ch * 8);
            }
#pragma unroll
            for (int c = 0; c < 2; c++) {
                int idx = tid + c * 128;
                int kk = idx >> 3, q = idx & 7;
                cpa(sb + UH[nx] + kk * 144 + q * 16,
                    g_Uh + (size_t)(k0 + kk) * MM + col0 + q * 8);
                cpa(sb + UL[nx] + kk * 144 + q * 16,
                    g_Ul + (size_t)(k0 + kk) * MM + col0 + q * 8);
            }
            CPCOMMIT();
            CPWAIT1();
        } else {
            CPWAIT0();
        }
        __syncthreads();

        uint32_t abase = sb + (uint32_t)((wr + (lane & 15)) * 80 + ((lane >> 4) << 3) * 2);
        uint32_t bbase = sb + (uint32_t)((lane & 15) * 144 + ((lane >> 4) << 3) * 2);
#pragma unroll
        for (int kk = 0; kk < 2; kk++) {
            uint32_t ah0[4], al0[4], ah1[4], al1[4];
            LDSM4(ah0, abase + ZH[cur] + kk * 32);
            LDSM4(al0, abase + ZL[cur] + kk * 32);
            LDSM4(ah1, abase + ZH[cur] + 1280 + kk * 32);
            LDSM4(al1, abase + ZL[cur] + 1280 + kk * 32);
#pragma unroll
            for (int jp = 0; jp < 4; jp++) {
                uint32_t off = (uint32_t)(kk * 2304 + jp * 32);
                uint32_t bh4[4], bl4[4];
                LDSM4T(bh4, bbase + UH[cur] + off);
                LDSM4T(bl4, bbase + UL[cur] + off);
                MMAB(acc[0][2 * jp], ah0, bh4[0], bh4[1]);
                MMAB(acc[0][2 * jp], ah0, bl4[0], bl4[1]);
                MMAB(acc[0][2 * jp], al0, bh4[0], bh4[1]);
                MMAB(acc[0][2 * jp + 1], ah0, bh4[2], bh4[3]);
                MMAB(acc[0][2 * jp + 1], ah0, bl4[2], bl4[3]);
                MMAB(acc[0][2 * jp + 1], al0, bh4[2], bh4[3]);
                MMAB(acc[1][2 * jp], ah1, bh4[0], bh4[1]);
                MMAB(acc[1][2 * jp], ah1, bl4[0], bl4[1]);
                MMAB(acc[1][2 * jp], al1, bh4[0], bh4[1]);
                MMAB(acc[1][2 * jp + 1], ah1, bh4[2], bh4[3]);
                MMAB(acc[1][2 * jp + 1], ah1, bl4[2], bl4[3]);
                MMAB(acc[1][2 * jp + 1], al1, bh4[2], bh4[3]);
            }
        }
    }

    int r = lane >> 2, cc = (lane & 3) * 2;
#pragma unroll
    for (int rb = 0; rb < 2; rb++) {
        int gr = row0 + wr + rb * 16 + r;
#pragma unroll
        for (int j = 0; j < 8; j++) {
            int gc = col0 + 8 * j + cc;
            float b0v = bo[gc], b1v = bo[gc + 1];
            *(float2*)(out + (size_t)gr * MM + gc) =
                make_float2(acc[rb][j][0] + b0v, acc[rb][j][1] + b1v);
            *(float2*)(out + (size_t)(gr + 8) * MM + gc) =
                make_float2(acc[rb][j][2] + b0v, acc[rb][j][3] + b1v);
        }
    }
}

// ---------------------------------------------------------------------------
extern "C" void kernel_launch(void* const* d_in, const int* in_sizes, int n_in,
                              void* d_out, int out_size) {
    const float* x  = (const float*)d_in[0];
    const float* Wq = (const float*)d_in[1];
    const float* Wk = (const float*)d_in[2];
    const float* Wv = (const float*)d_in[3];
    const float* Wo = (const float*)d_in[4];
    const float* bo = (const float*)d_in[5];
    float* out = (float*)d_out;

    cudaFuncSetAttribute(flashTC, cudaFuncAttributeMaxDynamicSharedMemorySize, FL_SMEM);
    cudaFuncSetAttribute(gemmOutTC, cudaFuncAttributeMaxDynamicSharedMemorySize, GO_SMEM);

    splitX<<<4096, 256>>>(x);
    computeA<<<16, 256>>>(Wq, Wk);
    computeU<<<dim3(8, 16), 256>>>(Wv, Wo);
    computeY<<<dim3(TT / 64, BB * HH), 256>>>(x);
    flashTC<<<dim3(TT / 64, BB * HH), 128, FL_SMEM>>>();
    gemmOutTC<<<dim3(MM / 64, (BB * TT) / 128), 128, GO_SMEM>>>(bo, out);
}

// round 6
// speedup vs baseline: 3.7326x; 1.2679x over previous
#include <cuda_runtime.h>
#include <cuda_bf16.h>
#include <math.h>
#include <stdint.h>

#define BB 2
#define TT 2048
#define HH 16
#define DD 64
#define MM 1024

// Persistent scratch (device globals)
__device__ float g_A[HH * DD * DD];                    // A_h = Wq Wk^T /8 * log2e
__device__ float g_Ap[8 * HH * DD * DD];               // k-split partials for A
__device__ __nv_bfloat16 g_xh[BB * HH * TT * DD];      // x per-head, bf16 hi  [bh][t][64]
__device__ __nv_bfloat16 g_xl[BB * HH * TT * DD];      // x per-head, bf16 lo
__device__ __nv_bfloat16 g_yh[BB * HH * TT * DD];      // Q = xh@A, bf16 hi    [bh][t][64]
__device__ __nv_bfloat16 g_yl[BB * HH * TT * DD];
__device__ __nv_bfloat16 g_zh[BB * TT * MM];           // attn out, bf16 hi    [b][t][1024]
__device__ __nv_bfloat16 g_zl[BB * TT * MM];
__device__ __nv_bfloat16 g_Uh[MM * MM];                // U = Wv@Wo, bf16 hi   [1024][1024]
__device__ __nv_bfloat16 g_Ul[MM * MM];

__device__ __forceinline__ uint32_t pk(float a, float b) {
    __nv_bfloat162 t = __floats2bfloat162_rn(a, b);
    return *reinterpret_cast<uint32_t*>(&t);
}
__device__ __forceinline__ float bfh(float x) {
    return __bfloat162float(__float2bfloat16_rn(x));
}
__device__ __forceinline__ void cpa(uint32_t d, const void* s) {
    asm volatile("cp.async.cg.shared.global [%0], [%1], 16;" :: "r"(d), "l"(s));
}
#define CPCOMMIT() asm volatile("cp.async.commit_group;")
#define CPWAIT1() asm volatile("cp.async.wait_group 1;")
#define CPWAIT0() asm volatile("cp.async.wait_group 0;")

#define LDSM4(R, A) asm volatile( \
    "ldmatrix.sync.aligned.m8n8.x4.shared.b16 {%0,%1,%2,%3},[%4];" \
    : "=r"((R)[0]), "=r"((R)[1]), "=r"((R)[2]), "=r"((R)[3]) : "r"(A))
#define LDSM4T(R, A) asm volatile( \
    "ldmatrix.sync.aligned.m8n8.x4.trans.shared.b16 {%0,%1,%2,%3},[%4];" \
    : "=r"((R)[0]), "=r"((R)[1]), "=r"((R)[2]), "=r"((R)[3]) : "r"(A))
#define MMAB(D, A, B0, B1) asm volatile( \
    "mma.sync.aligned.m16n8k16.row.col.f32.bf16.bf16.f32 " \
    "{%0,%1,%2,%3},{%4,%5,%6,%7},{%8,%9},{%0,%1,%2,%3};" \
    : "+f"((D)[0]), "+f"((D)[1]), "+f"((D)[2]), "+f"((D)[3]) \
    : "r"((A)[0]), "r"((A)[1]), "r"((A)[2]), "r"((A)[3]), "r"(B0), "r"(B1))

// ---------------------------------------------------------------------------
// Kernel 1a: partial A: g_Ap[ks][h][i][j] = sum_{m in seg ks} Wq[h][i][m] Wk[h][j][m]
// grid (16 h, 8 kseg), block 256
// ---------------------------------------------------------------------------
__global__ void __launch_bounds__(256) computeApart(const float* __restrict__ Wq,
                                                    const float* __restrict__ Wk) {
    const int h = blockIdx.x, ks = blockIdx.y, tid = threadIdx.x;
    const int tx = tid & 15, ty = tid >> 4;
    __shared__ float wqs[64 * 65];
    __shared__ float wks[64 * 65];
    float acc[4][4];
#pragma unroll
    for (int i = 0; i < 4; i++)
#pragma unroll
        for (int j = 0; j < 4; j++) acc[i][j] = 0.f;
    const float* wqh = Wq + (size_t)h * DD * MM;
    const float* wkh = Wk + (size_t)h * DD * MM;
    for (int m0 = ks * 128; m0 < ks * 128 + 128; m0 += 64) {
        __syncthreads();
#pragma unroll
        for (int c = 0; c < 4; c++) {
            int fi = tid + c * 256, i = fi >> 4, q = fi & 15;
            float4 a = *(const float4*)(wqh + i * MM + m0 + q * 4);
            wqs[i * 65 + q * 4 + 0] = a.x; wqs[i * 65 + q * 4 + 1] = a.y;
            wqs[i * 65 + q * 4 + 2] = a.z; wqs[i * 65 + q * 4 + 3] = a.w;
            float4 b = *(const float4*)(wkh + i * MM + m0 + q * 4);
            wks[i * 65 + q * 4 + 0] = b.x; wks[i * 65 + q * 4 + 1] = b.y;
            wks[i * 65 + q * 4 + 2] = b.z; wks[i * 65 + q * 4 + 3] = b.w;
        }
        __syncthreads();
        for (int m = 0; m < 64; m++) {
            float a[4], b[4];
#pragma unroll
            for (int i = 0; i < 4; i++) a[i] = wqs[(ty * 4 + i) * 65 + m];
#pragma unroll
            for (int j = 0; j < 4; j++) b[j] = wks[(tx * 4 + j) * 65 + m];
#pragma unroll
            for (int i = 0; i < 4; i++)
#pragma unroll
                for (int j = 0; j < 4; j++) acc[i][j] += a[i] * b[j];
        }
    }
    float* o = g_Ap + (size_t)ks * (HH * DD * DD) + h * DD * DD;
#pragma unroll
    for (int i = 0; i < 4; i++)
#pragma unroll
        for (int j = 0; j < 4; j++)
            o[(ty * 4 + i) * DD + tx * 4 + j] = acc[i][j];
}

// Kernel 1b: reduce partials, apply 0.125 * log2(e)
__global__ void __launch_bounds__(256) reduceA() {
    int i = blockIdx.x * 256 + threadIdx.x;   // 0..65535
    float s = 0.f;
#pragma unroll
    for (int k = 0; k < 8; k++) s += g_Ap[(size_t)k * (HH * DD * DD) + i];
    g_A[i] = s * (0.125f * 1.4426950408889634f);
}

// ---------------------------------------------------------------------------
// Kernel 2: U = Wv_h @ Wo_h — bf16x3 tensor core, in-kernel conversion
// grid (8 col-tiles of 128, 16 h), 128 threads; tile 64x128, k-chunk 32
// ---------------------------------------------------------------------------
#define CU_SMEM 55296

__global__ void __launch_bounds__(128, 1) computeUTC(const float* __restrict__ Wv,
                                                     const float* __restrict__ Wo) {
    extern __shared__ __align__(16) char sm[];
    const uint32_t sb = (uint32_t)__cvta_generic_to_shared(sm);
    const uint32_t AH[2] = {0u, 27648u}, AL[2] = {5120u, 32768u};
    const uint32_t BH[2] = {10240u, 37888u}, BL[2] = {18944u, 46592u};
    const int tid = threadIdx.x, lane = tid & 31, w = tid >> 5;
    const int h = blockIdx.y, col0 = blockIdx.x * 128;
    const float* wvh = Wv + (size_t)h * DD * MM;
    const float* woh = Wo + (size_t)h * MM * MM;

    // stage chunk 0 into buf 0
#pragma unroll
    for (int c = 0; c < 4; c++) {
        int idx = tid + c * 128;        // 0..511
        int r = idx >> 3, kq = idx & 7;
        float4 v = *(const float4*)(wvh + (size_t)r * MM + kq * 4);
        float hx = bfh(v.x), hy = bfh(v.y), hz = bfh(v.z), hw = bfh(v.w);
        uint32_t o = (uint32_t)(r * 80 + kq * 8);
        *(uint32_t*)(sm + AH[0] + o) = pk(hx, hy);
        *(uint32_t*)(sm + AH[0] + o + 4) = pk(hz, hw);
        *(uint32_t*)(sm + AL[0] + o) = pk(v.x - hx, v.y - hy);
        *(uint32_t*)(sm + AL[0] + o + 4) = pk(v.z - hz, v.w - hw);
    }
#pragma unroll
    for (int c = 0; c < 8; c++) {
        int fi = tid + c * 128;         // 0..1023
        int kk = fi >> 5, q = fi & 31;
        float4 v = *(const float4*)(woh + (size_t)kk * MM + col0 + q * 4);
        float hx = bfh(v.x), hy = bfh(v.y), hz = bfh(v.z), hw = bfh(v.w);
        uint32_t o = (uint32_t)(kk * 272 + q * 8);
        *(uint32_t*)(sm + BH[0] + o) = pk(hx, hy);
        *(uint32_t*)(sm + BH[0] + o + 4) = pk(hz, hw);
        *(uint32_t*)(sm + BL[0] + o) = pk(v.x - hx, v.y - hy);
        *(uint32_t*)(sm + BL[0] + o + 4) = pk(v.z - hz, v.w - hw);
    }
    __syncthreads();

    float acc[16][4];
#pragma unroll
    for (int j = 0; j < 16; j++)
        acc[j][0] = acc[j][1] = acc[j][2] = acc[j][3] = 0.f;

    const uint32_t aro = (uint32_t)((16 * w + (lane & 15)) * 80 + ((lane >> 4) << 3) * 2);
    const uint32_t bro = (uint32_t)((lane & 15) * 272 + ((lane >> 4) << 3) * 2);

    for (int it = 0; it < 32; it++) {
        const int cur = it & 1, nx = cur ^ 1;
        // prefetch next chunk to regs
        float4 pv[4], po[8];
        if (it < 31) {
            int m0 = (it + 1) * 32;
#pragma unroll
            for (int c = 0; c < 4; c++) {
                int idx = tid + c * 128;
                int r = idx >> 3, kq = idx & 7;
                pv[c] = *(const float4*)(wvh + (size_t)r * MM + m0 + kq * 4);
            }
#pragma unroll
            for (int c = 0; c < 8; c++) {
                int fi = tid + c * 128;
                int kk = fi >> 5, q = fi & 31;
                po[c] = *(const float4*)(woh + (size_t)(m0 + kk) * MM + col0 + q * 4);
            }
        }

#pragma unroll
        for (int kk = 0; kk < 2; kk++) {
            uint32_t ah4[4], al4[4];
            LDSM4(ah4, sb + AH[cur] + aro + kk * 32);
            LDSM4(al4, sb + AL[cur] + aro + kk * 32);
#pragma unroll
            for (int jp = 0; jp < 8; jp++) {
                uint32_t off = (uint32_t)(kk * 4352 + jp * 32);
                uint32_t bh4[4], bl4[4];
                LDSM4T(bh4, sb + BH[cur] + bro + off);
                LDSM4T(bl4, sb + BL[cur] + bro + off);
                MMAB(acc[2 * jp], ah4, bh4[0], bh4[1]);
                MMAB(acc[2 * jp], ah4, bl4[0], bl4[1]);
                MMAB(acc[2 * jp], al4, bh4[0], bh4[1]);
                MMAB(acc[2 * jp + 1], ah4, bh4[2], bh4[3]);
                MMAB(acc[2 * jp + 1], ah4, bl4[2], bl4[3]);
                MMAB(acc[2 * jp + 1], al4, bh4[2], bh4[3]);
            }
        }

        if (it < 31) {
#pragma unroll
            for (int c = 0; c < 4; c++) {
                int idx = tid + c * 128;
                int r = idx >> 3, kq = idx & 7;
                float4 v = pv[c];
                float hx = bfh(v.x), hy = bfh(v.y), hz = bfh(v.z), hw = bfh(v.w);
                uint32_t o = (uint32_t)(r * 80 + kq * 8);
                *(uint32_t*)(sm + AH[nx] + o) = pk(hx, hy);
                *(uint32_t*)(sm + AH[nx] + o + 4) = pk(hz, hw);
                *(uint32_t*)(sm + AL[nx] + o) = pk(v.x - hx, v.y - hy);
                *(uint32_t*)(sm + AL[nx] + o + 4) = pk(v.z - hz, v.w - hw);
            }
#pragma unroll
            for (int c = 0; c < 8; c++) {
                int fi = tid + c * 128;
                int kk = fi >> 5, q = fi & 31;
                float4 v = po[c];
                float hx = bfh(v.x), hy = bfh(v.y), hz = bfh(v.z), hw = bfh(v.w);
                uint32_t o = (uint32_t)(kk * 272 + q * 8);
                *(uint32_t*)(sm + BH[nx] + o) = pk(hx, hy);
                *(uint32_t*)(sm + BH[nx] + o + 4) = pk(hz, hw);
                *(uint32_t*)(sm + BL[nx] + o) = pk(v.x - hx, v.y - hy);
                *(uint32_t*)(sm + BL[nx] + o + 4) = pk(v.z - hz, v.w - hw);
            }
        }
        __syncthreads();
    }

    // write U hi/lo
    int r = lane >> 2, cc = (lane & 3) * 2;
    int row = h * 64 + 16 * w + r;
#pragma unroll
    for (int j = 0; j < 16; j++) {
        int gc = col0 + 8 * j + cc;
        float v0 = acc[j][0], v1 = acc[j][1], v2 = acc[j][2], v3 = acc[j][3];
        float h0 = bfh(v0), h1 = bfh(v1), h2 = bfh(v2), h3 = bfh(v3);
        size_t ia = (size_t)row * MM + gc;
        size_t ib = (size_t)(row + 8) * MM + gc;
        *(uint32_t*)((char*)g_Uh + ia * 2) = pk(h0, h1);
        *(uint32_t*)((char*)g_Ul + ia * 2) = pk(v0 - h0, v1 - h1);
        *(uint32_t*)((char*)g_Uh + ib * 2) = pk(h2, h3);
        *(uint32_t*)((char*)g_Ul + ib * 2) = pk(v2 - h2, v3 - h3);
    }
}

// ---------------------------------------------------------------------------
// Kernel 3: y = xh @ A_h, output bf16 hi/lo; ALSO emits g_xh/g_xl (fused split)
// ---------------------------------------------------------------------------
__global__ void __launch_bounds__(256) computeY(const float* __restrict__ x) {
    const int t0 = blockIdx.x * 64, bh = blockIdx.y;
    const int b = bh >> 4, h = bh & 15, tid = threadIdx.x;
    const int tx = tid & 15, ty = tid >> 4;
    __shared__ float As[64 * 66];
    __shared__ float xs[64 * 65];
    const float* ah = g_A + h * DD * DD;
#pragma unroll
    for (int c = 0; c < 4; c++) {
        int fi = tid + c * 256, d = fi >> 4, q = fi & 15;
        float4 a = *(const float4*)(ah + d * 64 + q * 4);
        As[d * 66 + q * 4 + 0] = a.x; As[d * 66 + q * 4 + 1] = a.y;
        As[d * 66 + q * 4 + 2] = a.z; As[d * 66 + q * 4 + 3] = a.w;
    }
    const float* xb = x + ((size_t)b * TT + t0) * MM + h * 64;
#pragma unroll
    for (int c = 0; c < 4; c++) {
        int fi = tid + c * 256, r = fi >> 4, q = fi & 15;
        float4 v = *(const float4*)(xb + (size_t)r * MM + q * 4);
        xs[r * 65 + q * 4 + 0] = v.x; xs[r * 65 + q * 4 + 1] = v.y;
        xs[r * 65 + q * 4 + 2] = v.z; xs[r * 65 + q * 4 + 3] = v.w;
        // fused splitX: per-head bf16 hi/lo of x
        float hx = bfh(v.x), hy = bfh(v.y), hz = bfh(v.z), hw = bfh(v.w);
        size_t dxi = ((size_t)bh * TT + t0 + r) * 64 + q * 4;
        *(uint32_t*)((char*)g_xh + dxi * 2) = pk(hx, hy);
        *(uint32_t*)((char*)g_xh + dxi * 2 + 4) = pk(hz, hw);
        *(uint32_t*)((char*)g_xl + dxi * 2) = pk(v.x - hx, v.y - hy);
        *(uint32_t*)((char*)g_xl + dxi * 2 + 4) = pk(v.z - hz, v.w - hw);
    }
    __syncthreads();
    float acc[4][4];
#pragma unroll
    for (int i = 0; i < 4; i++)
#pragma unroll
        for (int c = 0; c < 4; c++) acc[i][c] = 0.f;
    for (int d = 0; d < 64; d++) {
        float a[4], bfr[4];
#pragma unroll
        for (int i = 0; i < 4; i++) a[i] = xs[(ty * 4 + i) * 65 + d];
#pragma unroll
        for (int c = 0; c < 4; c++) bfr[c] = As[d * 66 + tx * 4 + c];
#pragma unroll
        for (int i = 0; i < 4; i++)
#pragma unroll
            for (int c = 0; c < 4; c++) acc[i][c] += a[i] * bfr[c];
    }
    size_t base = ((size_t)bh * TT + t0) * 64;
#pragma unroll
    for (int i = 0; i < 4; i++) {
        size_t di = base + (size_t)(ty * 4 + i) * 64 + tx * 4;
        float h0 = bfh(acc[i][0]), h1 = bfh(acc[i][1]);
        float h2 = bfh(acc[i][2]), h3 = bfh(acc[i][3]);
        *(uint32_t*)((char*)g_yh + di * 2) = pk(h0, h1);
        *(uint32_t*)((char*)g_yh + di * 2 + 4) = pk(h2, h3);
        *(uint32_t*)((char*)g_yl + di * 2) = pk(acc[i][0] - h0, acc[i][1] - h1);
        *(uint32_t*)((char*)g_yl + di * 2 + 4) = pk(acc[i][2] - h2, acc[i][3] - h3);
    }
}

// ---------------------------------------------------------------------------
// Kernel 4: flash attention — 128 threads (4 warps), 64-row Q tiles, 2 CTA/SM
// ---------------------------------------------------------------------------
#define FL_SMEM 73728

__global__ void __launch_bounds__(128, 2) flashTC() {
    extern __shared__ __align__(16) char sm[];
    const uint32_t sb = (uint32_t)__cvta_generic_to_shared(sm);
    const uint32_t KH0 = 0u, KL0 = 18432u, KH1 = 36864u, KL1 = 55296u;
    const uint32_t QH = KH1, QL = KL1;   // Q overlays K buffer 1
    const int tid = threadIdx.x, lane = tid & 31, w = tid >> 5;
    const int t0 = blockIdx.x * 64, bh = blockIdx.y;
    const int b = bh >> 4, h = bh & 15;

    const __nv_bfloat16* xh = g_xh + (size_t)bh * TT * 64;
    const __nv_bfloat16* xl = g_xl + (size_t)bh * TT * 64;

    {
        const __nv_bfloat16* yh = g_yh + ((size_t)bh * TT + t0) * 64;
        const __nv_bfloat16* yl = g_yl + ((size_t)bh * TT + t0) * 64;
#pragma unroll
        for (int c = 0; c < 4; c++) {
            int idx = tid + c * 128;
            int r = idx >> 3, ch = idx & 7;
            cpa(sb + QH + r * 144 + ch * 16, yh + (size_t)r * 64 + ch * 8);
            cpa(sb + QL + r * 144 + ch * 16, yl + (size_t)r * 64 + ch * 8);
        }
#pragma unroll
        for (int c = 0; c < 8; c++) {
            int idx = tid + c * 128;
            int r = idx >> 3, ch = idx & 7;
            cpa(sb + KH0 + r * 144 + ch * 16, xh + (size_t)r * 64 + ch * 8);
            cpa(sb + KL0 + r * 144 + ch * 16, xl + (size_t)r * 64 + ch * 8);
        }
        CPCOMMIT();
        CPWAIT0();
        __syncthreads();
    }

    uint32_t qh[4][4], ql[4][4];
    {
        uint32_t ro = (uint32_t)((16 * w + (lane & 15)) * 144 + ((lane >> 4) << 3) * 2);
#pragma unroll
        for (int kk = 0; kk < 4; kk++) {
            LDSM4(qh[kk], sb + QH + ro + kk * 32);
            LDSM4(ql[kk], sb + QL + ro + kk * 32);
        }
    }

    float acc[8][4];
    float mrow0 = -INFINITY, mrow1 = -INFINITY, lrow0 = 0.f, lrow1 = 0.f;
#pragma unroll
    for (int j = 0; j < 8; j++) { acc[j][0] = acc[j][1] = acc[j][2] = acc[j][3] = 0.f; }

    for (int it = 0; it < 16; it++) {
        const uint32_t curH = (it & 1) ? KH1 : KH0;
        const uint32_t curL = (it & 1) ? KL1 : KL0;
        const uint32_t nxtH = (it & 1) ? KH0 : KH1;
        const uint32_t nxtL = (it & 1) ? KL0 : KL1;

        __syncthreads();
        if (it < 15) {
            int s0 = (it + 1) * 128;
#pragma unroll
            for (int c = 0; c < 8; c++) {
                int idx = tid + c * 128;
                int r = idx >> 3, ch = idx & 7;
                cpa(sb + nxtH + r * 144 + ch * 16, xh + (size_t)(s0 + r) * 64 + ch * 8);
                cpa(sb + nxtL + r * 144 + ch * 16, xl + (size_t)(s0 + r) * 64 + ch * 8);
            }
            CPCOMMIT();
            CPWAIT1();
        } else {
            CPWAIT0();
        }
        __syncthreads();

        float S[16][4];
#pragma unroll
        for (int j = 0; j < 16; j++) { S[j][0] = S[j][1] = S[j][2] = S[j][3] = 0.f; }
        {
            uint32_t rbase = sb + (uint32_t)(((lane & 7) + ((lane >> 4) << 3)) * 144 +
                                             (((lane >> 3) & 1) << 3) * 2);
#pragma unroll
            for (int jp = 0; jp < 8; jp++) {
#pragma unroll
                for (int kk = 0; kk < 4; kk++) {
                    uint32_t off = (uint32_t)(jp * 2304 + kk * 32);
                    uint32_t bh4[4], bl4[4];
                    LDSM4(bh4, rbase + curH + off);
                    LDSM4(bl4, rbase + curL + off);
                    MMAB(S[2 * jp], qh[kk], bh4[0], bh4[1]);
                    MMAB(S[2 * jp], qh[kk], bl4[0], bl4[1]);
                    MMAB(S[2 * jp], ql[kk], bh4[0], bh4[1]);
                    MMAB(S[2 * jp + 1], qh[kk], bh4[2], bh4[3]);
                    MMAB(S[2 * jp + 1], qh[kk], bl4[2], bl4[3]);
                    MMAB(S[2 * jp + 1], ql[kk], bh4[2], bh4[3]);
                }
            }
        }

        float mx0 = -INFINITY, mx1 = -INFINITY;
#pragma unroll
        for (int j = 0; j < 16; j++) {
            mx0 = fmaxf(mx0, fmaxf(S[j][0], S[j][1]));
            mx1 = fmaxf(mx1, fmaxf(S[j][2], S[j][3]));
        }
        mx0 = fmaxf(mx0, __shfl_xor_sync(0xffffffffu, mx0, 1));
        mx0 = fmaxf(mx0, __shfl_xor_sync(0xffffffffu, mx0, 2));
        mx1 = fmaxf(mx1, __shfl_xor_sync(0xffffffffu, mx1, 1));
        mx1 = fmaxf(mx1, __shfl_xor_sync(0xffffffffu, mx1, 2));
        float mn0 = fmaxf(mrow0, mx0), mn1 = fmaxf(mrow1, mx1);
        float sc0 = exp2f(mrow0 - mn0), sc1 = exp2f(mrow1 - mn1);
        mrow0 = mn0; mrow1 = mn1;

        uint32_t php[8][4], plp[8][4];
        float rs0 = 0.f, rs1 = 0.f;
#pragma unroll
        for (int j = 0; j < 16; j++) {
            float p0 = exp2f(S[j][0] - mn0), p1 = exp2f(S[j][1] - mn0);
            float p2 = exp2f(S[j][2] - mn1), p3 = exp2f(S[j][3] - mn1);
            rs0 += p0 + p1; rs1 += p2 + p3;
            float h0 = bfh(p0), h1 = bfh(p1), h2 = bfh(p2), h3 = bfh(p3);
            int ss = j >> 1, ps = (j & 1) << 1;
            php[ss][ps] = pk(h0, h1);
            php[ss][ps + 1] = pk(h2, h3);
            plp[ss][ps] = pk(p0 - h0, p1 - h1);
            plp[ss][ps + 1] = pk(p2 - h2, p3 - h3);
        }
        rs0 += __shfl_xor_sync(0xffffffffu, rs0, 1);
        rs0 += __shfl_xor_sync(0xffffffffu, rs0, 2);
        rs1 += __shfl_xor_sync(0xffffffffu, rs1, 1);
        rs1 += __shfl_xor_sync(0xffffffffu, rs1, 2);
        lrow0 = lrow0 * sc0 + rs0;
        lrow1 = lrow1 * sc1 + rs1;
#pragma unroll
        for (int j = 0; j < 8; j++) {
            acc[j][0] *= sc0; acc[j][1] *= sc0; acc[j][2] *= sc1; acc[j][3] *= sc1;
        }

        {
            uint32_t rbase = sb + (uint32_t)((lane & 15) * 144 + ((lane >> 4) << 3) * 2);
#pragma unroll
            for (int ss = 0; ss < 8; ss++) {
#pragma unroll
                for (int jp = 0; jp < 4; jp++) {
                    uint32_t off = (uint32_t)(ss * 2304 + jp * 32);
                    uint32_t bh4[4], bl4[4];
                    LDSM4T(bh4, rbase + curH + off);
                    LDSM4T(bl4, rbase + curL + off);
                    MMAB(acc[2 * jp], php[ss], bh4[0], bh4[1]);
                    MMAB(acc[2 * jp], php[ss], bl4[0], bl4[1]);
                    MMAB(acc[2 * jp], plp[ss], bh4[0], bh4[1]);
                    MMAB(acc[2 * jp + 1], php[ss], bh4[2], bh4[3]);
                    MMAB(acc[2 * jp + 1], php[ss], bl4[2], bl4[3]);
                    MMAB(acc[2 * jp + 1], plp[ss], bh4[2], bh4[3]);
                }
            }
        }
    }

    float inv0 = 1.f / lrow0, inv1 = 1.f / lrow1;
    int r0 = lane >> 2, c0 = (lane & 3) * 2;
    size_t rowA = ((size_t)b * TT + t0 + 16 * w + r0) * MM + h * 64;
    size_t rowB = rowA + 8 * MM;
#pragma unroll
    for (int j = 0; j < 8; j++) {
        float o0 = acc[j][0] * inv0, o1 = acc[j][1] * inv0;
        float o2 = acc[j][2] * inv1, o3 = acc[j][3] * inv1;
        float h0 = bfh(o0), h1 = bfh(o1), h2 = bfh(o2), h3 = bfh(o3);
        size_t ia = rowA + 8 * j + c0, ib = rowB + 8 * j + c0;
        *(uint32_t*)((char*)g_zh + ia * 2) = pk(h0, h1);
        *(uint32_t*)((char*)g_zl + ia * 2) = pk(o0 - h0, o1 - h1);
        *(uint32_t*)((char*)g_zh + ib * 2) = pk(h2, h3);
        *(uint32_t*)((char*)g_zl + ib * 2) = pk(o2 - h2, o3 - h3);
    }
}

// ---------------------------------------------------------------------------
// Kernel 5: out = z @ U + bo — 128 threads, tile 128x64, k-chunk 64, 2 CTA/SM
// ---------------------------------------------------------------------------
#define GO_SMEM 110592

__global__ void __launch_bounds__(128, 2) gemmOutTC(const float* __restrict__ bo,
                                                    float* __restrict__ out) {
    extern __shared__ __align__(16) char sm[];
    const uint32_t sb = (uint32_t)__cvta_generic_to_shared(sm);
    const uint32_t ZH[2] = {0u, 55296u}, ZL[2] = {18432u, 73728u};
    const uint32_t UH[2] = {36864u, 92160u}, UL[2] = {46080u, 101376u};
    const int tid = threadIdx.x, lane = tid & 31, w = tid >> 5;
    const int col0 = blockIdx.x * 64, row0 = blockIdx.y * 128;
    const int wr = w * 32;

    // stage chunk 0 (k=64)
#pragma unroll
    for (int c = 0; c < 8; c++) {
        int idx = tid + c * 128;           // 0..1023
        int r = idx >> 3, ch = idx & 7;
        cpa(sb + ZH[0] + r * 144 + ch * 16, g_zh + (size_t)(row0 + r) * MM + ch * 8);
        cpa(sb + ZL[0] + r * 144 + ch * 16, g_zl + (size_t)(row0 + r) * MM + ch * 8);
    }
#pragma unroll
    for (int c = 0; c < 4; c++) {
        int idx = tid + c * 128;           // 0..511
        int kk = idx >> 3, q = idx & 7;
        cpa(sb + UH[0] + kk * 144 + q * 16, g_Uh + (size_t)kk * MM + col0 + q * 8);
        cpa(sb + UL[0] + kk * 144 + q * 16, g_Ul + (size_t)kk * MM + col0 + q * 8);
    }
    CPCOMMIT();

    float acc[2][8][4];
#pragma unroll
    for (int rb = 0; rb < 2; rb++)
#pragma unroll
        for (int j = 0; j < 8; j++)
            acc[rb][j][0] = acc[rb][j][1] = acc[rb][j][2] = acc[rb][j][3] = 0.f;

    const uint32_t aro = (uint32_t)((wr + (lane & 15)) * 144 + ((lane >> 4) << 3) * 2);
    const uint32_t bro = (uint32_t)((lane & 15) * 144 + ((lane >> 4) << 3) * 2);

    for (int it = 0; it < 16; it++) {
        const int cur = it & 1, nx = cur ^ 1;
        __syncthreads();
        if (it < 15) {
            int k0 = (it + 1) * 64;
#pragma unroll
            for (int c = 0; c < 8; c++) {
                int idx = tid + c * 128;
                int r = idx >> 3, ch = idx & 7;
                cpa(sb + ZH[nx] + r * 144 + ch * 16,
                    g_zh + (size_t)(row0 + r) * MM + k0 + ch * 8);
                cpa(sb + ZL[nx] + r * 144 + ch * 16,
                    g_zl + (size_t)(row0 + r) * MM + k0 + ch * 8);
            }
#pragma unroll
            for (int c = 0; c < 4; c++) {
                int idx = tid + c * 128;
                int kk = idx >> 3, q = idx & 7;
                cpa(sb + UH[nx] + kk * 144 + q * 16,
                    g_Uh + (size_t)(k0 + kk) * MM + col0 + q * 8);
                cpa(sb + UL[nx] + kk * 144 + q * 16,
                    g_Ul + (size_t)(k0 + kk) * MM + col0 + q * 8);
            }
            CPCOMMIT();
            CPWAIT1();
        } else {
            CPWAIT0();
        }
        __syncthreads();

#pragma unroll
        for (int kk = 0; kk < 4; kk++) {
            uint32_t ah0[4], al0[4], ah1[4], al1[4];
            LDSM4(ah0, sb + ZH[cur] + aro + kk * 32);
            LDSM4(al0, sb + ZL[cur] + aro + kk * 32);
            LDSM4(ah1, sb + ZH[cur] + aro + 2304 + kk * 32);
            LDSM4(al1, sb + ZL[cur] + aro + 2304 + kk * 32);
#pragma unroll
            for (int jp = 0; jp < 4; jp++) {
                uint32_t off = (uint32_t)(kk * 2304 + jp * 32);
                uint32_t bh4[4], bl4[4];
                LDSM4T(bh4, sb + UH[cur] + bro + off);
                LDSM4T(bl4, sb + UL[cur] + bro + off);
                MMAB(acc[0][2 * jp], ah0, bh4[0], bh4[1]);
                MMAB(acc[0][2 * jp], ah0, bl4[0], bl4[1]);
                MMAB(acc[0][2 * jp], al0, bh4[0], bh4[1]);
                MMAB(acc[0][2 * jp + 1], ah0, bh4[2], bh4[3]);
                MMAB(acc[0][2 * jp + 1], ah0, bl4[2], bl4[3]);
                MMAB(acc[0][2 * jp + 1], al0, bh4[2], bh4[3]);
                MMAB(acc[1][2 * jp], ah1, bh4[0], bh4[1]);
                MMAB(acc[1][2 * jp], ah1, bl4[0], bl4[1]);
                MMAB(acc[1][2 * jp], al1, bh4[0], bh4[1]);
                MMAB(acc[1][2 * jp + 1], ah1, bh4[2], bh4[3]);
                MMAB(acc[1][2 * jp + 1], ah1, bl4[2], bl4[3]);
                MMAB(acc[1][2 * jp + 1], al1, bh4[2], bh4[3]);
            }
        }
    }

    int r = lane >> 2, cc = (lane & 3) * 2;
#pragma unroll
    for (int rb = 0; rb < 2; rb++) {
        int gr = row0 + wr + rb * 16 + r;
#pragma unroll
        for (int j = 0; j < 8; j++) {
            int gc = col0 + 8 * j + cc;
            float b0v = bo[gc], b1v = bo[gc + 1];
            *(float2*)(out + (size_t)gr * MM + gc) =
                make_float2(acc[rb][j][0] + b0v, acc[rb][j][1] + b1v);
            *(float2*)(out + (size_t)(gr + 8) * MM + gc) =
                make_float2(acc[rb][j][2] + b0v, acc[rb][j][3] + b1v);
        }
    }
}

// ---------------------------------------------------------------------------
extern "C" void kernel_launch(void* const* d_in, const int* in_sizes, int n_in,
                              void* d_out, int out_size) {
    const float* x  = (const float*)d_in[0];
    const float* Wq = (const float*)d_in[1];
    const float* Wk = (const float*)d_in[2];
    const float* Wv = (const float*)d_in[3];
    const float* Wo = (const float*)d_in[4];
    const float* bo = (const float*)d_in[5];
    float* out = (float*)d_out;

    cudaFuncSetAttribute(flashTC, cudaFuncAttributeMaxDynamicSharedMemorySize, FL_SMEM);
    cudaFuncSetAttribute(gemmOutTC, cudaFuncAttributeMaxDynamicSharedMemorySize, GO_SMEM);
    cudaFuncSetAttribute(computeUTC, cudaFuncAttributeMaxDynamicSharedMemorySize, CU_SMEM);

    computeApart<<<dim3(16, 8), 256>>>(Wq, Wk);
    reduceA<<<256, 256>>>();
    computeUTC<<<dim3(8, 16), 128, CU_SMEM>>>(Wv, Wo);
    computeY<<<dim3(TT / 64, BB * HH), 256>>>(x);
    flashTC<<<dim3(TT / 64, BB * HH), 128, FL_SMEM>>>();
    gemmOutTC<<<dim3(MM / 64, (BB * TT) / 128), 128, GO_SMEM>>>(bo, out);
}

// round 8
// speedup vs baseline: 3.7929x; 1.0161x over previous
#include <cuda_runtime.h>
#include <cuda_bf16.h>
#include <math.h>
#include <stdint.h>

#define BB 2
#define TT 2048
#define HH 16
#define DD 64
#define MM 1024

// Persistent scratch (device globals)
__device__ float g_A[HH * DD * DD];                    // A_h = Wq Wk^T /8 * log2e
__device__ float g_Ap[8 * HH * DD * DD];               // k-split partials for A
__device__ __nv_bfloat16 g_xh[BB * HH * TT * DD];      // x per-head, bf16 hi  [bh][t][64]
__device__ __nv_bfloat16 g_xl[BB * HH * TT * DD];      // x per-head, bf16 lo
__device__ __nv_bfloat16 g_yh[BB * HH * TT * DD];      // Q = xh@A, bf16 hi    [bh][t][64]
__device__ __nv_bfloat16 g_yl[BB * HH * TT * DD];
__device__ __nv_bfloat16 g_zh[BB * TT * MM];           // attn out, bf16 hi    [b][t][1024]
__device__ __nv_bfloat16 g_zl[BB * TT * MM];
__device__ __nv_bfloat16 g_Uh[MM * MM];                // U = Wv@Wo, bf16 hi   [1024][1024]
__device__ __nv_bfloat16 g_Ul[MM * MM];

__device__ __forceinline__ uint32_t pk(float a, float b) {
    __nv_bfloat162 t = __floats2bfloat162_rn(a, b);
    return *reinterpret_cast<uint32_t*>(&t);
}
__device__ __forceinline__ float bfh(float x) {
    return __bfloat162float(__float2bfloat16_rn(x));
}
__device__ __forceinline__ float ex2f(float x) {
    float y;
    asm("ex2.approx.ftz.f32 %0, %1;" : "=f"(y) : "f"(x));
    return y;
}
__device__ __forceinline__ void cpa(uint32_t d, const void* s) {
    asm volatile("cp.async.cg.shared.global [%0], [%1], 16;" :: "r"(d), "l"(s));
}
#define CPCOMMIT() asm volatile("cp.async.commit_group;")
#define CPWAIT1() asm volatile("cp.async.wait_group 1;")
#define CPWAIT0() asm volatile("cp.async.wait_group 0;")

#define LDSM4(R, A) asm volatile( \
    "ldmatrix.sync.aligned.m8n8.x4.shared.b16 {%0,%1,%2,%3},[%4];" \
    : "=r"((R)[0]), "=r"((R)[1]), "=r"((R)[2]), "=r"((R)[3]) : "r"(A))
#define LDSM4T(R, A) asm volatile( \
    "ldmatrix.sync.aligned.m8n8.x4.trans.shared.b16 {%0,%1,%2,%3},[%4];" \
    : "=r"((R)[0]), "=r"((R)[1]), "=r"((R)[2]), "=r"((R)[3]) : "r"(A))
#define MMAB(D, A, B0, B1) asm volatile( \
    "mma.sync.aligned.m16n8k16.row.col.f32.bf16.bf16.f32 " \
    "{%0,%1,%2,%3},{%4,%5,%6,%7},{%8,%9},{%0,%1,%2,%3};" \
    : "+f"((D)[0]), "+f"((D)[1]), "+f"((D)[2]), "+f"((D)[3]) \
    : "r"((A)[0]), "r"((A)[1]), "r"((A)[2]), "r"((A)[3]), "r"(B0), "r"(B1))

// ---------------------------------------------------------------------------
// Kernel 1a: partial A; grid (16 h, 8 kseg)
// ---------------------------------------------------------------------------
__global__ void __launch_bounds__(256) computeApart(const float* __restrict__ Wq,
                                                    const float* __restrict__ Wk) {
    const int h = blockIdx.x, ks = blockIdx.y, tid = threadIdx.x;
    const int tx = tid & 15, ty = tid >> 4;
    __shared__ float wqs[64 * 65];
    __shared__ float wks[64 * 65];
    float acc[4][4];
#pragma unroll
    for (int i = 0; i < 4; i++)
#pragma unroll
        for (int j = 0; j < 4; j++) acc[i][j] = 0.f;
    const float* wqh = Wq + (size_t)h * DD * MM;
    const float* wkh = Wk + (size_t)h * DD * MM;
    for (int m0 = ks * 128; m0 < ks * 128 + 128; m0 += 64) {
        __syncthreads();
#pragma unroll
        for (int c = 0; c < 4; c++) {
            int fi = tid + c * 256, i = fi >> 4, q = fi & 15;
            float4 a = *(const float4*)(wqh + i * MM + m0 + q * 4);
            wqs[i * 65 + q * 4 + 0] = a.x; wqs[i * 65 + q * 4 + 1] = a.y;
            wqs[i * 65 + q * 4 + 2] = a.z; wqs[i * 65 + q * 4 + 3] = a.w;
            float4 b = *(const float4*)(wkh + i * MM + m0 + q * 4);
            wks[i * 65 + q * 4 + 0] = b.x; wks[i * 65 + q * 4 + 1] = b.y;
            wks[i * 65 + q * 4 + 2] = b.z; wks[i * 65 + q * 4 + 3] = b.w;
        }
        __syncthreads();
        for (int m = 0; m < 64; m++) {
            float a[4], b[4];
#pragma unroll
            for (int i = 0; i < 4; i++) a[i] = wqs[(ty * 4 + i) * 65 + m];
#pragma unroll
            for (int j = 0; j < 4; j++) b[j] = wks[(tx * 4 + j) * 65 + m];
#pragma unroll
            for (int i = 0; i < 4; i++)
#pragma unroll
                for (int j = 0; j < 4; j++) acc[i][j] += a[i] * b[j];
        }
    }
    float* o = g_Ap + (size_t)ks * (HH * DD * DD) + h * DD * DD;
#pragma unroll
    for (int i = 0; i < 4; i++)
#pragma unroll
        for (int j = 0; j < 4; j++)
            o[(ty * 4 + i) * DD + tx * 4 + j] = acc[i][j];
}

__global__ void __launch_bounds__(256) reduceA() {
    int i = blockIdx.x * 256 + threadIdx.x;
    float s = 0.f;
#pragma unroll
    for (int k = 0; k < 8; k++) s += g_Ap[(size_t)k * (HH * DD * DD) + i];
    g_A[i] = s * (0.125f * 1.4426950408889634f);
}

// ---------------------------------------------------------------------------
// Kernel 2: U = Wv_h @ Wo_h — bf16x3 mma.sync, output bf16 hi/lo (row-major)
// ---------------------------------------------------------------------------
#define CU_SMEM 55296

__global__ void __launch_bounds__(128, 1) computeUTC(const float* __restrict__ Wv,
                                                     const float* __restrict__ Wo) {
    extern __shared__ __align__(16) char sm[];
    const uint32_t sb = (uint32_t)__cvta_generic_to_shared(sm);
    const uint32_t AH[2] = {0u, 27648u}, AL[2] = {5120u, 32768u};
    const uint32_t BH[2] = {10240u, 37888u}, BL[2] = {18944u, 46592u};
    const int tid = threadIdx.x, lane = tid & 31, w = tid >> 5;
    const int h = blockIdx.y, col0 = blockIdx.x * 128;
    const float* wvh = Wv + (size_t)h * DD * MM;
    const float* woh = Wo + (size_t)h * MM * MM;

#pragma unroll
    for (int c = 0; c < 4; c++) {
        int idx = tid + c * 128;
        int r = idx >> 3, kq = idx & 7;
        float4 v = *(const float4*)(wvh + (size_t)r * MM + kq * 4);
        float hx = bfh(v.x), hy = bfh(v.y), hz = bfh(v.z), hw = bfh(v.w);
        uint32_t o = (uint32_t)(r * 80 + kq * 8);
        *(uint32_t*)(sm + AH[0] + o) = pk(hx, hy);
        *(uint32_t*)(sm + AH[0] + o + 4) = pk(hz, hw);
        *(uint32_t*)(sm + AL[0] + o) = pk(v.x - hx, v.y - hy);
        *(uint32_t*)(sm + AL[0] + o + 4) = pk(v.z - hz, v.w - hw);
    }
#pragma unroll
    for (int c = 0; c < 8; c++) {
        int fi = tid + c * 128;
        int kk = fi >> 5, q = fi & 31;
        float4 v = *(const float4*)(woh + (size_t)kk * MM + col0 + q * 4);
        float hx = bfh(v.x), hy = bfh(v.y), hz = bfh(v.z), hw = bfh(v.w);
        uint32_t o = (uint32_t)(kk * 272 + q * 8);
        *(uint32_t*)(sm + BH[0] + o) = pk(hx, hy);
        *(uint32_t*)(sm + BH[0] + o + 4) = pk(hz, hw);
        *(uint32_t*)(sm + BL[0] + o) = pk(v.x - hx, v.y - hy);
        *(uint32_t*)(sm + BL[0] + o + 4) = pk(v.z - hz, v.w - hw);
    }
    __syncthreads();

    float acc[16][4];
#pragma unroll
    for (int j = 0; j < 16; j++)
        acc[j][0] = acc[j][1] = acc[j][2] = acc[j][3] = 0.f;

    const uint32_t aro = (uint32_t)((16 * w + (lane & 15)) * 80 + ((lane >> 4) << 3) * 2);
    const uint32_t bro = (uint32_t)((lane & 15) * 272 + ((lane >> 4) << 3) * 2);

    for (int it = 0; it < 32; it++) {
        const int cur = it & 1, nx = cur ^ 1;
        float4 pv[4], po[8];
        if (it < 31) {
            int m0 = (it + 1) * 32;
#pragma unroll
            for (int c = 0; c < 4; c++) {
                int idx = tid + c * 128;
                int r = idx >> 3, kq = idx & 7;
                pv[c] = *(const float4*)(wvh + (size_t)r * MM + m0 + kq * 4);
            }
#pragma unroll
            for (int c = 0; c < 8; c++) {
                int fi = tid + c * 128;
                int kk = fi >> 5, q = fi & 31;
                po[c] = *(const float4*)(woh + (size_t)(m0 + kk) * MM + col0 + q * 4);
            }
        }

#pragma unroll
        for (int kk = 0; kk < 2; kk++) {
            uint32_t ah4[4], al4[4];
            LDSM4(ah4, sb + AH[cur] + aro + kk * 32);
            LDSM4(al4, sb + AL[cur] + aro + kk * 32);
#pragma unroll
            for (int jp = 0; jp < 8; jp++) {
                uint32_t off = (uint32_t)(kk * 4352 + jp * 32);
                uint32_t bh4[4], bl4[4];
                LDSM4T(bh4, sb + BH[cur] + bro + off);
                LDSM4T(bl4, sb + BL[cur] + bro + off);
                MMAB(acc[2 * jp], ah4, bh4[0], bh4[1]);
                MMAB(acc[2 * jp], ah4, bl4[0], bl4[1]);
                MMAB(acc[2 * jp], al4, bh4[0], bh4[1]);
                MMAB(acc[2 * jp + 1], ah4, bh4[2], bh4[3]);
                MMAB(acc[2 * jp + 1], ah4, bl4[2], bl4[3]);
                MMAB(acc[2 * jp + 1], al4, bh4[2], bh4[3]);
            }
        }

        if (it < 31) {
#pragma unroll
            for (int c = 0; c < 4; c++) {
                int idx = tid + c * 128;
                int r = idx >> 3, kq = idx & 7;
                float4 v = pv[c];
                float hx = bfh(v.x), hy = bfh(v.y), hz = bfh(v.z), hw = bfh(v.w);
                uint32_t o = (uint32_t)(r * 80 + kq * 8);
                *(uint32_t*)(sm + AH[nx] + o) = pk(hx, hy);
                *(uint32_t*)(sm + AH[nx] + o + 4) = pk(hz, hw);
                *(uint32_t*)(sm + AL[nx] + o) = pk(v.x - hx, v.y - hy);
                *(uint32_t*)(sm + AL[nx] + o + 4) = pk(v.z - hz, v.w - hw);
            }
#pragma unroll
            for (int c = 0; c < 8; c++) {
                int fi = tid + c * 128;
                int kk = fi >> 5, q = fi & 31;
                float4 v = po[c];
                float hx = bfh(v.x), hy = bfh(v.y), hz = bfh(v.z), hw = bfh(v.w);
                uint32_t o = (uint32_t)(kk * 272 + q * 8);
                *(uint32_t*)(sm + BH[nx] + o) = pk(hx, hy);
                *(uint32_t*)(sm + BH[nx] + o + 4) = pk(hz, hw);
                *(uint32_t*)(sm + BL[nx] + o) = pk(v.x - hx, v.y - hy);
                *(uint32_t*)(sm + BL[nx] + o + 4) = pk(v.z - hz, v.w - hw);
            }
        }
        __syncthreads();
    }

    int r = lane >> 2, cc = (lane & 3) * 2;
    int row = h * 64 + 16 * w + r;
#pragma unroll
    for (int j = 0; j < 16; j++) {
        int gc = col0 + 8 * j + cc;
        float v0 = acc[j][0], v1 = acc[j][1], v2 = acc[j][2], v3 = acc[j][3];
        float h0 = bfh(v0), h1 = bfh(v1), h2 = bfh(v2), h3 = bfh(v3);
        size_t ia = (size_t)row * MM + gc;
        size_t ib = (size_t)(row + 8) * MM + gc;
        *(uint32_t*)((char*)g_Uh + ia * 2) = pk(h0, h1);
        *(uint32_t*)((char*)g_Ul + ia * 2) = pk(v0 - h0, v1 - h1);
        *(uint32_t*)((char*)g_Uh + ib * 2) = pk(h2, h3);
        *(uint32_t*)((char*)g_Ul + ib * 2) = pk(v2 - h2, v3 - h3);
    }
}

// ---------------------------------------------------------------------------
// Kernel 3: y = xh @ A_h + fused split of x — 128-row tiles (2x work/CTA)
// dynamic smem: As[64*66] floats then xs[128*65] floats = 50176 B
// ---------------------------------------------------------------------------
#define CY_SMEM 50176

__global__ void __launch_bounds__(256) computeY(const float* __restrict__ x) {
    extern __shared__ float smY[];
    float* As = smY;                 // [64][66]
    float* xs = smY + 64 * 66;       // [128][65]
    const int t0 = blockIdx.x * 128, bh = blockIdx.y;
    const int b = bh >> 4, h = bh & 15, tid = threadIdx.x;
    const int tx = tid & 15, ty = tid >> 4;
    const float* ah = g_A + h * DD * DD;
#pragma unroll
    for (int c = 0; c < 4; c++) {
        int fi = tid + c * 256, d = fi >> 4, q = fi & 15;
        float4 a = *(const float4*)(ah + d * 64 + q * 4);
        As[d * 66 + q * 4 + 0] = a.x; As[d * 66 + q * 4 + 1] = a.y;
        As[d * 66 + q * 4 + 2] = a.z; As[d * 66 + q * 4 + 3] = a.w;
    }
    const float* xb = x + ((size_t)b * TT + t0) * MM + h * 64;
#pragma unroll
    for (int c = 0; c < 8; c++) {
        int fi = tid + c * 256, r = fi >> 4, q = fi & 15;
        float4 v = *(const float4*)(xb + (size_t)r * MM + q * 4);
        xs[r * 65 + q * 4 + 0] = v.x; xs[r * 65 + q * 4 + 1] = v.y;
        xs[r * 65 + q * 4 + 2] = v.z; xs[r * 65 + q * 4 + 3] = v.w;
        float hx = bfh(v.x), hy = bfh(v.y), hz = bfh(v.z), hw = bfh(v.w);
        size_t dxi = ((size_t)bh * TT + t0 + r) * 64 + q * 4;
        *(uint32_t*)((char*)g_xh + dxi * 2) = pk(hx, hy);
        *(uint32_t*)((char*)g_xh + dxi * 2 + 4) = pk(hz, hw);
        *(uint32_t*)((char*)g_xl + dxi * 2) = pk(v.x - hx, v.y - hy);
        *(uint32_t*)((char*)g_xl + dxi * 2 + 4) = pk(v.z - hz, v.w - hw);
    }
    __syncthreads();
    float acc[8][4];
#pragma unroll
    for (int i = 0; i < 8; i++)
#pragma unroll
        for (int c = 0; c < 4; c++) acc[i][c] = 0.f;
    for (int d = 0; d < 64; d++) {
        float a[8], bfr[4];
#pragma unroll
        for (int i = 0; i < 8; i++) a[i] = xs[(ty * 8 + i) * 65 + d];
#pragma unroll
        for (int c = 0; c < 4; c++) bfr[c] = As[d * 66 + tx * 4 + c];
#pragma unroll
        for (int i = 0; i < 8; i++)
#pragma unroll
            for (int c = 0; c < 4; c++) acc[i][c] += a[i] * bfr[c];
    }
    size_t base = ((size_t)bh * TT + t0) * 64;
#pragma unroll
    for (int i = 0; i < 8; i++) {
        size_t di = base + (size_t)(ty * 8 + i) * 64 + tx * 4;
        float h0 = bfh(acc[i][0]), h1 = bfh(acc[i][1]);
        float h2 = bfh(acc[i][2]), h3 = bfh(acc[i][3]);
        *(uint32_t*)((char*)g_yh + di * 2) = pk(h0, h1);
        *(uint32_t*)((char*)g_yh + di * 2 + 4) = pk(h2, h3);
        *(uint32_t*)((char*)g_yl + di * 2) = pk(acc[i][0] - h0, acc[i][1] - h1);
        *(uint32_t*)((char*)g_yl + di * 2 + 4) = pk(acc[i][2] - h2, acc[i][3] - h3);
    }
}

// ---------------------------------------------------------------------------
// Kernel 4: flash attention — 128 threads (4 warps), 64-row Q tiles, 2 CTA/SM
// ---------------------------------------------------------------------------
#define FL_SMEM 73728

__global__ void __launch_bounds__(128, 2) flashTC() {
    extern __shared__ __align__(16) char sm[];
    const uint32_t sb = (uint32_t)__cvta_generic_to_shared(sm);
    const uint32_t KH0 = 0u, KL0 = 18432u, KH1 = 36864u, KL1 = 55296u;
    const uint32_t QH = KH1, QL = KL1;
    const int tid = threadIdx.x, lane = tid & 31, w = tid >> 5;
    const int t0 = blockIdx.x * 64, bh = blockIdx.y;
    const int b = bh >> 4, h = bh & 15;

    const __nv_bfloat16* xh = g_xh + (size_t)bh * TT * 64;
    const __nv_bfloat16* xl = g_xl + (size_t)bh * TT * 64;

    {
        const __nv_bfloat16* yh = g_yh + ((size_t)bh * TT + t0) * 64;
        const __nv_bfloat16* yl = g_yl + ((size_t)bh * TT + t0) * 64;
#pragma unroll
        for (int c = 0; c < 4; c++) {
            int idx = tid + c * 128;
            int r = idx >> 3, ch = idx & 7;
            cpa(sb + QH + r * 144 + ch * 16, yh + (size_t)r * 64 + ch * 8);
            cpa(sb + QL + r * 144 + ch * 16, yl + (size_t)r * 64 + ch * 8);
        }
#pragma unroll
        for (int c = 0; c < 8; c++) {
            int idx = tid + c * 128;
            int r = idx >> 3, ch = idx & 7;
            cpa(sb + KH0 + r * 144 + ch * 16, xh + (size_t)r * 64 + ch * 8);
            cpa(sb + KL0 + r * 144 + ch * 16, xl + (size_t)r * 64 + ch * 8);
        }
        CPCOMMIT();
        CPWAIT0();
        __syncthreads();
    }

    uint32_t qh[4][4], ql[4][4];
    {
        uint32_t ro = (uint32_t)((16 * w + (lane & 15)) * 144 + ((lane >> 4) << 3) * 2);
#pragma unroll
        for (int kk = 0; kk < 4; kk++) {
            LDSM4(qh[kk], sb + QH + ro + kk * 32);
            LDSM4(ql[kk], sb + QL + ro + kk * 32);
        }
    }

    float acc[8][4];
    float mrow0 = -INFINITY, mrow1 = -INFINITY, lrow0 = 0.f, lrow1 = 0.f;
#pragma unroll
    for (int j = 0; j < 8; j++) { acc[j][0] = acc[j][1] = acc[j][2] = acc[j][3] = 0.f; }

    for (int it = 0; it < 16; it++) {
        const uint32_t curH = (it & 1) ? KH1 : KH0;
        const uint32_t curL = (it & 1) ? KL1 : KL0;
        const uint32_t nxtH = (it & 1) ? KH0 : KH1;
        const uint32_t nxtL = (it & 1) ? KL0 : KL1;

        __syncthreads();
        if (it < 15) {
            int s0 = (it + 1) * 128;
#pragma unroll
            for (int c = 0; c < 8; c++) {
                int idx = tid + c * 128;
                int r = idx >> 3, ch = idx & 7;
                cpa(sb + nxtH + r * 144 + ch * 16, xh + (size_t)(s0 + r) * 64 + ch * 8);
                cpa(sb + nxtL + r * 144 + ch * 16, xl + (size_t)(s0 + r) * 64 + ch * 8);
            }
            CPCOMMIT();
            CPWAIT1();
        } else {
            CPWAIT0();
        }
        __syncthreads();

        float S[16][4];
#pragma unroll
        for (int j = 0; j < 16; j++) { S[j][0] = S[j][1] = S[j][2] = S[j][3] = 0.f; }
        {
            uint32_t rbase = sb + (uint32_t)(((lane & 7) + ((lane >> 4) << 3)) * 144 +
                                             (((lane >> 3) & 1) << 3) * 2);
#pragma unroll
            for (int jp = 0; jp < 8; jp++) {
#pragma unroll
                for (int kk = 0; kk < 4; kk++) {
                    uint32_t off = (uint32_t)(jp * 2304 + kk * 32);
                    uint32_t bh4[4], bl4[4];
                    LDSM4(bh4, rbase + curH + off);
                    LDSM4(bl4, rbase + curL + off);
                    MMAB(S[2 * jp], qh[kk], bh4[0], bh4[1]);
                    MMAB(S[2 * jp], qh[kk], bl4[0], bl4[1]);
                    MMAB(S[2 * jp], ql[kk], bh4[0], bh4[1]);
                    MMAB(S[2 * jp + 1], qh[kk], bh4[2], bh4[3]);
                    MMAB(S[2 * jp + 1], qh[kk], bl4[2], bl4[3]);
                    MMAB(S[2 * jp + 1], ql[kk], bh4[2], bh4[3]);
                }
            }
        }

        float mx0 = -INFINITY, mx1 = -INFINITY;
#pragma unroll
        for (int j = 0; j < 16; j++) {
            mx0 = fmaxf(mx0, fmaxf(S[j][0], S[j][1]));
            mx1 = fmaxf(mx1, fmaxf(S[j][2], S[j][3]));
        }
        mx0 = fmaxf(mx0, __shfl_xor_sync(0xffffffffu, mx0, 1));
        mx0 = fmaxf(mx0, __shfl_xor_sync(0xffffffffu, mx0, 2));
        mx1 = fmaxf(mx1, __shfl_xor_sync(0xffffffffu, mx1, 1));
        mx1 = fmaxf(mx1, __shfl_xor_sync(0xffffffffu, mx1, 2));
        float mn0 = fmaxf(mrow0, mx0), mn1 = fmaxf(mrow1, mx1);
        float sc0 = ex2f(mrow0 - mn0), sc1 = ex2f(mrow1 - mn1);
        mrow0 = mn0; mrow1 = mn1;

        uint32_t php[8][4], plp[8][4];
        float rs0 = 0.f, rs1 = 0.f;
#pragma unroll
        for (int j = 0; j < 16; j++) {
            float p0 = ex2f(S[j][0] - mn0), p1 = ex2f(S[j][1] - mn0);
            float p2 = ex2f(S[j][2] - mn1), p3 = ex2f(S[j][3] - mn1);
            rs0 += p0 + p1; rs1 += p2 + p3;
            float h0 = bfh(p0), h1 = bfh(p1), h2 = bfh(p2), h3 = bfh(p3);
            int ss = j >> 1, ps = (j & 1) << 1;
            php[ss][ps] = pk(h0, h1);
            php[ss][ps + 1] = pk(h2, h3);
            plp[ss][ps] = pk(p0 - h0, p1 - h1);
            plp[ss][ps + 1] = pk(p2 - h2, p3 - h3);
        }
        rs0 += __shfl_xor_sync(0xffffffffu, rs0, 1);
        rs0 += __shfl_xor_sync(0xffffffffu, rs0, 2);
        rs1 += __shfl_xor_sync(0xffffffffu, rs1, 1);
        rs1 += __shfl_xor_sync(0xffffffffu, rs1, 2);
        lrow0 = lrow0 * sc0 + rs0;
        lrow1 = lrow1 * sc1 + rs1;
#pragma unroll
        for (int j = 0; j < 8; j++) {
            acc[j][0] *= sc0; acc[j][1] *= sc0; acc[j][2] *= sc1; acc[j][3] *= sc1;
        }

        {
            uint32_t rbase = sb + (uint32_t)((lane & 15) * 144 + ((lane >> 4) << 3) * 2);
#pragma unroll
            for (int ss = 0; ss < 8; ss++) {
#pragma unroll
                for (int jp = 0; jp < 4; jp++) {
                    uint32_t off = (uint32_t)(ss * 2304 + jp * 32);
                    uint32_t bh4[4], bl4[4];
                    LDSM4T(bh4, rbase + curH + off);
                    LDSM4T(bl4, rbase + curL + off);
                    MMAB(acc[2 * jp], php[ss], bh4[0], bh4[1]);
                    MMAB(acc[2 * jp], php[ss], bl4[0], bl4[1]);
                    MMAB(acc[2 * jp], plp[ss], bh4[0], bh4[1]);
                    MMAB(acc[2 * jp + 1], php[ss], bh4[2], bh4[3]);
                    MMAB(acc[2 * jp + 1], php[ss], bl4[2], bl4[3]);
                    MMAB(acc[2 * jp + 1], plp[ss], bh4[2], bh4[3]);
                }
            }
        }
    }

    float inv0 = 1.f / lrow0, inv1 = 1.f / lrow1;
    int r0 = lane >> 2, c0 = (lane & 3) * 2;
    size_t rowA = ((size_t)b * TT + t0 + 16 * w + r0) * MM + h * 64;
    size_t rowB = rowA + 8 * MM;
#pragma unroll
    for (int j = 0; j < 8; j++) {
        float o0 = acc[j][0] * inv0, o1 = acc[j][1] * inv0;
        float o2 = acc[j][2] * inv1, o3 = acc[j][3] * inv1;
        float h0 = bfh(o0), h1 = bfh(o1), h2 = bfh(o2), h3 = bfh(o3);
        size_t ia = rowA + 8 * j + c0, ib = rowB + 8 * j + c0;
        *(uint32_t*)((char*)g_zh + ia * 2) = pk(h0, h1);
        *(uint32_t*)((char*)g_zl + ia * 2) = pk(o0 - h0, o1 - h1);
        *(uint32_t*)((char*)g_zh + ib * 2) = pk(h2, h3);
        *(uint32_t*)((char*)g_zl + ib * 2) = pk(o2 - h2, o3 - h3);
    }
}

// ---------------------------------------------------------------------------
// Kernel 5: out = z @ U + bo — 128 threads, tile 128x64, k-chunk 64, 2 CTA/SM
// ---------------------------------------------------------------------------
#define GO_SMEM 110592

__global__ void __launch_bounds__(128, 2) gemmOutTC(const float* __restrict__ bo,
                                                    float* __restrict__ out) {
    extern __shared__ __align__(16) char sm[];
    const uint32_t sb = (uint32_t)__cvta_generic_to_shared(sm);
    const uint32_t ZH[2] = {0u, 55296u}, ZL[2] = {18432u, 73728u};
    const uint32_t UH[2] = {36864u, 92160u}, UL[2] = {46080u, 101376u};
    const int tid = threadIdx.x, lane = tid & 31, w = tid >> 5;
    const int col0 = blockIdx.x * 64, row0 = blockIdx.y * 128;
    const int wr = w * 32;

#pragma unroll
    for (int c = 0; c < 8; c++) {
        int idx = tid + c * 128;
        int r = idx >> 3, ch = idx & 7;
        cpa(sb + ZH[0] + r * 144 + ch * 16, g_zh + (size_t)(row0 + r) * MM + ch * 8);
        cpa(sb + ZL[0] + r * 144 + ch * 16, g_zl + (size_t)(row0 + r) * MM + ch * 8);
    }
#pragma unroll
    for (int c = 0; c < 4; c++) {
        int idx = tid + c * 128;
        int kk = idx >> 3, q = idx & 7;
        cpa(sb + UH[0] + kk * 144 + q * 16, g_Uh + (size_t)kk * MM + col0 + q * 8);
        cpa(sb + UL[0] + kk * 144 + q * 16, g_Ul + (size_t)kk * MM + col0 + q * 8);
    }
    CPCOMMIT();

    float acc[2][8][4];
#pragma unroll
    for (int rb = 0; rb < 2; rb++)
#pragma unroll
        for (int j = 0; j < 8; j++)
            acc[rb][j][0] = acc[rb][j][1] = acc[rb][j][2] = acc[rb][j][3] = 0.f;

    const uint32_t aro = (uint32_t)((wr + (lane & 15)) * 144 + ((lane >> 4) << 3) * 2);
    const uint32_t bro = (uint32_t)((lane & 15) * 144 + ((lane >> 4) << 3) * 2);

    for (int it = 0; it < 16; it++) {
        const int cur = it & 1, nx = cur ^ 1;
        __syncthreads();
        if (it < 15) {
            int k0 = (it + 1) * 64;
#pragma unroll
            for (int c = 0; c < 8; c++) {
                int idx = tid + c * 128;
                int r = idx >> 3, ch = idx & 7;
                cpa(sb + ZH[nx] + r * 144 + ch * 16,
                    g_zh + (size_t)(row0 + r) * MM + k0 + ch * 8);
                cpa(sb + ZL[nx] + r * 144 + ch * 16,
                    g_zl + (size_t)(row0 + r) * MM + k0 + ch * 8);
            }
#pragma unroll
            for (int c = 0; c < 4; c++) {
                int idx = tid + c * 128;
                int kk = idx >> 3, q = idx & 7;
                cpa(sb + UH[nx] + kk * 144 + q * 16,
                    g_Uh + (size_t)(k0 + kk) * MM + col0 + q * 8);
                cpa(sb + UL[nx] + kk * 144 + q * 16,
                    g_Ul + (size_t)(k0 + kk) * MM + col0 + q * 8);
            }
            CPCOMMIT();
            CPWAIT1();
        } else {
            CPWAIT0();
        }
        __syncthreads();

#pragma unroll
        for (int kk = 0; kk < 4; kk++) {
            uint32_t ah0[4], al0[4], ah1[4], al1[4];
            LDSM4(ah0, sb + ZH[cur] + aro + kk * 32);
            LDSM4(al0, sb + ZL[cur] + aro + kk * 32);
            LDSM4(ah1, sb + ZH[cur] + aro + 2304 + kk * 32);
            LDSM4(al1, sb + ZL[cur] + aro + 2304 + kk * 32);
#pragma unroll
            for (int jp = 0; jp < 4; jp++) {
                uint32_t off = (uint32_t)(kk * 2304 + jp * 32);
                uint32_t bh4[4], bl4[4];
                LDSM4T(bh4, sb + UH[cur] + bro + off);
                LDSM4T(bl4, sb + UL[cur] + bro + off);
                MMAB(acc[0][2 * jp], ah0, bh4[0], bh4[1]);
                MMAB(acc[0][2 * jp], ah0, bl4[0], bl4[1]);
                MMAB(acc[0][2 * jp], al0, bh4[0], bh4[1]);
                MMAB(acc[0][2 * jp + 1], ah0, bh4[2], bh4[3]);
                MMAB(acc[0][2 * jp + 1], ah0, bl4[2], bl4[3]);
                MMAB(acc[0][2 * jp + 1], al0, bh4[2], bh4[3]);
                MMAB(acc[1][2 * jp], ah1, bh4[0], bh4[1]);
                MMAB(acc[1][2 * jp], ah1, bl4[0], bl4[1]);
                MMAB(acc[1][2 * jp], al1, bh4[0], bh4[1]);
                MMAB(acc[1][2 * jp + 1], ah1, bh4[2], bh4[3]);
                MMAB(acc[1][2 * jp + 1], ah1, bl4[2], bl4[3]);
                MMAB(acc[1][2 * jp + 1], al1, bh4[2], bh4[3]);
            }
        }
    }

    int r = lane >> 2, cc = (lane & 3) * 2;
#pragma unroll
    for (int rb = 0; rb < 2; rb++) {
        int gr = row0 + wr + rb * 16 + r;
#pragma unroll
        for (int j = 0; j < 8; j++) {
            int gc = col0 + 8 * j + cc;
            float b0v = bo[gc], b1v = bo[gc + 1];
            *(float2*)(out + (size_t)gr * MM + gc) =
                make_float2(acc[rb][j][0] + b0v, acc[rb][j][1] + b1v);
            *(float2*)(out + (size_t)(gr + 8) * MM + gc) =
                make_float2(acc[rb][j][2] + b0v, acc[rb][j][3] + b1v);
        }
    }
}

// ---------------------------------------------------------------------------
extern "C" void kernel_launch(void* const* d_in, const int* in_sizes, int n_in,
                              void* d_out, int out_size) {
    const float* x  = (const float*)d_in[0];
    const float* Wq = (const float*)d_in[1];
    const float* Wk = (const float*)d_in[2];
    const float* Wv = (const float*)d_in[3];
    const float* Wo = (const float*)d_in[4];
    const float* bo = (const float*)d_in[5];
    float* out = (float*)d_out;

    cudaFuncSetAttribute(flashTC, cudaFuncAttributeMaxDynamicSharedMemorySize, FL_SMEM);
    cudaFuncSetAttribute(gemmOutTC, cudaFuncAttributeMaxDynamicSharedMemorySize, GO_SMEM);
    cudaFuncSetAttribute(computeUTC, cudaFuncAttributeMaxDynamicSharedMemorySize, CU_SMEM);
    cudaFuncSetAttribute(computeY, cudaFuncAttributeMaxDynamicSharedMemorySize, CY_SMEM);

    computeApart<<<dim3(16, 8), 256>>>(Wq, Wk);
    reduceA<<<256, 256>>>();
    computeUTC<<<dim3(8, 16), 128, CU_SMEM>>>(Wv, Wo);
    computeY<<<dim3(TT / 128, BB * HH), 256, CY_SMEM>>>(x);
    flashTC<<<dim3(TT / 64, BB * HH), 128, FL_SMEM>>>();
    gemmOutTC<<<dim3(MM / 64, (BB * TT) / 128), 128, GO_SMEM>>>(bo, out);
}

// round 9
// speedup vs baseline: 3.9995x; 1.0545x over previous
#include <cuda_runtime.h>
#include <cuda_bf16.h>
#include <math.h>
#include <stdint.h>

#define BB 2
#define TT 2048
#define HH 16
#define DD 64
#define MM 1024

// Persistent scratch (device globals)
__device__ float g_Ap[8 * HH * DD * DD];               // k-split partials for A
__device__ __nv_bfloat16 g_Ah[HH * DD * DD];           // A split hi  [h][d][d']
__device__ __nv_bfloat16 g_Al[HH * DD * DD];           // A split lo
__device__ __nv_bfloat16 g_xh[BB * HH * TT * DD];      // x per-head, bf16 hi  [bh][t][64]
__device__ __nv_bfloat16 g_xl[BB * HH * TT * DD];      // x per-head, bf16 lo
__device__ __nv_bfloat16 g_zh[BB * TT * MM];           // attn out, bf16 hi    [b][t][1024]
__device__ __nv_bfloat16 g_zl[BB * TT * MM];
__device__ __nv_bfloat16 g_Uh[MM * MM];                // U = Wv@Wo, bf16 hi   [1024][1024]
__device__ __nv_bfloat16 g_Ul[MM * MM];

__device__ __forceinline__ uint32_t pk(float a, float b) {
    __nv_bfloat162 t = __floats2bfloat162_rn(a, b);
    return *reinterpret_cast<uint32_t*>(&t);
}
__device__ __forceinline__ float bfh(float x) {
    return __bfloat162float(__float2bfloat16_rn(x));
}
__device__ __forceinline__ float ex2f(float x) {
    float y;
    asm("ex2.approx.ftz.f32 %0, %1;" : "=f"(y) : "f"(x));
    return y;
}
__device__ __forceinline__ void cpa(uint32_t d, const void* s) {
    asm volatile("cp.async.cg.shared.global [%0], [%1], 16;" :: "r"(d), "l"(s));
}
#define CPCOMMIT() asm volatile("cp.async.commit_group;")
#define CPWAIT1() asm volatile("cp.async.wait_group 1;")
#define CPWAIT0() asm volatile("cp.async.wait_group 0;")

#define LDSM4(R, A) asm volatile( \
    "ldmatrix.sync.aligned.m8n8.x4.shared.b16 {%0,%1,%2,%3},[%4];" \
    : "=r"((R)[0]), "=r"((R)[1]), "=r"((R)[2]), "=r"((R)[3]) : "r"(A))
#define LDSM4T(R, A) asm volatile( \
    "ldmatrix.sync.aligned.m8n8.x4.trans.shared.b16 {%0,%1,%2,%3},[%4];" \
    : "=r"((R)[0]), "=r"((R)[1]), "=r"((R)[2]), "=r"((R)[3]) : "r"(A))
#define MMAB(D, A, B0, B1) asm volatile( \
    "mma.sync.aligned.m16n8k16.row.col.f32.bf16.bf16.f32 " \
    "{%0,%1,%2,%3},{%4,%5,%6,%7},{%8,%9},{%0,%1,%2,%3};" \
    : "+f"((D)[0]), "+f"((D)[1]), "+f"((D)[2]), "+f"((D)[3]) \
    : "r"((A)[0]), "r"((A)[1]), "r"((A)[2]), "r"((A)[3]), "r"(B0), "r"(B1))

// ---------------------------------------------------------------------------
// Kernel 0: split x into per-head bf16 hi/lo, layout [bh][t][64]
// ---------------------------------------------------------------------------
__global__ void __launch_bounds__(256) splitX(const float* __restrict__ x) {
    int fi = blockIdx.x * 256 + threadIdx.x;
    size_t e = (size_t)fi * 4;
    int b = (int)(e / ((size_t)TT * MM));
    size_t rem = e % ((size_t)TT * MM);
    int t = (int)(rem / MM);
    int col = (int)(rem % MM);
    int h = col >> 6, c = col & 63;
    float4 v = *(const float4*)(x + e);
    float hx = bfh(v.x), hy = bfh(v.y), hz = bfh(v.z), hw = bfh(v.w);
    size_t di = (((size_t)(b * 16 + h) * TT + t) * 64 + c);
    *(uint32_t*)((char*)g_xh + di * 2) = pk(hx, hy);
    *(uint32_t*)((char*)g_xh + di * 2 + 4) = pk(hz, hw);
    *(uint32_t*)((char*)g_xl + di * 2) = pk(v.x - hx, v.y - hy);
    *(uint32_t*)((char*)g_xl + di * 2 + 4) = pk(v.z - hz, v.w - hw);
}

// ---------------------------------------------------------------------------
// Kernel 1a: partial A; grid (16 h, 8 kseg)
// ---------------------------------------------------------------------------
__global__ void __launch_bounds__(256) computeApart(const float* __restrict__ Wq,
                                                    const float* __restrict__ Wk) {
    const int h = blockIdx.x, ks = blockIdx.y, tid = threadIdx.x;
    const int tx = tid & 15, ty = tid >> 4;
    __shared__ float wqs[64 * 65];
    __shared__ float wks[64 * 65];
    float acc[4][4];
#pragma unroll
    for (int i = 0; i < 4; i++)
#pragma unroll
        for (int j = 0; j < 4; j++) acc[i][j] = 0.f;
    const float* wqh = Wq + (size_t)h * DD * MM;
    const float* wkh = Wk + (size_t)h * DD * MM;
    for (int m0 = ks * 128; m0 < ks * 128 + 128; m0 += 64) {
        __syncthreads();
#pragma unroll
        for (int c = 0; c < 4; c++) {
            int fi = tid + c * 256, i = fi >> 4, q = fi & 15;
            float4 a = *(const float4*)(wqh + i * MM + m0 + q * 4);
            wqs[i * 65 + q * 4 + 0] = a.x; wqs[i * 65 + q * 4 + 1] = a.y;
            wqs[i * 65 + q * 4 + 2] = a.z; wqs[i * 65 + q * 4 + 3] = a.w;
            float4 b = *(const float4*)(wkh + i * MM + m0 + q * 4);
            wks[i * 65 + q * 4 + 0] = b.x; wks[i * 65 + q * 4 + 1] = b.y;
            wks[i * 65 + q * 4 + 2] = b.z; wks[i * 65 + q * 4 + 3] = b.w;
        }
        __syncthreads();
        for (int m = 0; m < 64; m++) {
            float a[4], b[4];
#pragma unroll
            for (int i = 0; i < 4; i++) a[i] = wqs[(ty * 4 + i) * 65 + m];
#pragma unroll
            for (int j = 0; j < 4; j++) b[j] = wks[(tx * 4 + j) * 65 + m];
#pragma unroll
            for (int i = 0; i < 4; i++)
#pragma unroll
                for (int j = 0; j < 4; j++) acc[i][j] += a[i] * b[j];
        }
    }
    float* o = g_Ap + (size_t)ks * (HH * DD * DD) + h * DD * DD;
#pragma unroll
    for (int i = 0; i < 4; i++)
#pragma unroll
        for (int j = 0; j < 4; j++)
            o[(ty * 4 + i) * DD + tx * 4 + j] = acc[i][j];
}

// Kernel 1b: reduce partials, scale, split to bf16 hi/lo
__global__ void __launch_bounds__(256) reduceA() {
    int i = blockIdx.x * 256 + threadIdx.x;
    float s = 0.f;
#pragma unroll
    for (int k = 0; k < 8; k++) s += g_Ap[(size_t)k * (HH * DD * DD) + i];
    s *= (0.125f * 1.4426950408889634f);
    float hv = bfh(s);
    g_Ah[i] = __float2bfloat16_rn(s);
    g_Al[i] = __float2bfloat16_rn(s - hv);
}

// ---------------------------------------------------------------------------
// Kernel 2: U = Wv_h @ Wo_h — bf16x3 mma.sync, 256 threads (8 warps)
// warp w: rows 16*(w&3), cols 64*(w>>2) of the 64x128 tile
// ---------------------------------------------------------------------------
#define CU_SMEM 55296

__global__ void __launch_bounds__(256, 1) computeUTC(const float* __restrict__ Wv,
                                                     const float* __restrict__ Wo) {
    extern __shared__ __align__(16) char sm[];
    const uint32_t sb = (uint32_t)__cvta_generic_to_shared(sm);
    const uint32_t AH[2] = {0u, 27648u}, AL[2] = {5120u, 32768u};
    const uint32_t BH[2] = {10240u, 37888u}, BL[2] = {18944u, 46592u};
    const int tid = threadIdx.x, lane = tid & 31, w = tid >> 5;
    const int h = blockIdx.y, col0 = blockIdx.x * 128;
    const int wr = (w & 3) * 16, wc = (w >> 2) * 64;
    const float* wvh = Wv + (size_t)h * DD * MM;
    const float* woh = Wo + (size_t)h * MM * MM;

#pragma unroll
    for (int c = 0; c < 2; c++) {
        int idx = tid + c * 256;        // 0..511
        int r = idx >> 3, kq = idx & 7;
        float4 v = *(const float4*)(wvh + (size_t)r * MM + kq * 4);
        float hx = bfh(v.x), hy = bfh(v.y), hz = bfh(v.z), hw = bfh(v.w);
        uint32_t o = (uint32_t)(r * 80 + kq * 8);
        *(uint32_t*)(sm + AH[0] + o) = pk(hx, hy);
        *(uint32_t*)(sm + AH[0] + o + 4) = pk(hz, hw);
        *(uint32_t*)(sm + AL[0] + o) = pk(v.x - hx, v.y - hy);
        *(uint32_t*)(sm + AL[0] + o + 4) = pk(v.z - hz, v.w - hw);
    }
#pragma unroll
    for (int c = 0; c < 4; c++) {
        int fi = tid + c * 256;         // 0..1023
        int kk = fi >> 5, q = fi & 31;
        float4 v = *(const float4*)(woh + (size_t)kk * MM + col0 + q * 4);
        float hx = bfh(v.x), hy = bfh(v.y), hz = bfh(v.z), hw = bfh(v.w);
        uint32_t o = (uint32_t)(kk * 272 + q * 8);
        *(uint32_t*)(sm + BH[0] + o) = pk(hx, hy);
        *(uint32_t*)(sm + BH[0] + o + 4) = pk(hz, hw);
        *(uint32_t*)(sm + BL[0] + o) = pk(v.x - hx, v.y - hy);
        *(uint32_t*)(sm + BL[0] + o + 4) = pk(v.z - hz, v.w - hw);
    }
    __syncthreads();

    float acc[8][4];
#pragma unroll
    for (int j = 0; j < 8; j++)
        acc[j][0] = acc[j][1] = acc[j][2] = acc[j][3] = 0.f;

    const uint32_t aro = (uint32_t)((wr + (lane & 15)) * 80 + ((lane >> 4) << 3) * 2);
    const uint32_t bro = (uint32_t)((lane & 15) * 272 + (wc + ((lane >> 4) << 3)) * 2);

    for (int it = 0; it < 32; it++) {
        const int cur = it & 1, nx = cur ^ 1;
        float4 pv[2], po[4];
        if (it < 31) {
            int m0 = (it + 1) * 32;
#pragma unroll
            for (int c = 0; c < 2; c++) {
                int idx = tid + c * 256;
                int r = idx >> 3, kq = idx & 7;
                pv[c] = *(const float4*)(wvh + (size_t)r * MM + m0 + kq * 4);
            }
#pragma unroll
            for (int c = 0; c < 4; c++) {
                int fi = tid + c * 256;
                int kk = fi >> 5, q = fi & 31;
                po[c] = *(const float4*)(woh + (size_t)(m0 + kk) * MM + col0 + q * 4);
            }
        }

#pragma unroll
        for (int kk = 0; kk < 2; kk++) {
            uint32_t ah4[4], al4[4];
            LDSM4(ah4, sb + AH[cur] + aro + kk * 32);
            LDSM4(al4, sb + AL[cur] + aro + kk * 32);
#pragma unroll
            for (int jp = 0; jp < 4; jp++) {
                uint32_t off = (uint32_t)(kk * 4352 + jp * 32);
                uint32_t bh4[4], bl4[4];
                LDSM4T(bh4, sb + BH[cur] + bro + off);
                LDSM4T(bl4, sb + BL[cur] + bro + off);
                MMAB(acc[2 * jp], ah4, bh4[0], bh4[1]);
                MMAB(acc[2 * jp], ah4, bl4[0], bl4[1]);
                MMAB(acc[2 * jp], al4, bh4[0], bh4[1]);
                MMAB(acc[2 * jp + 1], ah4, bh4[2], bh4[3]);
                MMAB(acc[2 * jp + 1], ah4, bl4[2], bl4[3]);
                MMAB(acc[2 * jp + 1], al4, bh4[2], bh4[3]);
            }
        }

        if (it < 31) {
#pragma unroll
            for (int c = 0; c < 2; c++) {
                int idx = tid + c * 256;
                int r = idx >> 3, kq = idx & 7;
                float4 v = pv[c];
                float hx = bfh(v.x), hy = bfh(v.y), hz = bfh(v.z), hw = bfh(v.w);
                uint32_t o = (uint32_t)(r * 80 + kq * 8);
                *(uint32_t*)(sm + AH[nx] + o) = pk(hx, hy);
                *(uint32_t*)(sm + AH[nx] + o + 4) = pk(hz, hw);
                *(uint32_t*)(sm + AL[nx] + o) = pk(v.x - hx, v.y - hy);
                *(uint32_t*)(sm + AL[nx] + o + 4) = pk(v.z - hz, v.w - hw);
            }
#pragma unroll
            for (int c = 0; c < 4; c++) {
                int fi = tid + c * 256;
                int kk = fi >> 5, q = fi & 31;
                float4 v = po[c];
                float hx = bfh(v.x), hy = bfh(v.y), hz = bfh(v.z), hw = bfh(v.w);
                uint32_t o = (uint32_t)(kk * 272 + q * 8);
                *(uint32_t*)(sm + BH[nx] + o) = pk(hx, hy);
                *(uint32_t*)(sm + BH[nx] + o + 4) = pk(hz, hw);
                *(uint32_t*)(sm + BL[nx] + o) = pk(v.x - hx, v.y - hy);
                *(uint32_t*)(sm + BL[nx] + o + 4) = pk(v.z - hz, v.w - hw);
            }
        }
        __syncthreads();
    }

    int r = lane >> 2, cc = (lane & 3) * 2;
    int row = h * 64 + wr + r;
#pragma unroll
    for (int j = 0; j < 8; j++) {
        int gc = col0 + wc + 8 * j + cc;
        float v0 = acc[j][0], v1 = acc[j][1], v2 = acc[j][2], v3 = acc[j][3];
        float h0 = bfh(v0), h1 = bfh(v1), h2 = bfh(v2), h3 = bfh(v3);
        size_t ia = (size_t)row * MM + gc;
        size_t ib = (size_t)(row + 8) * MM + gc;
        *(uint32_t*)((char*)g_Uh + ia * 2) = pk(h0, h1);
        *(uint32_t*)((char*)g_Ul + ia * 2) = pk(v0 - h0, v1 - h1);
        *(uint32_t*)((char*)g_Uh + ib * 2) = pk(h2, h3);
        *(uint32_t*)((char*)g_Ul + ib * 2) = pk(v2 - h2, v3 - h3);
    }
}

// ---------------------------------------------------------------------------
// Kernel 4: flash attention — Q computed in-kernel via bf16x3 MMA (x @ A)
// 128 threads (4 warps), 64-row Q tiles, 2 CTA/SM
// ---------------------------------------------------------------------------
#define FL_SMEM 73728

__global__ void __launch_bounds__(128, 2) flashTC() {
    extern __shared__ __align__(16) char sm[];
    const uint32_t sb = (uint32_t)__cvta_generic_to_shared(sm);
    const uint32_t KH0 = 0u, KL0 = 18432u, KH1 = 36864u, KL1 = 55296u;
    const uint32_t QH = KH1, QL = KL1;   // x rows for Q overlay K buffer 1
    const int tid = threadIdx.x, lane = tid & 31, w = tid >> 5;
    const int t0 = blockIdx.x * 64, bh = blockIdx.y;
    const int b = bh >> 4, h = bh & 15;

    const __nv_bfloat16* xh = g_xh + (size_t)bh * TT * 64;
    const __nv_bfloat16* xl = g_xl + (size_t)bh * TT * 64;

    // Prologue 1: stage x rows t0..t0+63 (Q source) -> buf1, A matrix -> buf0
    {
        const __nv_bfloat16* Ah = g_Ah + (size_t)h * DD * DD;
        const __nv_bfloat16* Al = g_Al + (size_t)h * DD * DD;
#pragma unroll
        for (int c = 0; c < 4; c++) {
            int idx = tid + c * 128;       // 0..511
            int r = idx >> 3, ch = idx & 7;
            cpa(sb + QH + r * 144 + ch * 16, xh + (size_t)(t0 + r) * 64 + ch * 8);
            cpa(sb + QL + r * 144 + ch * 16, xl + (size_t)(t0 + r) * 64 + ch * 8);
            cpa(sb + KH0 + r * 144 + ch * 16, Ah + (size_t)r * 64 + ch * 8);
            cpa(sb + KL0 + r * 144 + ch * 16, Al + (size_t)r * 64 + ch * 8);
        }
        CPCOMMIT();
        CPWAIT0();
        __syncthreads();
    }

    // Prologue 2: Q = x @ A via bf16x3 MMA; C-fragments -> A-fragments (pk trick)
    uint32_t qh[4][4], ql[4][4];
    {
        float QS[8][4];
#pragma unroll
        for (int j = 0; j < 8; j++) { QS[j][0] = QS[j][1] = QS[j][2] = QS[j][3] = 0.f; }
        uint32_t xro = (uint32_t)((16 * w + (lane & 15)) * 144 + ((lane >> 4) << 3) * 2);
        uint32_t aro = (uint32_t)((lane & 15) * 144 + ((lane >> 4) << 3) * 2);
#pragma unroll
        for (int kk = 0; kk < 4; kk++) {
            uint32_t xh4[4], xl4[4];
            LDSM4(xh4, sb + QH + xro + kk * 32);
            LDSM4(xl4, sb + QL + xro + kk * 32);
#pragma unroll
            for (int jp = 0; jp < 4; jp++) {
                uint32_t off = (uint32_t)(kk * 2304 + jp * 32);
                uint32_t bh4[4], bl4[4];
                LDSM4T(bh4, sb + KH0 + aro + off);
                LDSM4T(bl4, sb + KL0 + aro + off);
                MMAB(QS[2 * jp], xh4, bh4[0], bh4[1]);
                MMAB(QS[2 * jp], xh4, bl4[0], bl4[1]);
                MMAB(QS[2 * jp], xl4, bh4[0], bh4[1]);
                MMAB(QS[2 * jp + 1], xh4, bh4[2], bh4[3]);
                MMAB(QS[2 * jp + 1], xh4, bl4[2], bl4[3]);
                MMAB(QS[2 * jp + 1], xl4, bh4[2], bh4[3]);
            }
        }
#pragma unroll
        for (int j = 0; j < 8; j++) {
            float q0 = QS[j][0], q1 = QS[j][1], q2 = QS[j][2], q3 = QS[j][3];
            float h0 = bfh(q0), h1 = bfh(q1), h2 = bfh(q2), h3 = bfh(q3);
            int kkq = j >> 1, ps = (j & 1) << 1;
            qh[kkq][ps] = pk(h0, h1);
            qh[kkq][ps + 1] = pk(h2, h3);
            ql[kkq][ps] = pk(q0 - h0, q1 - h1);
            ql[kkq][ps + 1] = pk(q2 - h2, q3 - h3);
        }
    }
    __syncthreads();   // all warps done reading buf0 (A) and buf1 (x)

    // Prologue 3: stage K tile 0 -> buf0
#pragma unroll
    for (int c = 0; c < 8; c++) {
        int idx = tid + c * 128;
        int r = idx >> 3, ch = idx & 7;
        cpa(sb + KH0 + r * 144 + ch * 16, xh + (size_t)r * 64 + ch * 8);
        cpa(sb + KL0 + r * 144 + ch * 16, xl + (size_t)r * 64 + ch * 8);
    }
    CPCOMMIT();

    float acc[8][4];
    float mrow0 = -INFINITY, mrow1 = -INFINITY, lrow0 = 0.f, lrow1 = 0.f;
#pragma unroll
    for (int j = 0; j < 8; j++) { acc[j][0] = acc[j][1] = acc[j][2] = acc[j][3] = 0.f; }

    for (int it = 0; it < 16; it++) {
        const uint32_t curH = (it & 1) ? KH1 : KH0;
        const uint32_t curL = (it & 1) ? KL1 : KL0;
        const uint32_t nxtH = (it & 1) ? KH0 : KH1;
        const uint32_t nxtL = (it & 1) ? KL0 : KL1;

        __syncthreads();
        if (it < 15) {
            int s0 = (it + 1) * 128;
#pragma unroll
            for (int c = 0; c < 8; c++) {
                int idx = tid + c * 128;
                int r = idx >> 3, ch = idx & 7;
                cpa(sb + nxtH + r * 144 + ch * 16, xh + (size_t)(s0 + r) * 64 + ch * 8);
                cpa(sb + nxtL + r * 144 + ch * 16, xl + (size_t)(s0 + r) * 64 + ch * 8);
            }
            CPCOMMIT();
            CPWAIT1();
        } else {
            CPWAIT0();
        }
        __syncthreads();

        float S[16][4];
#pragma unroll
        for (int j = 0; j < 16; j++) { S[j][0] = S[j][1] = S[j][2] = S[j][3] = 0.f; }
        {
            uint32_t rbase = sb + (uint32_t)(((lane & 7) + ((lane >> 4) << 3)) * 144 +
                                             (((lane >> 3) & 1) << 3) * 2);
#pragma unroll
            for (int jp = 0; jp < 8; jp++) {
#pragma unroll
                for (int kk = 0; kk < 4; kk++) {
                    uint32_t off = (uint32_t)(jp * 2304 + kk * 32);
                    uint32_t bh4[4], bl4[4];
                    LDSM4(bh4, rbase + curH + off);
                    LDSM4(bl4, rbase + curL + off);
                    MMAB(S[2 * jp], qh[kk], bh4[0], bh4[1]);
                    MMAB(S[2 * jp], qh[kk], bl4[0], bl4[1]);
                    MMAB(S[2 * jp], ql[kk], bh4[0], bh4[1]);
                    MMAB(S[2 * jp + 1], qh[kk], bh4[2], bh4[3]);
                    MMAB(S[2 * jp + 1], qh[kk], bl4[2], bl4[3]);
                    MMAB(S[2 * jp + 1], ql[kk], bh4[2], bh4[3]);
                }
            }
        }

        float mx0 = -INFINITY, mx1 = -INFINITY;
#pragma unroll
        for (int j = 0; j < 16; j++) {
            mx0 = fmaxf(mx0, fmaxf(S[j][0], S[j][1]));
            mx1 = fmaxf(mx1, fmaxf(S[j][2], S[j][3]));
        }
        mx0 = fmaxf(mx0, __shfl_xor_sync(0xffffffffu, mx0, 1));
        mx0 = fmaxf(mx0, __shfl_xor_sync(0xffffffffu, mx0, 2));
        mx1 = fmaxf(mx1, __shfl_xor_sync(0xffffffffu, mx1, 1));
        mx1 = fmaxf(mx1, __shfl_xor_sync(0xffffffffu, mx1, 2));
        float mn0 = fmaxf(mrow0, mx0), mn1 = fmaxf(mrow1, mx1);
        float sc0 = ex2f(mrow0 - mn0), sc1 = ex2f(mrow1 - mn1);
        mrow0 = mn0; mrow1 = mn1;

        uint32_t php[8][4], plp[8][4];
        float rs0 = 0.f, rs1 = 0.f;
#pragma unroll
        for (int j = 0; j < 16; j++) {
            float p0 = ex2f(S[j][0] - mn0), p1 = ex2f(S[j][1] - mn0);
            float p2 = ex2f(S[j][2] - mn1), p3 = ex2f(S[j][3] - mn1);
            rs0 += p0 + p1; rs1 += p2 + p3;
            float h0 = bfh(p0), h1 = bfh(p1), h2 = bfh(p2), h3 = bfh(p3);
            int ss = j >> 1, ps = (j & 1) << 1;
            php[ss][ps] = pk(h0, h1);
            php[ss][ps + 1] = pk(h2, h3);
            plp[ss][ps] = pk(p0 - h0, p1 - h1);
            plp[ss][ps + 1] = pk(p2 - h2, p3 - h3);
        }
        rs0 += __shfl_xor_sync(0xffffffffu, rs0, 1);
        rs0 += __shfl_xor_sync(0xffffffffu, rs0, 2);
        rs1 += __shfl_xor_sync(0xffffffffu, rs1, 1);
        rs1 += __shfl_xor_sync(0xffffffffu, rs1, 2);
        lrow0 = lrow0 * sc0 + rs0;
        lrow1 = lrow1 * sc1 + rs1;
#pragma unroll
        for (int j = 0; j < 8; j++) {
            acc[j][0] *= sc0; acc[j][1] *= sc0; acc[j][2] *= sc1; acc[j][3] *= sc1;
        }

        {
            uint32_t rbase = sb + (uint32_t)((lane & 15) * 144 + ((lane >> 4) << 3) * 2);
#pragma unroll
            for (int ss = 0; ss < 8; ss++) {
#pragma unroll
                for (int jp = 0; jp < 4; jp++) {
                    uint32_t off = (uint32_t)(ss * 2304 + jp * 32);
                    uint32_t bh4[4], bl4[4];
                    LDSM4T(bh4, rbase + curH + off);
                    LDSM4T(bl4, rbase + curL + off);
                    MMAB(acc[2 * jp], php[ss], bh4[0], bh4[1]);
                    MMAB(acc[2 * jp], php[ss], bl4[0], bl4[1]);
                    MMAB(acc[2 * jp], plp[ss], bh4[0], bh4[1]);
                    MMAB(acc[2 * jp + 1], php[ss], bh4[2], bh4[3]);
                    MMAB(acc[2 * jp + 1], php[ss], bl4[2], bl4[3]);
                    MMAB(acc[2 * jp + 1], plp[ss], bh4[2], bh4[3]);
                }
            }
        }
    }

    float inv0 = 1.f / lrow0, inv1 = 1.f / lrow1;
    int r0 = lane >> 2, c0 = (lane & 3) * 2;
    size_t rowA = ((size_t)b * TT + t0 + 16 * w + r0) * MM + h * 64;
    size_t rowB = rowA + 8 * MM;
#pragma unroll
    for (int j = 0; j < 8; j++) {
        float o0 = acc[j][0] * inv0, o1 = acc[j][1] * inv0;
        float o2 = acc[j][2] * inv1, o3 = acc[j][3] * inv1;
        float h0 = bfh(o0), h1 = bfh(o1), h2 = bfh(o2), h3 = bfh(o3);
        size_t ia = rowA + 8 * j + c0, ib = rowB + 8 * j + c0;
        *(uint32_t*)((char*)g_zh + ia * 2) = pk(h0, h1);
        *(uint32_t*)((char*)g_zl + ia * 2) = pk(o0 - h0, o1 - h1);
        *(uint32_t*)((char*)g_zh + ib * 2) = pk(h2, h3);
        *(uint32_t*)((char*)g_zl + ib * 2) = pk(o2 - h2, o3 - h3);
    }
}

// ---------------------------------------------------------------------------
// Kernel 5: out = z @ U + bo — 128 threads, tile 128x64, k-chunk 64, 2 CTA/SM
// ---------------------------------------------------------------------------
#define GO_SMEM 110592

__global__ void __launch_bounds__(128, 2) gemmOutTC(const float* __restrict__ bo,
                                                    float* __restrict__ out) {
    extern __shared__ __align__(16) char sm[];
    const uint32_t sb = (uint32_t)__cvta_generic_to_shared(sm);
    const uint32_t ZH[2] = {0u, 55296u}, ZL[2] = {18432u, 73728u};
    const uint32_t UH[2] = {36864u, 92160u}, UL[2] = {46080u, 101376u};
    const int tid = threadIdx.x, lane = tid & 31, w = tid >> 5;
    const int col0 = blockIdx.x * 64, row0 = blockIdx.y * 128;
    const int wr = w * 32;

#pragma unroll
    for (int c = 0; c < 8; c++) {
        int idx = tid + c * 128;
        int r = idx >> 3, ch = idx & 7;
        cpa(sb + ZH[0] + r * 144 + ch * 16, g_zh + (size_t)(row0 + r) * MM + ch * 8);
        cpa(sb + ZL[0] + r * 144 + ch * 16, g_zl + (size_t)(row0 + r) * MM + ch * 8);
    }
#pragma unroll
    for (int c = 0; c < 4; c++) {
        int idx = tid + c * 128;
        int kk = idx >> 3, q = idx & 7;
        cpa(sb + UH[0] + kk * 144 + q * 16, g_Uh + (size_t)kk * MM + col0 + q * 8);
        cpa(sb + UL[0] + kk * 144 + q * 16, g_Ul + (size_t)kk * MM + col0 + q * 8);
    }
    CPCOMMIT();

    float acc[2][8][4];
#pragma unroll
    for (int rb = 0; rb < 2; rb++)
#pragma unroll
        for (int j = 0; j < 8; j++)
            acc[rb][j][0] = acc[rb][j][1] = acc[rb][j][2] = acc[rb][j][3] = 0.f;

    const uint32_t aro = (uint32_t)((wr + (lane & 15)) * 144 + ((lane >> 4) << 3) * 2);
    const uint32_t bro = (uint32_t)((lane & 15) * 144 + ((lane >> 4) << 3) * 2);

    for (int it = 0; it < 16; it++) {
        const int cur = it & 1, nx = cur ^ 1;
        __syncthreads();
        if (it < 15) {
            int k0 = (it + 1) * 64;
#pragma unroll
            for (int c = 0; c < 8; c++) {
                int idx = tid + c * 128;
                int r = idx >> 3, ch = idx & 7;
                cpa(sb + ZH[nx] + r * 144 + ch * 16,
                    g_zh + (size_t)(row0 + r) * MM + k0 + ch * 8);
                cpa(sb + ZL[nx] + r * 144 + ch * 16,
                    g_zl + (size_t)(row0 + r) * MM + k0 + ch * 8);
            }
#pragma unroll
            for (int c = 0; c < 4; c++) {
                int idx = tid + c * 128;
                int kk = idx >> 3, q = idx & 7;
                cpa(sb + UH[nx] + kk * 144 + q * 16,
                    g_Uh + (size_t)(k0 + kk) * MM + col0 + q * 8);
                cpa(sb + UL[nx] + kk * 144 + q * 16,
                    g_Ul + (size_t)(k0 + kk) * MM + col0 + q * 8);
            }
            CPCOMMIT();
            CPWAIT1();
        } else {
            CPWAIT0();
        }
        __syncthreads();

#pragma unroll
        for (int kk = 0; kk < 4; kk++) {
            uint32_t ah0[4], al0[4], ah1[4], al1[4];
            LDSM4(ah0, sb + ZH[cur] + aro + kk * 32);
            LDSM4(al0, sb + ZL[cur] + aro + kk * 32);
            LDSM4(ah1, sb + ZH[cur] + aro + 2304 + kk * 32);
            LDSM4(al1, sb + ZL[cur] + aro + 2304 + kk * 32);
#pragma unroll
            for (int jp = 0; jp < 4; jp++) {
                uint32_t off = (uint32_t)(kk * 2304 + jp * 32);
                uint32_t bh4[4], bl4[4];
                LDSM4T(bh4, sb + UH[cur] + bro + off);
                LDSM4T(bl4, sb + UL[cur] + bro + off);
                MMAB(acc[0][2 * jp], ah0, bh4[0], bh4[1]);
                MMAB(acc[0][2 * jp], ah0, bl4[0], bl4[1]);
                MMAB(acc[0][2 * jp], al0, bh4[0], bh4[1]);
                MMAB(acc[0][2 * jp + 1], ah0, bh4[2], bh4[3]);
                MMAB(acc[0][2 * jp + 1], ah0, bl4[2], bl4[3]);
                MMAB(acc[0][2 * jp + 1], al0, bh4[2], bh4[3]);
                MMAB(acc[1][2 * jp], ah1, bh4[0], bh4[1]);
                MMAB(acc[1][2 * jp], ah1, bl4[0], bl4[1]);
                MMAB(acc[1][2 * jp], al1, bh4[0], bh4[1]);
                MMAB(acc[1][2 * jp + 1], ah1, bh4[2], bh4[3]);
                MMAB(acc[1][2 * jp + 1], ah1, bl4[2], bl4[3]);
                MMAB(acc[1][2 * jp + 1], al1, bh4[2], bh4[3]);
            }
        }
    }

    int r = lane >> 2, cc = (lane & 3) * 2;
#pragma unroll
    for (int rb = 0; rb < 2; rb++) {
        int gr = row0 + wr + rb * 16 + r;
#pragma unroll
        for (int j = 0; j < 8; j++) {
            int gc = col0 + 8 * j + cc;
            float b0v = bo[gc], b1v = bo[gc + 1];
            *(float2*)(out + (size_t)gr * MM + gc) =
                make_float2(acc[rb][j][0] + b0v, acc[rb][j][1] + b1v);
            *(float2*)(out + (size_t)(gr + 8) * MM + gc) =
                make_float2(acc[rb][j][2] + b0v, acc[rb][j][3] + b1v);
        }
    }
}

// ---------------------------------------------------------------------------
extern "C" void kernel_launch(void* const* d_in, const int* in_sizes, int n_in,
                              void* d_out, int out_size) {
    const float* x  = (const float*)d_in[0];
    const float* Wq = (const float*)d_in[1];
    const float* Wk = (const float*)d_in[2];
    const float* Wv = (const float*)d_in[3];
    const float* Wo = (const float*)d_in[4];
    const float* bo = (const float*)d_in[5];
    float* out = (float*)d_out;

    cudaFuncSetAttribute(flashTC, cudaFuncAttributeMaxDynamicSharedMemorySize, FL_SMEM);
    cudaFuncSetAttribute(gemmOutTC, cudaFuncAttributeMaxDynamicSharedMemorySize, GO_SMEM);
    cudaFuncSetAttribute(computeUTC, cudaFuncAttributeMaxDynamicSharedMemorySize, CU_SMEM);

    splitX<<<4096, 256>>>(x);
    computeApart<<<dim3(16, 8), 256>>>(Wq, Wk);
    reduceA<<<256, 256>>>();
    computeUTC<<<dim3(8, 16), 256, CU_SMEM>>>(Wv, Wo);
    flashTC<<<dim3(TT / 64, BB * HH), 128, FL_SMEM>>>();
    gemmOutTC<<<dim3(MM / 64, (BB * TT) / 128), 128, GO_SMEM>>>(bo, out);
}

// round 10
// speedup vs baseline: 4.2797x; 1.0701x over previous
#include <cuda_runtime.h>
#include <cuda_fp16.h>
#include <math.h>
#include <stdint.h>

#define BB 2
#define TT 2048
#define HH 16
#define DD 64
#define MM 1024

// Persistent scratch (device globals)
__device__ float g_Ap[8 * HH * DD * DD];        // k-split partials for A
__device__ float g_Up[4 * MM * MM];             // k-split partials for U (fp32)
__device__ __half g_Ah[HH * DD * DD];           // A split hi  [h][d][d']
__device__ __half g_Al[HH * DD * DD];           // A split lo
__device__ __half g_xh[BB * HH * TT * DD];      // x per-head, fp16 hi  [bh][t][64]
__device__ __half g_xl[BB * HH * TT * DD];      // x per-head, fp16 lo
__device__ __half g_zh[BB * TT * MM];           // attn out, fp16 hi    [b][t][1024]
__device__ __half g_zl[BB * TT * MM];
__device__ __half g_Uh[MM * MM];                // U = Wv@Wo, fp16 hi
__device__ __half g_Ul[MM * MM];

__device__ __forceinline__ uint32_t pkh(float a, float b) {
    __half2 t = __floats2half2_rn(a, b);
    return *reinterpret_cast<uint32_t*>(&t);
}
__device__ __forceinline__ float hfh(float x) {
    return __half2float(__float2half_rn(x));
}
__device__ __forceinline__ float ex2f(float x) {
    float y;
    asm("ex2.approx.ftz.f32 %0, %1;" : "=f"(y) : "f"(x));
    return y;
}
__device__ __forceinline__ void cpa(uint32_t d, const void* s) {
    asm volatile("cp.async.cg.shared.global [%0], [%1], 16;" :: "r"(d), "l"(s));
}
#define CPCOMMIT() asm volatile("cp.async.commit_group;")
#define CPWAIT1() asm volatile("cp.async.wait_group 1;")
#define CPWAIT0() asm volatile("cp.async.wait_group 0;")

#define LDSM4(R, A) asm volatile( \
    "ldmatrix.sync.aligned.m8n8.x4.shared.b16 {%0,%1,%2,%3},[%4];" \
    : "=r"((R)[0]), "=r"((R)[1]), "=r"((R)[2]), "=r"((R)[3]) : "r"(A))
#define LDSM4T(R, A) asm volatile( \
    "ldmatrix.sync.aligned.m8n8.x4.trans.shared.b16 {%0,%1,%2,%3},[%4];" \
    : "=r"((R)[0]), "=r"((R)[1]), "=r"((R)[2]), "=r"((R)[3]) : "r"(A))
#define MMAH(D, A, B0, B1) asm volatile( \
    "mma.sync.aligned.m16n8k16.row.col.f32.f16.f16.f32 " \
    "{%0,%1,%2,%3},{%4,%5,%6,%7},{%8,%9},{%0,%1,%2,%3};" \
    : "+f"((D)[0]), "+f"((D)[1]), "+f"((D)[2]), "+f"((D)[3]) \
    : "r"((A)[0]), "r"((A)[1]), "r"((A)[2]), "r"((A)[3]), "r"(B0), "r"(B1))

// ---------------------------------------------------------------------------
// Kernel 0: split x into per-head fp16 hi/lo, layout [bh][t][64]
// ---------------------------------------------------------------------------
__global__ void __launch_bounds__(256) splitX(const float* __restrict__ x) {
    int fi = blockIdx.x * 256 + threadIdx.x;
    size_t e = (size_t)fi * 4;
    int b = (int)(e / ((size_t)TT * MM));
    size_t rem = e % ((size_t)TT * MM);
    int t = (int)(rem / MM);
    int col = (int)(rem % MM);
    int h = col >> 6, c = col & 63;
    float4 v = *(const float4*)(x + e);
    float hx = hfh(v.x), hy = hfh(v.y), hz = hfh(v.z), hw = hfh(v.w);
    size_t di = (((size_t)(b * 16 + h) * TT + t) * 64 + c);
    *(uint32_t*)((char*)g_xh + di * 2) = pkh(hx, hy);
    *(uint32_t*)((char*)g_xh + di * 2 + 4) = pkh(hz, hw);
    *(uint32_t*)((char*)g_xl + di * 2) = pkh(v.x - hx, v.y - hy);
    *(uint32_t*)((char*)g_xl + di * 2 + 4) = pkh(v.z - hz, v.w - hw);
}

// ---------------------------------------------------------------------------
// Kernel 1a: partial A; grid (16 h, 8 kseg)
// ---------------------------------------------------------------------------
__global__ void __launch_bounds__(256) computeApart(const float* __restrict__ Wq,
                                                    const float* __restrict__ Wk) {
    const int h = blockIdx.x, ks = blockIdx.y, tid = threadIdx.x;
    const int tx = tid & 15, ty = tid >> 4;
    __shared__ float wqs[64 * 65];
    __shared__ float wks[64 * 65];
    float acc[4][4];
#pragma unroll
    for (int i = 0; i < 4; i++)
#pragma unroll
        for (int j = 0; j < 4; j++) acc[i][j] = 0.f;
    const float* wqh = Wq + (size_t)h * DD * MM;
    const float* wkh = Wk + (size_t)h * DD * MM;
    for (int m0 = ks * 128; m0 < ks * 128 + 128; m0 += 64) {
        __syncthreads();
#pragma unroll
        for (int c = 0; c < 4; c++) {
            int fi = tid + c * 256, i = fi >> 4, q = fi & 15;
            float4 a = *(const float4*)(wqh + i * MM + m0 + q * 4);
            wqs[i * 65 + q * 4 + 0] = a.x; wqs[i * 65 + q * 4 + 1] = a.y;
            wqs[i * 65 + q * 4 + 2] = a.z; wqs[i * 65 + q * 4 + 3] = a.w;
            float4 b = *(const float4*)(wkh + i * MM + m0 + q * 4);
            wks[i * 65 + q * 4 + 0] = b.x; wks[i * 65 + q * 4 + 1] = b.y;
            wks[i * 65 + q * 4 + 2] = b.z; wks[i * 65 + q * 4 + 3] = b.w;
        }
        __syncthreads();
        for (int m = 0; m < 64; m++) {
            float a[4], b[4];
#pragma unroll
            for (int i = 0; i < 4; i++) a[i] = wqs[(ty * 4 + i) * 65 + m];
#pragma unroll
            for (int j = 0; j < 4; j++) b[j] = wks[(tx * 4 + j) * 65 + m];
#pragma unroll
            for (int i = 0; i < 4; i++)
#pragma unroll
                for (int j = 0; j < 4; j++) acc[i][j] += a[i] * b[j];
        }
    }
    float* o = g_Ap + (size_t)ks * (HH * DD * DD) + h * DD * DD;
#pragma unroll
    for (int i = 0; i < 4; i++)
#pragma unroll
        for (int j = 0; j < 4; j++)
            o[(ty * 4 + i) * DD + tx * 4 + j] = acc[i][j];
}

// Kernel 1b: reduce partials, scale, split to fp16 hi/lo
__global__ void __launch_bounds__(256) reduceA() {
    int i = blockIdx.x * 256 + threadIdx.x;
    float s = 0.f;
#pragma unroll
    for (int k = 0; k < 8; k++) s += g_Ap[(size_t)k * (HH * DD * DD) + i];
    s *= (0.125f * 1.4426950408889634f);
    float hv = hfh(s);
    g_Ah[i] = __float2half_rn(s);
    g_Al[i] = __float2half_rn(s - hv);
}

// ---------------------------------------------------------------------------
// Kernel 2a: U partials — fp16x3 mma.sync, k-split x4, fp32 partial output
// grid (8 col-tiles, 16 h, 4 ks), 256 threads; tile 64x128, k-range 256
// ---------------------------------------------------------------------------
#define CU_SMEM 55296

__global__ void __launch_bounds__(256, 1) computeUTC(const float* __restrict__ Wv,
                                                     const float* __restrict__ Wo) {
    extern __shared__ __align__(16) char sm[];
    const uint32_t sb = (uint32_t)__cvta_generic_to_shared(sm);
    const uint32_t AH[2] = {0u, 27648u}, AL[2] = {5120u, 32768u};
    const uint32_t BH[2] = {10240u, 37888u}, BL[2] = {18944u, 46592u};
    const int tid = threadIdx.x, lane = tid & 31, w = tid >> 5;
    const int h = blockIdx.y, col0 = blockIdx.x * 128, ks = blockIdx.z;
    const int kbase = ks * 256;
    const int wr = (w & 3) * 16, wc = (w >> 2) * 64;
    const float* wvh = Wv + (size_t)h * DD * MM;
    const float* woh = Wo + (size_t)h * MM * MM;

#pragma unroll
    for (int c = 0; c < 2; c++) {
        int idx = tid + c * 256;
        int r = idx >> 3, kq = idx & 7;
        float4 v = *(const float4*)(wvh + (size_t)r * MM + kbase + kq * 4);
        float hx = hfh(v.x), hy = hfh(v.y), hz = hfh(v.z), hw = hfh(v.w);
        uint32_t o = (uint32_t)(r * 80 + kq * 8);
        *(uint32_t*)(sm + AH[0] + o) = pkh(hx, hy);
        *(uint32_t*)(sm + AH[0] + o + 4) = pkh(hz, hw);
        *(uint32_t*)(sm + AL[0] + o) = pkh(v.x - hx, v.y - hy);
        *(uint32_t*)(sm + AL[0] + o + 4) = pkh(v.z - hz, v.w - hw);
    }
#pragma unroll
    for (int c = 0; c < 4; c++) {
        int fi = tid + c * 256;
        int kk = fi >> 5, q = fi & 31;
        float4 v = *(const float4*)(woh + (size_t)(kbase + kk) * MM + col0 + q * 4);
        float hx = hfh(v.x), hy = hfh(v.y), hz = hfh(v.z), hw = hfh(v.w);
        uint32_t o = (uint32_t)(kk * 272 + q * 8);
        *(uint32_t*)(sm + BH[0] + o) = pkh(hx, hy);
        *(uint32_t*)(sm + BH[0] + o + 4) = pkh(hz, hw);
        *(uint32_t*)(sm + BL[0] + o) = pkh(v.x - hx, v.y - hy);
        *(uint32_t*)(sm + BL[0] + o + 4) = pkh(v.z - hz, v.w - hw);
    }
    __syncthreads();

    float acc[8][4];
#pragma unroll
    for (int j = 0; j < 8; j++)
        acc[j][0] = acc[j][1] = acc[j][2] = acc[j][3] = 0.f;

    const uint32_t aro = (uint32_t)((wr + (lane & 15)) * 80 + ((lane >> 4) << 3) * 2);
    const uint32_t bro = (uint32_t)((lane & 15) * 272 + (wc + ((lane >> 4) << 3)) * 2);

    for (int it = 0; it < 8; it++) {
        const int cur = it & 1, nx = cur ^ 1;
        float4 pv[2], po[4];
        if (it < 7) {
            int m0 = kbase + (it + 1) * 32;
#pragma unroll
            for (int c = 0; c < 2; c++) {
                int idx = tid + c * 256;
                int r = idx >> 3, kq = idx & 7;
                pv[c] = *(const float4*)(wvh + (size_t)r * MM + m0 + kq * 4);
            }
#pragma unroll
            for (int c = 0; c < 4; c++) {
                int fi = tid + c * 256;
                int kk = fi >> 5, q = fi & 31;
                po[c] = *(const float4*)(woh + (size_t)(m0 + kk) * MM + col0 + q * 4);
            }
        }

#pragma unroll
        for (int kk = 0; kk < 2; kk++) {
            uint32_t ah4[4], al4[4];
            LDSM4(ah4, sb + AH[cur] + aro + kk * 32);
            LDSM4(al4, sb + AL[cur] + aro + kk * 32);
#pragma unroll
            for (int jp = 0; jp < 4; jp++) {
                uint32_t off = (uint32_t)(kk * 4352 + jp * 32);
                uint32_t bh4[4], bl4[4];
                LDSM4T(bh4, sb + BH[cur] + bro + off);
                LDSM4T(bl4, sb + BL[cur] + bro + off);
                MMAH(acc[2 * jp], ah4, bh4[0], bh4[1]);
                MMAH(acc[2 * jp], ah4, bl4[0], bl4[1]);
                MMAH(acc[2 * jp], al4, bh4[0], bh4[1]);
                MMAH(acc[2 * jp + 1], ah4, bh4[2], bh4[3]);
                MMAH(acc[2 * jp + 1], ah4, bl4[2], bl4[3]);
                MMAH(acc[2 * jp + 1], al4, bh4[2], bh4[3]);
            }
        }

        if (it < 7) {
#pragma unroll
            for (int c = 0; c < 2; c++) {
                int idx = tid + c * 256;
                int r = idx >> 3, kq = idx & 7;
                float4 v = pv[c];
                float hx = hfh(v.x), hy = hfh(v.y), hz = hfh(v.z), hw = hfh(v.w);
                uint32_t o = (uint32_t)(r * 80 + kq * 8);
                *(uint32_t*)(sm + AH[nx] + o) = pkh(hx, hy);
                *(uint32_t*)(sm + AH[nx] + o + 4) = pkh(hz, hw);
                *(uint32_t*)(sm + AL[nx] + o) = pkh(v.x - hx, v.y - hy);
                *(uint32_t*)(sm + AL[nx] + o + 4) = pkh(v.z - hz, v.w - hw);
            }
#pragma unroll
            for (int c = 0; c < 4; c++) {
                int fi = tid + c * 256;
                int kk = fi >> 5, q = fi & 31;
                float4 v = po[c];
                float hx = hfh(v.x), hy = hfh(v.y), hz = hfh(v.z), hw = hfh(v.w);
                uint32_t o = (uint32_t)(kk * 272 + q * 8);
                *(uint32_t*)(sm + BH[nx] + o) = pkh(hx, hy);
                *(uint32_t*)(sm + BH[nx] + o + 4) = pkh(hz, hw);
                *(uint32_t*)(sm + BL[nx] + o) = pkh(v.x - hx, v.y - hy);
                *(uint32_t*)(sm + BL[nx] + o + 4) = pkh(v.z - hz, v.w - hw);
            }
        }
        __syncthreads();
    }

    // write fp32 partials
    float* up = g_Up + (size_t)ks * MM * MM;
    int r = lane >> 2, cc = (lane & 3) * 2;
    int row = h * 64 + wr + r;
#pragma unroll
    for (int j = 0; j < 8; j++) {
        int gc = col0 + wc + 8 * j + cc;
        *(float2*)(up + (size_t)row * MM + gc) = make_float2(acc[j][0], acc[j][1]);
        *(float2*)(up + (size_t)(row + 8) * MM + gc) = make_float2(acc[j][2], acc[j][3]);
    }
}

// Kernel 2b: reduce U partials, split to fp16 hi/lo
__global__ void __launch_bounds__(256) reduceU() {
    size_t i = ((size_t)blockIdx.x * 256 + threadIdx.x) * 4;
    float4 s = *(const float4*)(g_Up + i);
#pragma unroll
    for (int k = 1; k < 4; k++) {
        float4 t = *(const float4*)(g_Up + (size_t)k * MM * MM + i);
        s.x += t.x; s.y += t.y; s.z += t.z; s.w += t.w;
    }
    float hx = hfh(s.x), hy = hfh(s.y), hz = hfh(s.z), hw = hfh(s.w);
    *(uint32_t*)((char*)g_Uh + i * 2) = pkh(hx, hy);
    *(uint32_t*)((char*)g_Uh + i * 2 + 4) = pkh(hz, hw);
    *(uint32_t*)((char*)g_Ul + i * 2) = pkh(s.x - hx, s.y - hy);
    *(uint32_t*)((char*)g_Ul + i * 2 + 4) = pkh(s.z - hz, s.w - hw);
}

// ---------------------------------------------------------------------------
// Kernel 4: flash attention — fp16; GEMM1 3-term, GEMM2 P-single x V-2-term
// 128 threads (4 warps), 64-row Q tiles, 2 CTA/SM
// ---------------------------------------------------------------------------
#define FL_SMEM 73728

__global__ void __launch_bounds__(128, 2) flashTC() {
    extern __shared__ __align__(16) char sm[];
    const uint32_t sb = (uint32_t)__cvta_generic_to_shared(sm);
    const uint32_t KH0 = 0u, KL0 = 18432u, KH1 = 36864u, KL1 = 55296u;
    const uint32_t QH = KH1, QL = KL1;
    const int tid = threadIdx.x, lane = tid & 31, w = tid >> 5;
    const int t0 = blockIdx.x * 64, bh = blockIdx.y;
    const int b = bh >> 4, h = bh & 15;

    const __half* xh = g_xh + (size_t)bh * TT * 64;
    const __half* xl = g_xl + (size_t)bh * TT * 64;

    // Prologue 1: x rows (Q source) -> buf1, A -> buf0
    {
        const __half* Ah = g_Ah + (size_t)h * DD * DD;
        const __half* Al = g_Al + (size_t)h * DD * DD;
#pragma unroll
        for (int c = 0; c < 4; c++) {
            int idx = tid + c * 128;
            int r = idx >> 3, ch = idx & 7;
            cpa(sb + QH + r * 144 + ch * 16, xh + (size_t)(t0 + r) * 64 + ch * 8);
            cpa(sb + QL + r * 144 + ch * 16, xl + (size_t)(t0 + r) * 64 + ch * 8);
            cpa(sb + KH0 + r * 144 + ch * 16, Ah + (size_t)r * 64 + ch * 8);
            cpa(sb + KL0 + r * 144 + ch * 16, Al + (size_t)r * 64 + ch * 8);
        }
        CPCOMMIT();
        CPWAIT0();
        __syncthreads();
    }

    // Prologue 2: Q = x @ A (fp16x3), C-frags -> A-frags
    uint32_t qh[4][4], ql[4][4];
    {
        float QS[8][4];
#pragma unroll
        for (int j = 0; j < 8; j++) { QS[j][0] = QS[j][1] = QS[j][2] = QS[j][3] = 0.f; }
        uint32_t xro = (uint32_t)((16 * w + (lane & 15)) * 144 + ((lane >> 4) << 3) * 2);
        uint32_t aro = (uint32_t)((lane & 15) * 144 + ((lane >> 4) << 3) * 2);
#pragma unroll
        for (int kk = 0; kk < 4; kk++) {
            uint32_t xh4[4], xl4[4];
            LDSM4(xh4, sb + QH + xro + kk * 32);
            LDSM4(xl4, sb + QL + xro + kk * 32);
#pragma unroll
            for (int jp = 0; jp < 4; jp++) {
                uint32_t off = (uint32_t)(kk * 2304 + jp * 32);
                uint32_t bh4[4], bl4[4];
                LDSM4T(bh4, sb + KH0 + aro + off);
                LDSM4T(bl4, sb + KL0 + aro + off);
                MMAH(QS[2 * jp], xh4, bh4[0], bh4[1]);
                MMAH(QS[2 * jp], xh4, bl4[0], bl4[1]);
                MMAH(QS[2 * jp], xl4, bh4[0], bh4[1]);
                MMAH(QS[2 * jp + 1], xh4, bh4[2], bh4[3]);
                MMAH(QS[2 * jp + 1], xh4, bl4[2], bl4[3]);
                MMAH(QS[2 * jp + 1], xl4, bh4[2], bh4[3]);
            }
        }
#pragma unroll
        for (int j = 0; j < 8; j++) {
            float q0 = QS[j][0], q1 = QS[j][1], q2 = QS[j][2], q3 = QS[j][3];
            float h0 = hfh(q0), h1 = hfh(q1), h2 = hfh(q2), h3 = hfh(q3);
            int kkq = j >> 1, ps = (j & 1) << 1;
            qh[kkq][ps] = pkh(h0, h1);
            qh[kkq][ps + 1] = pkh(h2, h3);
            ql[kkq][ps] = pkh(q0 - h0, q1 - h1);
            ql[kkq][ps + 1] = pkh(q2 - h2, q3 - h3);
        }
    }
    __syncthreads();

    // Prologue 3: K tile 0 -> buf0
#pragma unroll
    for (int c = 0; c < 8; c++) {
        int idx = tid + c * 128;
        int r = idx >> 3, ch = idx & 7;
        cpa(sb + KH0 + r * 144 + ch * 16, xh + (size_t)r * 64 + ch * 8);
        cpa(sb + KL0 + r * 144 + ch * 16, xl + (size_t)r * 64 + ch * 8);
    }
    CPCOMMIT();

    float acc[8][4];
    float mrow0 = -INFINITY, mrow1 = -INFINITY, lrow0 = 0.f, lrow1 = 0.f;
#pragma unroll
    for (int j = 0; j < 8; j++) { acc[j][0] = acc[j][1] = acc[j][2] = acc[j][3] = 0.f; }

    for (int it = 0; it < 16; it++) {
        const uint32_t curH = (it & 1) ? KH1 : KH0;
        const uint32_t curL = (it & 1) ? KL1 : KL0;
        const uint32_t nxtH = (it & 1) ? KH0 : KH1;
        const uint32_t nxtL = (it & 1) ? KL0 : KL1;

        __syncthreads();
        if (it < 15) {
            int s0 = (it + 1) * 128;
#pragma unroll
            for (int c = 0; c < 8; c++) {
                int idx = tid + c * 128;
                int r = idx >> 3, ch = idx & 7;
                cpa(sb + nxtH + r * 144 + ch * 16, xh + (size_t)(s0 + r) * 64 + ch * 8);
                cpa(sb + nxtL + r * 144 + ch * 16, xl + (size_t)(s0 + r) * 64 + ch * 8);
            }
            CPCOMMIT();
            CPWAIT1();
        } else {
            CPWAIT0();
        }
        __syncthreads();

        // GEMM1: S = Q @ K^T, fp16 3-term
        float S[16][4];
#pragma unroll
        for (int j = 0; j < 16; j++) { S[j][0] = S[j][1] = S[j][2] = S[j][3] = 0.f; }
        {
            uint32_t rbase = sb + (uint32_t)(((lane & 7) + ((lane >> 4) << 3)) * 144 +
                                             (((lane >> 3) & 1) << 3) * 2);
#pragma unroll
            for (int jp = 0; jp < 8; jp++) {
#pragma unroll
                for (int kk = 0; kk < 4; kk++) {
                    uint32_t off = (uint32_t)(jp * 2304 + kk * 32);
                    uint32_t bh4[4], bl4[4];
                    LDSM4(bh4, rbase + curH + off);
                    LDSM4(bl4, rbase + curL + off);
                    MMAH(S[2 * jp], qh[kk], bh4[0], bh4[1]);
                    MMAH(S[2 * jp], qh[kk], bl4[0], bl4[1]);
                    MMAH(S[2 * jp], ql[kk], bh4[0], bh4[1]);
                    MMAH(S[2 * jp + 1], qh[kk], bh4[2], bh4[3]);
                    MMAH(S[2 * jp + 1], qh[kk], bl4[2], bl4[3]);
                    MMAH(S[2 * jp + 1], ql[kk], bh4[2], bh4[3]);
                }
            }
        }

        // online softmax (base-2); P packed as single fp16
        float mx0 = -INFINITY, mx1 = -INFINITY;
#pragma unroll
        for (int j = 0; j < 16; j++) {
            mx0 = fmaxf(mx0, fmaxf(S[j][0], S[j][1]));
            mx1 = fmaxf(mx1, fmaxf(S[j][2], S[j][3]));
        }
        mx0 = fmaxf(mx0, __shfl_xor_sync(0xffffffffu, mx0, 1));
        mx0 = fmaxf(mx0, __shfl_xor_sync(0xffffffffu, mx0, 2));
        mx1 = fmaxf(mx1, __shfl_xor_sync(0xffffffffu, mx1, 1));
        mx1 = fmaxf(mx1, __shfl_xor_sync(0xffffffffu, mx1, 2));
        float mn0 = fmaxf(mrow0, mx0), mn1 = fmaxf(mrow1, mx1);
        float sc0 = ex2f(mrow0 - mn0), sc1 = ex2f(mrow1 - mn1);
        mrow0 = mn0; mrow1 = mn1;

        uint32_t php[8][4];
        float rs0 = 0.f, rs1 = 0.f;
#pragma unroll
        for (int j = 0; j < 16; j++) {
            float p0 = ex2f(S[j][0] - mn0), p1 = ex2f(S[j][1] - mn0);
            float p2 = ex2f(S[j][2] - mn1), p3 = ex2f(S[j][3] - mn1);
            rs0 += p0 + p1; rs1 += p2 + p3;
            int ss = j >> 1, ps = (j & 1) << 1;
            php[ss][ps] = pkh(p0, p1);
            php[ss][ps + 1] = pkh(p2, p3);
        }
        rs0 += __shfl_xor_sync(0xffffffffu, rs0, 1);
        rs0 += __shfl_xor_sync(0xffffffffu, rs0, 2);
        rs1 += __shfl_xor_sync(0xffffffffu, rs1, 1);
        rs1 += __shfl_xor_sync(0xffffffffu, rs1, 2);
        lrow0 = lrow0 * sc0 + rs0;
        lrow1 = lrow1 * sc1 + rs1;
#pragma unroll
        for (int j = 0; j < 8; j++) {
            acc[j][0] *= sc0; acc[j][1] *= sc0; acc[j][2] *= sc1; acc[j][3] *= sc1;
        }

        // GEMM2: acc += P_h @ (V_h + V_l)  — 4 MMAs per (ss, jp-pair)
        {
            uint32_t rbase = sb + (uint32_t)((lane & 15) * 144 + ((lane >> 4) << 3) * 2);
#pragma unroll
            for (int ss = 0; ss < 8; ss++) {
#pragma unroll
                for (int jp = 0; jp < 4; jp++) {
                    uint32_t off = (uint32_t)(ss * 2304 + jp * 32);
                    uint32_t vh4[4], vl4[4];
                    LDSM4T(vh4, rbase + curH + off);
                    LDSM4T(vl4, rbase + curL + off);
                    MMAH(acc[2 * jp], php[ss], vh4[0], vh4[1]);
                    MMAH(acc[2 * jp], php[ss], vl4[0], vl4[1]);
                    MMAH(acc[2 * jp + 1], php[ss], vh4[2], vh4[3]);
                    MMAH(acc[2 * jp + 1], php[ss], vl4[2], vl4[3]);
                }
            }
        }
    }

    float inv0 = 1.f / lrow0, inv1 = 1.f / lrow1;
    int r0 = lane >> 2, c0 = (lane & 3) * 2;
    size_t rowA = ((size_t)b * TT + t0 + 16 * w + r0) * MM + h * 64;
    size_t rowB = rowA + 8 * MM;
#pragma unroll
    for (int j = 0; j < 8; j++) {
        float o0 = acc[j][0] * inv0, o1 = acc[j][1] * inv0;
        float o2 = acc[j][2] * inv1, o3 = acc[j][3] * inv1;
        float h0 = hfh(o0), h1 = hfh(o1), h2 = hfh(o2), h3 = hfh(o3);
        size_t ia = rowA + 8 * j + c0, ib = rowB + 8 * j + c0;
        *(uint32_t*)((char*)g_zh + ia * 2) = pkh(h0, h1);
        *(uint32_t*)((char*)g_zl + ia * 2) = pkh(o0 - h0, o1 - h1);
        *(uint32_t*)((char*)g_zh + ib * 2) = pkh(h2, h3);
        *(uint32_t*)((char*)g_zl + ib * 2) = pkh(o2 - h2, o3 - h3);
    }
}

// ---------------------------------------------------------------------------
// Kernel 5: out = z @ U + bo — fp16x3, 128 threads, tile 128x64, 2 CTA/SM
// ---------------------------------------------------------------------------
#define GO_SMEM 110592

__global__ void __launch_bounds__(128, 2) gemmOutTC(const float* __restrict__ bo,
                                                    float* __restrict__ out) {
    extern __shared__ __align__(16) char sm[];
    const uint32_t sb = (uint32_t)__cvta_generic_to_shared(sm);
    const uint32_t ZH[2] = {0u, 55296u}, ZL[2] = {18432u, 73728u};
    const uint32_t UH[2] = {36864u, 92160u}, UL[2] = {46080u, 101376u};
    const int tid = threadIdx.x, lane = tid & 31, w = tid >> 5;
    const int col0 = blockIdx.x * 64, row0 = blockIdx.y * 128;
    const int wr = w * 32;

#pragma unroll
    for (int c = 0; c < 8; c++) {
        int idx = tid + c * 128;
        int r = idx >> 3, ch = idx & 7;
        cpa(sb + ZH[0] + r * 144 + ch * 16, g_zh + (size_t)(row0 + r) * MM + ch * 8);
        cpa(sb + ZL[0] + r * 144 + ch * 16, g_zl + (size_t)(row0 + r) * MM + ch * 8);
    }
#pragma unroll
    for (int c = 0; c < 4; c++) {
        int idx = tid + c * 128;
        int kk = idx >> 3, q = idx & 7;
        cpa(sb + UH[0] + kk * 144 + q * 16, g_Uh + (size_t)kk * MM + col0 + q * 8);
        cpa(sb + UL[0] + kk * 144 + q * 16, g_Ul + (size_t)kk * MM + col0 + q * 8);
    }
    CPCOMMIT();

    float acc[2][8][4];
#pragma unroll
    for (int rb = 0; rb < 2; rb++)
#pragma unroll
        for (int j = 0; j < 8; j++)
            acc[rb][j][0] = acc[rb][j][1] = acc[rb][j][2] = acc[rb][j][3] = 0.f;

    const uint32_t aro = (uint32_t)((wr + (lane & 15)) * 144 + ((lane >> 4) << 3) * 2);
    const uint32_t bro = (uint32_t)((lane & 15) * 144 + ((lane >> 4) << 3) * 2);

    for (int it = 0; it < 16; it++) {
        const int cur = it & 1, nx = cur ^ 1;
        __syncthreads();
        if (it < 15) {
            int k0 = (it + 1) * 64;
#pragma unroll
            for (int c = 0; c < 8; c++) {
                int idx = tid + c * 128;
                int r = idx >> 3, ch = idx & 7;
                cpa(sb + ZH[nx] + r * 144 + ch * 16,
                    g_zh + (size_t)(row0 + r) * MM + k0 + ch * 8);
                cpa(sb + ZL[nx] + r * 144 + ch * 16,
                    g_zl + (size_t)(row0 + r) * MM + k0 + ch * 8);
            }
#pragma unroll
            for (int c = 0; c < 4; c++) {
                int idx = tid + c * 128;
                int kk = idx >> 3, q = idx & 7;
                cpa(sb + UH[nx] + kk * 144 + q * 16,
                    g_Uh + (size_t)(k0 + kk) * MM + col0 + q * 8);
                cpa(sb + UL[nx] + kk * 144 + q * 16,
                    g_Ul + (size_t)(k0 + kk) * MM + col0 + q * 8);
            }
            CPCOMMIT();
            CPWAIT1();
        } else {
            CPWAIT0();
        }
        __syncthreads();

#pragma unroll
        for (int kk = 0; kk < 4; kk++) {
            uint32_t ah0[4], al0[4], ah1[4], al1[4];
            LDSM4(ah0, sb + ZH[cur] + aro + kk * 32);
            LDSM4(al0, sb + ZL[cur] + aro + kk * 32);
            LDSM4(ah1, sb + ZH[cur] + aro + 2304 + kk * 32);
            LDSM4(al1, sb + ZL[cur] + aro + 2304 + kk * 32);
#pragma unroll
            for (int jp = 0; jp < 4; jp++) {
                uint32_t off = (uint32_t)(kk * 2304 + jp * 32);
                uint32_t bh4[4], bl4[4];
                LDSM4T(bh4, sb + UH[cur] + bro + off);
                LDSM4T(bl4, sb + UL[cur] + bro + off);
                MMAH(acc[0][2 * jp], ah0, bh4[0], bh4[1]);
                MMAH(acc[0][2 * jp], ah0, bl4[0], bl4[1]);
                MMAH(acc[0][2 * jp], al0, bh4[0], bh4[1]);
                MMAH(acc[0][2 * jp + 1], ah0, bh4[2], bh4[3]);
                MMAH(acc[0][2 * jp + 1], ah0, bl4[2], bl4[3]);
                MMAH(acc[0][2 * jp + 1], al0, bh4[2], bh4[3]);
                MMAH(acc[1][2 * jp], ah1, bh4[0], bh4[1]);
                MMAH(acc[1][2 * jp], ah1, bl4[0], bl4[1]);
                MMAH(acc[1][2 * jp], al1, bh4[0], bh4[1]);
                MMAH(acc[1][2 * jp + 1], ah1, bh4[2], bh4[3]);
                MMAH(acc[1][2 * jp + 1], ah1, bl4[2], bl4[3]);
                MMAH(acc[1][2 * jp + 1], al1, bh4[2], bh4[3]);
            }
        }
    }

    int r = lane >> 2, cc = (lane & 3) * 2;
#pragma unroll
    for (int rb = 0; rb < 2; rb++) {
        int gr = row0 + wr + rb * 16 + r;
#pragma unroll
        for (int j = 0; j < 8; j++) {
            int gc = col0 + 8 * j + cc;
            float b0v = bo[gc], b1v = bo[gc + 1];
            *(float2*)(out + (size_t)gr * MM + gc) =
                make_float2(acc[rb][j][0] + b0v, acc[rb][j][1] + b1v);
            *(float2*)(out + (size_t)(gr + 8) * MM + gc) =
                make_float2(acc[rb][j][2] + b0v, acc[rb][j][3] + b1v);
        }
    }
}

// ---------------------------------------------------------------------------
extern "C" void kernel_launch(void* const* d_in, const int* in_sizes, int n_in,
                              void* d_out, int out_size) {
    const float* x  = (const float*)d_in[0];
    const float* Wq = (const float*)d_in[1];
    const float* Wk = (const float*)d_in[2];
    const float* Wv = (const float*)d_in[3];
    const float* Wo = (const float*)d_in[4];
    const float* bo = (const float*)d_in[5];
    float* out = (float*)d_out;

    cudaFuncSetAttribute(flashTC, cudaFuncAttributeMaxDynamicSharedMemorySize, FL_SMEM);
    cudaFuncSetAttribute(gemmOutTC, cudaFuncAttributeMaxDynamicSharedMemorySize, GO_SMEM);
    cudaFuncSetAttribute(computeUTC, cudaFuncAttributeMaxDynamicSharedMemorySize, CU_SMEM);

    splitX<<<4096, 256>>>(x);
    computeApart<<<dim3(16, 8), 256>>>(Wq, Wk);
    reduceA<<<256, 256>>>();
    computeUTC<<<dim3(8, 16, 4), 256, CU_SMEM>>>(Wv, Wo);
    reduceU<<<1024, 256>>>();
    flashTC<<<dim3(TT / 64, BB * HH), 128, FL_SMEM>>>();
    gemmOutTC<<<dim3(MM / 64, (BB * TT) / 128), 128, GO_SMEM>>>(bo, out);
}

// round 11
// speedup vs baseline: 5.2185x; 1.2194x over previous
#include <cuda_runtime.h>
#include <cuda_fp16.h>
#include <math.h>
#include <stdint.h>

#define BB 2
#define TT 2048
#define HH 16
#define DD 64
#define MM 1024

// Persistent scratch (device globals)
__device__ float g_Ap[8 * HH * DD * DD];        // k-split partials for A
__device__ float g_Up[4 * MM * MM];             // k-split partials for U (fp32)
__device__ __half g_Ah[HH * DD * DD];           // A split hi  [h][d][d']
__device__ __half g_Al[HH * DD * DD];           // A split lo
__device__ __half g_xh[BB * HH * TT * DD];      // x per-head, fp16 hi  [bh][t][64]
__device__ __half g_xl[BB * HH * TT * DD];      // x per-head, fp16 lo
__device__ __half g_zh[BB * TT * MM];           // attn out, fp16 hi    [b][t][1024]
__device__ __half g_zl[BB * TT * MM];
__device__ __half g_Uh[MM * MM];                // U = Wv@Wo, fp16 (single)

__device__ __forceinline__ uint32_t pkh(float a, float b) {
    __half2 t = __floats2half2_rn(a, b);
    return *reinterpret_cast<uint32_t*>(&t);
}
__device__ __forceinline__ float hfh(float x) {
    return __half2float(__float2half_rn(x));
}
__device__ __forceinline__ float ex2f(float x) {
    float y;
    asm("ex2.approx.ftz.f32 %0, %1;" : "=f"(y) : "f"(x));
    return y;
}
__device__ __forceinline__ void cpa(uint32_t d, const void* s) {
    asm volatile("cp.async.cg.shared.global [%0], [%1], 16;" :: "r"(d), "l"(s));
}
#define CPCOMMIT() asm volatile("cp.async.commit_group;")
#define CPWAIT1() asm volatile("cp.async.wait_group 1;")
#define CPWAIT0() asm volatile("cp.async.wait_group 0;")

#define LDSM4(R, A) asm volatile( \
    "ldmatrix.sync.aligned.m8n8.x4.shared.b16 {%0,%1,%2,%3},[%4];" \
    : "=r"((R)[0]), "=r"((R)[1]), "=r"((R)[2]), "=r"((R)[3]) : "r"(A))
#define LDSM4T(R, A) asm volatile( \
    "ldmatrix.sync.aligned.m8n8.x4.trans.shared.b16 {%0,%1,%2,%3},[%4];" \
    : "=r"((R)[0]), "=r"((R)[1]), "=r"((R)[2]), "=r"((R)[3]) : "r"(A))
#define MMAH(D, A, B0, B1) asm volatile( \
    "mma.sync.aligned.m16n8k16.row.col.f32.f16.f16.f32 " \
    "{%0,%1,%2,%3},{%4,%5,%6,%7},{%8,%9},{%0,%1,%2,%3};" \
    : "+f"((D)[0]), "+f"((D)[1]), "+f"((D)[2]), "+f"((D)[3]) \
    : "r"((A)[0]), "r"((A)[1]), "r"((A)[2]), "r"((A)[3]), "r"(B0), "r"(B1))

// ---------------------------------------------------------------------------
// Kernel 0: split x into per-head fp16 hi/lo, layout [bh][t][64]
// ---------------------------------------------------------------------------
__global__ void __launch_bounds__(256) splitX(const float* __restrict__ x) {
    int fi = blockIdx.x * 256 + threadIdx.x;
    size_t e = (size_t)fi * 4;
    int b = (int)(e / ((size_t)TT * MM));
    size_t rem = e % ((size_t)TT * MM);
    int t = (int)(rem / MM);
    int col = (int)(rem % MM);
    int h = col >> 6, c = col & 63;
    float4 v = *(const float4*)(x + e);
    float hx = hfh(v.x), hy = hfh(v.y), hz = hfh(v.z), hw = hfh(v.w);
    size_t di = (((size_t)(b * 16 + h) * TT + t) * 64 + c);
    *(uint32_t*)((char*)g_xh + di * 2) = pkh(hx, hy);
    *(uint32_t*)((char*)g_xh + di * 2 + 4) = pkh(hz, hw);
    *(uint32_t*)((char*)g_xl + di * 2) = pkh(v.x - hx, v.y - hy);
    *(uint32_t*)((char*)g_xl + di * 2 + 4) = pkh(v.z - hz, v.w - hw);
}

// ---------------------------------------------------------------------------
// Kernel 1a: partial A; grid (16 h, 8 kseg)
// ---------------------------------------------------------------------------
__global__ void __launch_bounds__(256) computeApart(const float* __restrict__ Wq,
                                                    const float* __restrict__ Wk) {
    const int h = blockIdx.x, ks = blockIdx.y, tid = threadIdx.x;
    const int tx = tid & 15, ty = tid >> 4;
    __shared__ float wqs[64 * 65];
    __shared__ float wks[64 * 65];
    float acc[4][4];
#pragma unroll
    for (int i = 0; i < 4; i++)
#pragma unroll
        for (int j = 0; j < 4; j++) acc[i][j] = 0.f;
    const float* wqh = Wq + (size_t)h * DD * MM;
    const float* wkh = Wk + (size_t)h * DD * MM;
    for (int m0 = ks * 128; m0 < ks * 128 + 128; m0 += 64) {
        __syncthreads();
#pragma unroll
        for (int c = 0; c < 4; c++) {
            int fi = tid + c * 256, i = fi >> 4, q = fi & 15;
            float4 a = *(const float4*)(wqh + i * MM + m0 + q * 4);
            wqs[i * 65 + q * 4 + 0] = a.x; wqs[i * 65 + q * 4 + 1] = a.y;
            wqs[i * 65 + q * 4 + 2] = a.z; wqs[i * 65 + q * 4 + 3] = a.w;
            float4 b = *(const float4*)(wkh + i * MM + m0 + q * 4);
            wks[i * 65 + q * 4 + 0] = b.x; wks[i * 65 + q * 4 + 1] = b.y;
            wks[i * 65 + q * 4 + 2] = b.z; wks[i * 65 + q * 4 + 3] = b.w;
        }
        __syncthreads();
        for (int m = 0; m < 64; m++) {
            float a[4], b[4];
#pragma unroll
            for (int i = 0; i < 4; i++) a[i] = wqs[(ty * 4 + i) * 65 + m];
#pragma unroll
            for (int j = 0; j < 4; j++) b[j] = wks[(tx * 4 + j) * 65 + m];
#pragma unroll
            for (int i = 0; i < 4; i++)
#pragma unroll
                for (int j = 0; j < 4; j++) acc[i][j] += a[i] * b[j];
        }
    }
    float* o = g_Ap + (size_t)ks * (HH * DD * DD) + h * DD * DD;
#pragma unroll
    for (int i = 0; i < 4; i++)
#pragma unroll
        for (int j = 0; j < 4; j++)
            o[(ty * 4 + i) * DD + tx * 4 + j] = acc[i][j];
}

// Kernel 1b: reduce partials, scale, split to fp16 hi/lo
__global__ void __launch_bounds__(256) reduceA() {
    int i = blockIdx.x * 256 + threadIdx.x;
    float s = 0.f;
#pragma unroll
    for (int k = 0; k < 8; k++) s += g_Ap[(size_t)k * (HH * DD * DD) + i];
    s *= (0.125f * 1.4426950408889634f);
    float hv = hfh(s);
    g_Ah[i] = __float2half_rn(s);
    g_Al[i] = __float2half_rn(s - hv);
}

// ---------------------------------------------------------------------------
// Kernel 2a: U partials — Wv fp16-split x Wo fp16-single (2 MMA terms)
// grid (8 col-tiles, 16 h, 4 ks), 256 threads; tile 64x128, k-range 256
// ---------------------------------------------------------------------------
#define CU_SMEM 37888

__global__ void __launch_bounds__(256, 1) computeUTC(const float* __restrict__ Wv,
                                                     const float* __restrict__ Wo) {
    extern __shared__ __align__(16) char sm[];
    const uint32_t sb = (uint32_t)__cvta_generic_to_shared(sm);
    const uint32_t AH[2] = {0u, 18944u}, AL[2] = {5120u, 24064u};
    const uint32_t BH[2] = {10240u, 29184u};
    const int tid = threadIdx.x, lane = tid & 31, w = tid >> 5;
    const int h = blockIdx.y, col0 = blockIdx.x * 128, ks = blockIdx.z;
    const int kbase = ks * 256;
    const int wr = (w & 3) * 16, wc = (w >> 2) * 64;
    const float* wvh = Wv + (size_t)h * DD * MM;
    const float* woh = Wo + (size_t)h * MM * MM;

#pragma unroll
    for (int c = 0; c < 2; c++) {
        int idx = tid + c * 256;
        int r = idx >> 3, kq = idx & 7;
        float4 v = *(const float4*)(wvh + (size_t)r * MM + kbase + kq * 4);
        float hx = hfh(v.x), hy = hfh(v.y), hz = hfh(v.z), hw = hfh(v.w);
        uint32_t o = (uint32_t)(r * 80 + kq * 8);
        *(uint32_t*)(sm + AH[0] + o) = pkh(hx, hy);
        *(uint32_t*)(sm + AH[0] + o + 4) = pkh(hz, hw);
        *(uint32_t*)(sm + AL[0] + o) = pkh(v.x - hx, v.y - hy);
        *(uint32_t*)(sm + AL[0] + o + 4) = pkh(v.z - hz, v.w - hw);
    }
#pragma unroll
    for (int c = 0; c < 4; c++) {
        int fi = tid + c * 256;
        int kk = fi >> 5, q = fi & 31;
        float4 v = *(const float4*)(woh + (size_t)(kbase + kk) * MM + col0 + q * 4);
        uint32_t o = (uint32_t)(kk * 272 + q * 8);
        *(uint32_t*)(sm + BH[0] + o) = pkh(v.x, v.y);
        *(uint32_t*)(sm + BH[0] + o + 4) = pkh(v.z, v.w);
    }
    __syncthreads();

    float acc[8][4];
#pragma unroll
    for (int j = 0; j < 8; j++)
        acc[j][0] = acc[j][1] = acc[j][2] = acc[j][3] = 0.f;

    const uint32_t aro = (uint32_t)((wr + (lane & 15)) * 80 + ((lane >> 4) << 3) * 2);
    const uint32_t bro = (uint32_t)((lane & 15) * 272 + (wc + ((lane >> 4) << 3)) * 2);

    for (int it = 0; it < 8; it++) {
        const int cur = it & 1, nx = cur ^ 1;
        float4 pv[2], po[4];
        if (it < 7) {
            int m0 = kbase + (it + 1) * 32;
#pragma unroll
            for (int c = 0; c < 2; c++) {
                int idx = tid + c * 256;
                int r = idx >> 3, kq = idx & 7;
                pv[c] = *(const float4*)(wvh + (size_t)r * MM + m0 + kq * 4);
            }
#pragma unroll
            for (int c = 0; c < 4; c++) {
                int fi = tid + c * 256;
                int kk = fi >> 5, q = fi & 31;
                po[c] = *(const float4*)(woh + (size_t)(m0 + kk) * MM + col0 + q * 4);
            }
        }

#pragma unroll
        for (int kk = 0; kk < 2; kk++) {
            uint32_t ah4[4], al4[4];
            LDSM4(ah4, sb + AH[cur] + aro + kk * 32);
            LDSM4(al4, sb + AL[cur] + aro + kk * 32);
#pragma unroll
            for (int jp = 0; jp < 4; jp++) {
                uint32_t off = (uint32_t)(kk * 4352 + jp * 32);
                uint32_t bh4[4];
                LDSM4T(bh4, sb + BH[cur] + bro + off);
                MMAH(acc[2 * jp], ah4, bh4[0], bh4[1]);
                MMAH(acc[2 * jp], al4, bh4[0], bh4[1]);
                MMAH(acc[2 * jp + 1], ah4, bh4[2], bh4[3]);
                MMAH(acc[2 * jp + 1], al4, bh4[2], bh4[3]);
            }
        }

        if (it < 7) {
#pragma unroll
            for (int c = 0; c < 2; c++) {
                int idx = tid + c * 256;
                int r = idx >> 3, kq = idx & 7;
                float4 v = pv[c];
                float hx = hfh(v.x), hy = hfh(v.y), hz = hfh(v.z), hw = hfh(v.w);
                uint32_t o = (uint32_t)(r * 80 + kq * 8);
                *(uint32_t*)(sm + AH[nx] + o) = pkh(hx, hy);
                *(uint32_t*)(sm + AH[nx] + o + 4) = pkh(hz, hw);
                *(uint32_t*)(sm + AL[nx] + o) = pkh(v.x - hx, v.y - hy);
                *(uint32_t*)(sm + AL[nx] + o + 4) = pkh(v.z - hz, v.w - hw);
            }
#pragma unroll
            for (int c = 0; c < 4; c++) {
                int fi = tid + c * 256;
                int kk = fi >> 5, q = fi & 31;
                float4 v = po[c];
                uint32_t o = (uint32_t)(kk * 272 + q * 8);
                *(uint32_t*)(sm + BH[nx] + o) = pkh(v.x, v.y);
                *(uint32_t*)(sm + BH[nx] + o + 4) = pkh(v.z, v.w);
            }
        }
        __syncthreads();
    }

    float* up = g_Up + (size_t)ks * MM * MM;
    int r = lane >> 2, cc = (lane & 3) * 2;
    int row = h * 64 + wr + r;
#pragma unroll
    for (int j = 0; j < 8; j++) {
        int gc = col0 + wc + 8 * j + cc;
        *(float2*)(up + (size_t)row * MM + gc) = make_float2(acc[j][0], acc[j][1]);
        *(float2*)(up + (size_t)(row + 8) * MM + gc) = make_float2(acc[j][2], acc[j][3]);
    }
}

// Kernel 2b: reduce U partials -> single fp16
__global__ void __launch_bounds__(256) reduceU() {
    size_t i = ((size_t)blockIdx.x * 256 + threadIdx.x) * 4;
    float4 s = *(const float4*)(g_Up + i);
#pragma unroll
    for (int k = 1; k < 4; k++) {
        float4 t = *(const float4*)(g_Up + (size_t)k * MM * MM + i);
        s.x += t.x; s.y += t.y; s.z += t.z; s.w += t.w;
    }
    *(uint32_t*)((char*)g_Uh + i * 2) = pkh(s.x, s.y);
    *(uint32_t*)((char*)g_Uh + i * 2 + 4) = pkh(s.z, s.w);
}

// ---------------------------------------------------------------------------
// Kernel 4: flash attention — fp16; GEMM1 3-term, GEMM2 P-single x V-single
// 128 threads (4 warps), 64-row Q tiles, 2 CTA/SM
// ---------------------------------------------------------------------------
#define FL_SMEM 73728

__global__ void __launch_bounds__(128, 2) flashTC() {
    extern __shared__ __align__(16) char sm[];
    const uint32_t sb = (uint32_t)__cvta_generic_to_shared(sm);
    const uint32_t KH0 = 0u, KL0 = 18432u, KH1 = 36864u, KL1 = 55296u;
    const uint32_t QH = KH1, QL = KL1;
    const int tid = threadIdx.x, lane = tid & 31, w = tid >> 5;
    const int t0 = blockIdx.x * 64, bh = blockIdx.y;
    const int b = bh >> 4, h = bh & 15;

    const __half* xh = g_xh + (size_t)bh * TT * 64;
    const __half* xl = g_xl + (size_t)bh * TT * 64;

    // Prologue 1: x rows (Q source) -> buf1, A -> buf0
    {
        const __half* Ah = g_Ah + (size_t)h * DD * DD;
        const __half* Al = g_Al + (size_t)h * DD * DD;
#pragma unroll
        for (int c = 0; c < 4; c++) {
            int idx = tid + c * 128;
            int r = idx >> 3, ch = idx & 7;
            cpa(sb + QH + r * 144 + ch * 16, xh + (size_t)(t0 + r) * 64 + ch * 8);
            cpa(sb + QL + r * 144 + ch * 16, xl + (size_t)(t0 + r) * 64 + ch * 8);
            cpa(sb + KH0 + r * 144 + ch * 16, Ah + (size_t)r * 64 + ch * 8);
            cpa(sb + KL0 + r * 144 + ch * 16, Al + (size_t)r * 64 + ch * 8);
        }
        CPCOMMIT();
        CPWAIT0();
        __syncthreads();
    }

    // Prologue 2: Q = x @ A (fp16x3), C-frags -> A-frags
    uint32_t qh[4][4], ql[4][4];
    {
        float QS[8][4];
#pragma unroll
        for (int j = 0; j < 8; j++) { QS[j][0] = QS[j][1] = QS[j][2] = QS[j][3] = 0.f; }
        uint32_t xro = (uint32_t)((16 * w + (lane & 15)) * 144 + ((lane >> 4) << 3) * 2);
        uint32_t aro = (uint32_t)((lane & 15) * 144 + ((lane >> 4) << 3) * 2);
#pragma unroll
        for (int kk = 0; kk < 4; kk++) {
            uint32_t xh4[4], xl4[4];
            LDSM4(xh4, sb + QH + xro + kk * 32);
            LDSM4(xl4, sb + QL + xro + kk * 32);
#pragma unroll
            for (int jp = 0; jp < 4; jp++) {
                uint32_t off = (uint32_t)(kk * 2304 + jp * 32);
                uint32_t bh4[4], bl4[4];
                LDSM4T(bh4, sb + KH0 + aro + off);
                LDSM4T(bl4, sb + KL0 + aro + off);
                MMAH(QS[2 * jp], xh4, bh4[0], bh4[1]);
                MMAH(QS[2 * jp], xh4, bl4[0], bl4[1]);
                MMAH(QS[2 * jp], xl4, bh4[0], bh4[1]);
                MMAH(QS[2 * jp + 1], xh4, bh4[2], bh4[3]);
                MMAH(QS[2 * jp + 1], xh4, bl4[2], bl4[3]);
                MMAH(QS[2 * jp + 1], xl4, bh4[2], bh4[3]);
            }
        }
#pragma unroll
        for (int j = 0; j < 8; j++) {
            float q0 = QS[j][0], q1 = QS[j][1], q2 = QS[j][2], q3 = QS[j][3];
            float h0 = hfh(q0), h1 = hfh(q1), h2 = hfh(q2), h3 = hfh(q3);
            int kkq = j >> 1, ps = (j & 1) << 1;
            qh[kkq][ps] = pkh(h0, h1);
            qh[kkq][ps + 1] = pkh(h2, h3);
            ql[kkq][ps] = pkh(q0 - h0, q1 - h1);
            ql[kkq][ps + 1] = pkh(q2 - h2, q3 - h3);
        }
    }
    __syncthreads();

    // Prologue 3: K tile 0 -> buf0
#pragma unroll
    for (int c = 0; c < 8; c++) {
        int idx = tid + c * 128;
        int r = idx >> 3, ch = idx & 7;
        cpa(sb + KH0 + r * 144 + ch * 16, xh + (size_t)r * 64 + ch * 8);
        cpa(sb + KL0 + r * 144 + ch * 16, xl + (size_t)r * 64 + ch * 8);
    }
    CPCOMMIT();

    float acc[8][4];
    float mrow0 = -INFINITY, mrow1 = -INFINITY, lrow0 = 0.f, lrow1 = 0.f;
#pragma unroll
    for (int j = 0; j < 8; j++) { acc[j][0] = acc[j][1] = acc[j][2] = acc[j][3] = 0.f; }

    for (int it = 0; it < 16; it++) {
        const uint32_t curH = (it & 1) ? KH1 : KH0;
        const uint32_t curL = (it & 1) ? KL1 : KL0;
        const uint32_t nxtH = (it & 1) ? KH0 : KH1;
        const uint32_t nxtL = (it & 1) ? KL0 : KL1;

        __syncthreads();
        if (it < 15) {
            int s0 = (it + 1) * 128;
#pragma unroll
            for (int c = 0; c < 8; c++) {
                int idx = tid + c * 128;
                int r = idx >> 3, ch = idx & 7;
                cpa(sb + nxtH + r * 144 + ch * 16, xh + (size_t)(s0 + r) * 64 + ch * 8);
                cpa(sb + nxtL + r * 144 + ch * 16, xl + (size_t)(s0 + r) * 64 + ch * 8);
            }
            CPCOMMIT();
            CPWAIT1();
        } else {
            CPWAIT0();
        }
        __syncthreads();

        // GEMM1: S = Q @ K^T, fp16 3-term
        float S[16][4];
#pragma unroll
        for (int j = 0; j < 16; j++) { S[j][0] = S[j][1] = S[j][2] = S[j][3] = 0.f; }
        {
            uint32_t rbase = sb + (uint32_t)(((lane & 7) + ((lane >> 4) << 3)) * 144 +
                                             (((lane >> 3) & 1) << 3) * 2);
#pragma unroll
            for (int jp = 0; jp < 8; jp++) {
#pragma unroll
                for (int kk = 0; kk < 4; kk++) {
                    uint32_t off = (uint32_t)(jp * 2304 + kk * 32);
                    uint32_t bh4[4], bl4[4];
                    LDSM4(bh4, rbase + curH + off);
                    LDSM4(bl4, rbase + curL + off);
                    MMAH(S[2 * jp], qh[kk], bh4[0], bh4[1]);
                    MMAH(S[2 * jp], qh[kk], bl4[0], bl4[1]);
                    MMAH(S[2 * jp], ql[kk], bh4[0], bh4[1]);
                    MMAH(S[2 * jp + 1], qh[kk], bh4[2], bh4[3]);
                    MMAH(S[2 * jp + 1], qh[kk], bl4[2], bl4[3]);
                    MMAH(S[2 * jp + 1], ql[kk], bh4[2], bh4[3]);
                }
            }
        }

        // online softmax (base-2); P packed as single fp16
        float mx0 = -INFINITY, mx1 = -INFINITY;
#pragma unroll
        for (int j = 0; j < 16; j++) {
            mx0 = fmaxf(mx0, fmaxf(S[j][0], S[j][1]));
            mx1 = fmaxf(mx1, fmaxf(S[j][2], S[j][3]));
        }
        mx0 = fmaxf(mx0, __shfl_xor_sync(0xffffffffu, mx0, 1));
        mx0 = fmaxf(mx0, __shfl_xor_sync(0xffffffffu, mx0, 2));
        mx1 = fmaxf(mx1, __shfl_xor_sync(0xffffffffu, mx1, 1));
        mx1 = fmaxf(mx1, __shfl_xor_sync(0xffffffffu, mx1, 2));
        float mn0 = fmaxf(mrow0, mx0), mn1 = fmaxf(mrow1, mx1);
        float sc0 = ex2f(mrow0 - mn0), sc1 = ex2f(mrow1 - mn1);
        mrow0 = mn0; mrow1 = mn1;

        uint32_t php[8][4];
        float rs0 = 0.f, rs1 = 0.f;
#pragma unroll
        for (int j = 0; j < 16; j++) {
            float p0 = ex2f(S[j][0] - mn0), p1 = ex2f(S[j][1] - mn0);
            float p2 = ex2f(S[j][2] - mn1), p3 = ex2f(S[j][3] - mn1);
            rs0 += p0 + p1; rs1 += p2 + p3;
            int ss = j >> 1, ps = (j & 1) << 1;
            php[ss][ps] = pkh(p0, p1);
            php[ss][ps + 1] = pkh(p2, p3);
        }
        rs0 += __shfl_xor_sync(0xffffffffu, rs0, 1);
        rs0 += __shfl_xor_sync(0xffffffffu, rs0, 2);
        rs1 += __shfl_xor_sync(0xffffffffu, rs1, 1);
        rs1 += __shfl_xor_sync(0xffffffffu, rs1, 2);
        lrow0 = lrow0 * sc0 + rs0;
        lrow1 = lrow1 * sc1 + rs1;
#pragma unroll
        for (int j = 0; j < 8; j++) {
            acc[j][0] *= sc0; acc[j][1] *= sc0; acc[j][2] *= sc1; acc[j][3] *= sc1;
        }

        // GEMM2: acc += P_h @ V_h (single-term V)
        {
            uint32_t rbase = sb + (uint32_t)((lane & 15) * 144 + ((lane >> 4) << 3) * 2);
#pragma unroll
            for (int ss = 0; ss < 8; ss++) {
#pragma unroll
                for (int jp = 0; jp < 4; jp++) {
                    uint32_t off = (uint32_t)(ss * 2304 + jp * 32);
                    uint32_t vh4[4];
                    LDSM4T(vh4, rbase + curH + off);
                    MMAH(acc[2 * jp], php[ss], vh4[0], vh4[1]);
                    MMAH(acc[2 * jp + 1], php[ss], vh4[2], vh4[3]);
                }
            }
        }
    }

    float inv0 = 1.f / lrow0, inv1 = 1.f / lrow1;
    int r0 = lane >> 2, c0 = (lane & 3) * 2;
    size_t rowA = ((size_t)b * TT + t0 + 16 * w + r0) * MM + h * 64;
    size_t rowB = rowA + 8 * MM;
#pragma unroll
    for (int j = 0; j < 8; j++) {
        float o0 = acc[j][0] * inv0, o1 = acc[j][1] * inv0;
        float o2 = acc[j][2] * inv1, o3 = acc[j][3] * inv1;
        float h0 = hfh(o0), h1 = hfh(o1), h2 = hfh(o2), h3 = hfh(o3);
        size_t ia = rowA + 8 * j + c0, ib = rowB + 8 * j + c0;
        *(uint32_t*)((char*)g_zh + ia * 2) = pkh(h0, h1);
        *(uint32_t*)((char*)g_zl + ia * 2) = pkh(o0 - h0, o1 - h1);
        *(uint32_t*)((char*)g_zh + ib * 2) = pkh(h2, h3);
        *(uint32_t*)((char*)g_zl + ib * 2) = pkh(o2 - h2, o3 - h3);
    }
}

// ---------------------------------------------------------------------------
// Kernel 5: out = z @ U + bo — z fp16-split x U fp16-single (2 MMA terms)
// 128 threads, tile 128x64, k-chunk 64, 2 CTA/SM
// ---------------------------------------------------------------------------
#define GO_SMEM 92160

__global__ void __launch_bounds__(128, 2) gemmOutTC(const float* __restrict__ bo,
                                                    float* __restrict__ out) {
    extern __shared__ __align__(16) char sm[];
    const uint32_t sb = (uint32_t)__cvta_generic_to_shared(sm);
    const uint32_t ZH[2] = {0u, 46080u}, ZL[2] = {18432u, 64512u};
    const uint32_t UH[2] = {36864u, 82944u};
    const int tid = threadIdx.x, lane = tid & 31, w = tid >> 5;
    const int col0 = blockIdx.x * 64, row0 = blockIdx.y * 128;
    const int wr = w * 32;

#pragma unroll
    for (int c = 0; c < 8; c++) {
        int idx = tid + c * 128;
        int r = idx >> 3, ch = idx & 7;
        cpa(sb + ZH[0] + r * 144 + ch * 16, g_zh + (size_t)(row0 + r) * MM + ch * 8);
        cpa(sb + ZL[0] + r * 144 + ch * 16, g_zl + (size_t)(row0 + r) * MM + ch * 8);
    }
#pragma unroll
    for (int c = 0; c < 4; c++) {
        int idx = tid + c * 128;
        int kk = idx >> 3, q = idx & 7;
        cpa(sb + UH[0] + kk * 144 + q * 16, g_Uh + (size_t)kk * MM + col0 + q * 8);
    }
    CPCOMMIT();

    float acc[2][8][4];
#pragma unroll
    for (int rb = 0; rb < 2; rb++)
#pragma unroll
        for (int j = 0; j < 8; j++)
            acc[rb][j][0] = acc[rb][j][1] = acc[rb][j][2] = acc[rb][j][3] = 0.f;

    const uint32_t aro = (uint32_t)((wr + (lane & 15)) * 144 + ((lane >> 4) << 3) * 2);
    const uint32_t bro = (uint32_t)((lane & 15) * 144 + ((lane >> 4) << 3) * 2);

    for (int it = 0; it < 16; it++) {
        const int cur = it & 1, nx = cur ^ 1;
        __syncthreads();
        if (it < 15) {
            int k0 = (it + 1) * 64;
#pragma unroll
            for (int c = 0; c < 8; c++) {
                int idx = tid + c * 128;
                int r = idx >> 3, ch = idx & 7;
                cpa(sb + ZH[nx] + r * 144 + ch * 16,
                    g_zh + (size_t)(row0 + r) * MM + k0 + ch * 8);
                cpa(sb + ZL[nx] + r * 144 + ch * 16,
                    g_zl + (size_t)(row0 + r) * MM + k0 + ch * 8);
            }
#pragma unroll
            for (int c = 0; c < 4; c++) {
                int idx = tid + c * 128;
                int kk = idx >> 3, q = idx & 7;
                cpa(sb + UH[nx] + kk * 144 + q * 16,
                    g_Uh + (size_t)(k0 + kk) * MM + col0 + q * 8);
            }
            CPCOMMIT();
            CPWAIT1();
        } else {
            CPWAIT0();
        }
        __syncthreads();

#pragma unroll
        for (int kk = 0; kk < 4; kk++) {
            uint32_t ah0[4], al0[4], ah1[4], al1[4];
            LDSM4(ah0, sb + ZH[cur] + aro + kk * 32);
            LDSM4(al0, sb + ZL[cur] + aro + kk * 32);
            LDSM4(ah1, sb + ZH[cur] + aro + 2304 + kk * 32);
            LDSM4(al1, sb + ZL[cur] + aro + 2304 + kk * 32);
#pragma unroll
            for (int jp = 0; jp < 4; jp++) {
                uint32_t off = (uint32_t)(kk * 2304 + jp * 32);
                uint32_t bh4[4];
                LDSM4T(bh4, sb + UH[cur] + bro + off);
                MMAH(acc[0][2 * jp], ah0, bh4[0], bh4[1]);
                MMAH(acc[0][2 * jp], al0, bh4[0], bh4[1]);
                MMAH(acc[0][2 * jp + 1], ah0, bh4[2], bh4[3]);
                MMAH(acc[0][2 * jp + 1], al0, bh4[2], bh4[3]);
                MMAH(acc[1][2 * jp], ah1, bh4[0], bh4[1]);
                MMAH(acc[1][2 * jp], al1, bh4[0], bh4[1]);
                MMAH(acc[1][2 * jp + 1], ah1, bh4[2], bh4[3]);
                MMAH(acc[1][2 * jp + 1], al1, bh4[2], bh4[3]);
            }
        }
    }

    int r = lane >> 2, cc = (lane & 3) * 2;
#pragma unroll
    for (int rb = 0; rb < 2; rb++) {
        int gr = row0 + wr + rb * 16 + r;
#pragma unroll
        for (int j = 0; j < 8; j++) {
            int gc = col0 + 8 * j + cc;
            float b0v = bo[gc], b1v = bo[gc + 1];
            *(float2*)(out + (size_t)gr * MM + gc) =
                make_float2(acc[rb][j][0] + b0v, acc[rb][j][1] + b1v);
            *(float2*)(out + (size_t)(gr + 8) * MM + gc) =
                make_float2(acc[rb][j][2] + b0v, acc[rb][j][3] + b1v);
        }
    }
}

// ---------------------------------------------------------------------------
extern "C" void kernel_launch(void* const* d_in, const int* in_sizes, int n_in,
                              void* d_out, int out_size) {
    const float* x  = (const float*)d_in[0];
    const float* Wq = (const float*)d_in[1];
    const float* Wk = (const float*)d_in[2];
    const float* Wv = (const float*)d_in[3];
    const float* Wo = (const float*)d_in[4];
    const float* bo = (const float*)d_in[5];
    float* out = (float*)d_out;

    cudaFuncSetAttribute(flashTC, cudaFuncAttributeMaxDynamicSharedMemorySize, FL_SMEM);
    cudaFuncSetAttribute(gemmOutTC, cudaFuncAttributeMaxDynamicSharedMemorySize, GO_SMEM);
    cudaFuncSetAttribute(computeUTC, cudaFuncAttributeMaxDynamicSharedMemorySize, CU_SMEM);

    splitX<<<4096, 256>>>(x);
    computeApart<<<dim3(16, 8), 256>>>(Wq, Wk);
    reduceA<<<256, 256>>>();
    computeUTC<<<dim3(8, 16, 4), 256, CU_SMEM>>>(Wv, Wo);
    reduceU<<<1024, 256>>>();
    flashTC<<<dim3(TT / 64, BB * HH), 128, FL_SMEM>>>();
    gemmOutTC<<<dim3(MM / 64, (BB * TT) / 128), 128, GO_SMEM>>>(bo, out);
}

// round 12
// speedup vs baseline: 6.4079x; 1.2279x over previous
#include <cuda_runtime.h>
#include <cuda_fp16.h>
#include <math.h>
#include <stdint.h>

#define BB 2
#define TT 2048
#define HH 16
#define DD 64
#define MM 1024

// Persistent scratch (device globals)
__device__ float g_Ap[8 * HH * DD * DD];        // k-split partials for A
__device__ float g_Up[2 * MM * MM];             // k-split partials for U (fp32)
__device__ __half g_Ah[HH * DD * DD];           // A split hi  [h][d][d']
__device__ __half g_Al[HH * DD * DD];           // A split lo
__device__ __half g_xh[BB * HH * TT * DD];      // x per-head, fp16 hi  [bh][t][64]
__device__ __half g_xl[BB * HH * TT * DD];      // x per-head, fp16 lo
__device__ __half g_zh[BB * TT * MM];           // attn out, fp16 hi    [b][t][1024]
__device__ __half g_zl[BB * TT * MM];
__device__ __half g_Uh[MM * MM];                // U = Wv@Wo, fp16 (single)

__device__ __forceinline__ uint32_t pkh(float a, float b) {
    __half2 t = __floats2half2_rn(a, b);
    return *reinterpret_cast<uint32_t*>(&t);
}
__device__ __forceinline__ float hfh(float x) {
    return __half2float(__float2half_rn(x));
}
__device__ __forceinline__ float ex2f(float x) {
    float y;
    asm("ex2.approx.ftz.f32 %0, %1;" : "=f"(y) : "f"(x));
    return y;
}
__device__ __forceinline__ void cpa(uint32_t d, const void* s) {
    asm volatile("cp.async.cg.shared.global [%0], [%1], 16;" :: "r"(d), "l"(s));
}
#define CPCOMMIT() asm volatile("cp.async.commit_group;")
#define CPWAIT1() asm volatile("cp.async.wait_group 1;")
#define CPWAIT0() asm volatile("cp.async.wait_group 0;")

#define LDSM4(R, A) asm volatile( \
    "ldmatrix.sync.aligned.m8n8.x4.shared.b16 {%0,%1,%2,%3},[%4];" \
    : "=r"((R)[0]), "=r"((R)[1]), "=r"((R)[2]), "=r"((R)[3]) : "r"(A))
#define LDSM4T(R, A) asm volatile( \
    "ldmatrix.sync.aligned.m8n8.x4.trans.shared.b16 {%0,%1,%2,%3},[%4];" \
    : "=r"((R)[0]), "=r"((R)[1]), "=r"((R)[2]), "=r"((R)[3]) : "r"(A))
#define MMAH(D, A, B0, B1) asm volatile( \
    "mma.sync.aligned.m16n8k16.row.col.f32.f16.f16.f32 " \
    "{%0,%1,%2,%3},{%4,%5,%6,%7},{%8,%9},{%0,%1,%2,%3};" \
    : "+f"((D)[0]), "+f"((D)[1]), "+f"((D)[2]), "+f"((D)[3]) \
    : "r"((A)[0]), "r"((A)[1]), "r"((A)[2]), "r"((A)[3]), "r"(B0), "r"(B1))

// ---------------------------------------------------------------------------
// Kernel 0: split x into per-head fp16 hi/lo, layout [bh][t][64]
// ---------------------------------------------------------------------------
__global__ void __launch_bounds__(256) splitX(const float* __restrict__ x) {
    int fi = blockIdx.x * 256 + threadIdx.x;
    size_t e = (size_t)fi * 4;
    int b = (int)(e / ((size_t)TT * MM));
    size_t rem = e % ((size_t)TT * MM);
    int t = (int)(rem / MM);
    int col = (int)(rem % MM);
    int h = col >> 6, c = col & 63;
    float4 v = *(const float4*)(x + e);
    float hx = hfh(v.x), hy = hfh(v.y), hz = hfh(v.z), hw = hfh(v.w);
    size_t di = (((size_t)(b * 16 + h) * TT + t) * 64 + c);
    *(uint32_t*)((char*)g_xh + di * 2) = pkh(hx, hy);
    *(uint32_t*)((char*)g_xh + di * 2 + 4) = pkh(hz, hw);
    *(uint32_t*)((char*)g_xl + di * 2) = pkh(v.x - hx, v.y - hy);
    *(uint32_t*)((char*)g_xl + di * 2 + 4) = pkh(v.z - hz, v.w - hw);
}

// ---------------------------------------------------------------------------
// Kernel 1a: partial A; grid (16 h, 8 kseg)
// ---------------------------------------------------------------------------
__global__ void __launch_bounds__(256) computeApart(const float* __restrict__ Wq,
                                                    const float* __restrict__ Wk) {
    const int h = blockIdx.x, ks = blockIdx.y, tid = threadIdx.x;
    const int tx = tid & 15, ty = tid >> 4;
    __shared__ float wqs[64 * 65];
    __shared__ float wks[64 * 65];
    float acc[4][4];
#pragma unroll
    for (int i = 0; i < 4; i++)
#pragma unroll
        for (int j = 0; j < 4; j++) acc[i][j] = 0.f;
    const float* wqh = Wq + (size_t)h * DD * MM;
    const float* wkh = Wk + (size_t)h * DD * MM;
    for (int m0 = ks * 128; m0 < ks * 128 + 128; m0 += 64) {
        __syncthreads();
#pragma unroll
        for (int c = 0; c < 4; c++) {
            int fi = tid + c * 256, i = fi >> 4, q = fi & 15;
            float4 a = *(const float4*)(wqh + i * MM + m0 + q * 4);
            wqs[i * 65 + q * 4 + 0] = a.x; wqs[i * 65 + q * 4 + 1] = a.y;
            wqs[i * 65 + q * 4 + 2] = a.z; wqs[i * 65 + q * 4 + 3] = a.w;
            float4 b = *(const float4*)(wkh + i * MM + m0 + q * 4);
            wks[i * 65 + q * 4 + 0] = b.x; wks[i * 65 + q * 4 + 1] = b.y;
            wks[i * 65 + q * 4 + 2] = b.z; wks[i * 65 + q * 4 + 3] = b.w;
        }
        __syncthreads();
        for (int m = 0; m < 64; m++) {
            float a[4], b[4];
#pragma unroll
            for (int i = 0; i < 4; i++) a[i] = wqs[(ty * 4 + i) * 65 + m];
#pragma unroll
            for (int j = 0; j < 4; j++) b[j] = wks[(tx * 4 + j) * 65 + m];
#pragma unroll
            for (int i = 0; i < 4; i++)
#pragma unroll
                for (int j = 0; j < 4; j++) acc[i][j] += a[i] * b[j];
        }
    }
    float* o = g_Ap + (size_t)ks * (HH * DD * DD) + h * DD * DD;
#pragma unroll
    for (int i = 0; i < 4; i++)
#pragma unroll
        for (int j = 0; j < 4; j++)
            o[(ty * 4 + i) * DD + tx * 4 + j] = acc[i][j];
}

// Kernel 1b: reduce partials, scale, split to fp16 hi/lo
__global__ void __launch_bounds__(256) reduceA() {
    int i = blockIdx.x * 256 + threadIdx.x;
    float s = 0.f;
#pragma unroll
    for (int k = 0; k < 8; k++) s += g_Ap[(size_t)k * (HH * DD * DD) + i];
    s *= (0.125f * 1.4426950408889634f);
    float hv = hfh(s);
    g_Ah[i] = __float2half_rn(s);
    g_Al[i] = __float2half_rn(s - hv);
}

// ---------------------------------------------------------------------------
// Kernel 2a: U partials — Wv fp16-split x Wo fp16-single, k-split x2
// grid (8 col-tiles, 16 h, 2 ks), 256 threads; tile 64x128, k-range 512
// ---------------------------------------------------------------------------
#define CU_SMEM 37888

__global__ void __launch_bounds__(256, 1) computeUTC(const float* __restrict__ Wv,
                                                     const float* __restrict__ Wo) {
    extern __shared__ __align__(16) char sm[];
    const uint32_t sb = (uint32_t)__cvta_generic_to_shared(sm);
    const uint32_t AH[2] = {0u, 18944u}, AL[2] = {5120u, 24064u};
    const uint32_t BH[2] = {10240u, 29184u};
    const int tid = threadIdx.x, lane = tid & 31, w = tid >> 5;
    const int h = blockIdx.y, col0 = blockIdx.x * 128, ks = blockIdx.z;
    const int kbase = ks * 512;
    const int wr = (w & 3) * 16, wc = (w >> 2) * 64;
    const float* wvh = Wv + (size_t)h * DD * MM;
    const float* woh = Wo + (size_t)h * MM * MM;

#pragma unroll
    for (int c = 0; c < 2; c++) {
        int idx = tid + c * 256;
        int r = idx >> 3, kq = idx & 7;
        float4 v = *(const float4*)(wvh + (size_t)r * MM + kbase + kq * 4);
        float hx = hfh(v.x), hy = hfh(v.y), hz = hfh(v.z), hw = hfh(v.w);
        uint32_t o = (uint32_t)(r * 80 + kq * 8);
        *(uint32_t*)(sm + AH[0] + o) = pkh(hx, hy);
        *(uint32_t*)(sm + AH[0] + o + 4) = pkh(hz, hw);
        *(uint32_t*)(sm + AL[0] + o) = pkh(v.x - hx, v.y - hy);
        *(uint32_t*)(sm + AL[0] + o + 4) = pkh(v.z - hz, v.w - hw);
    }
#pragma unroll
    for (int c = 0; c < 4; c++) {
        int fi = tid + c * 256;
        int kk = fi >> 5, q = fi & 31;
        float4 v = *(const float4*)(woh + (size_t)(kbase + kk) * MM + col0 + q * 4);
        uint32_t o = (uint32_t)(kk * 272 + q * 8);
        *(uint32_t*)(sm + BH[0] + o) = pkh(v.x, v.y);
        *(uint32_t*)(sm + BH[0] + o + 4) = pkh(v.z, v.w);
    }
    __syncthreads();

    float acc[8][4];
#pragma unroll
    for (int j = 0; j < 8; j++)
        acc[j][0] = acc[j][1] = acc[j][2] = acc[j][3] = 0.f;

    const uint32_t aro = (uint32_t)((wr + (lane & 15)) * 80 + ((lane >> 4) << 3) * 2);
    const uint32_t bro = (uint32_t)((lane & 15) * 272 + (wc + ((lane >> 4) << 3)) * 2);

    for (int it = 0; it < 16; it++) {
        const int cur = it & 1, nx = cur ^ 1;
        float4 pv[2], po[4];
        if (it < 15) {
            int m0 = kbase + (it + 1) * 32;
#pragma unroll
            for (int c = 0; c < 2; c++) {
                int idx = tid + c * 256;
                int r = idx >> 3, kq = idx & 7;
                pv[c] = *(const float4*)(wvh + (size_t)r * MM + m0 + kq * 4);
            }
#pragma unroll
            for (int c = 0; c < 4; c++) {
                int fi = tid + c * 256;
                int kk = fi >> 5, q = fi & 31;
                po[c] = *(const float4*)(woh + (size_t)(m0 + kk) * MM + col0 + q * 4);
            }
        }

#pragma unroll
        for (int kk = 0; kk < 2; kk++) {
            uint32_t ah4[4], al4[4];
            LDSM4(ah4, sb + AH[cur] + aro + kk * 32);
            LDSM4(al4, sb + AL[cur] + aro + kk * 32);
#pragma unroll
            for (int jp = 0; jp < 4; jp++) {
                uint32_t off = (uint32_t)(kk * 4352 + jp * 32);
                uint32_t bh4[4];
                LDSM4T(bh4, sb + BH[cur] + bro + off);
                MMAH(acc[2 * jp], ah4, bh4[0], bh4[1]);
                MMAH(acc[2 * jp], al4, bh4[0], bh4[1]);
                MMAH(acc[2 * jp + 1], ah4, bh4[2], bh4[3]);
                MMAH(acc[2 * jp + 1], al4, bh4[2], bh4[3]);
            }
        }

        if (it < 15) {
#pragma unroll
            for (int c = 0; c < 2; c++) {
                int idx = tid + c * 256;
                int r = idx >> 3, kq = idx & 7;
                float4 v = pv[c];
                float hx = hfh(v.x), hy = hfh(v.y), hz = hfh(v.z), hw = hfh(v.w);
                uint32_t o = (uint32_t)(r * 80 + kq * 8);
                *(uint32_t*)(sm + AH[nx] + o) = pkh(hx, hy);
                *(uint32_t*)(sm + AH[nx] + o + 4) = pkh(hz, hw);
                *(uint32_t*)(sm + AL[nx] + o) = pkh(v.x - hx, v.y - hy);
                *(uint32_t*)(sm + AL[nx] + o + 4) = pkh(v.z - hz, v.w - hw);
            }
#pragma unroll
            for (int c = 0; c < 4; c++) {
                int fi = tid + c * 256;
                int kk = fi >> 5, q = fi & 31;
                float4 v = po[c];
                uint32_t o = (uint32_t)(kk * 272 + q * 8);
                *(uint32_t*)(sm + BH[nx] + o) = pkh(v.x, v.y);
                *(uint32_t*)(sm + BH[nx] + o + 4) = pkh(v.z, v.w);
            }
        }
        __syncthreads();
    }

    float* up = g_Up + (size_t)ks * MM * MM;
    int r = lane >> 2, cc = (lane & 3) * 2;
    int row = h * 64 + wr + r;
#pragma unroll
    for (int j = 0; j < 8; j++) {
        int gc = col0 + wc + 8 * j + cc;
        *(float2*)(up + (size_t)row * MM + gc) = make_float2(acc[j][0], acc[j][1]);
        *(float2*)(up + (size_t)(row + 8) * MM + gc) = make_float2(acc[j][2], acc[j][3]);
    }
}

// Kernel 2b: reduce U partials -> single fp16
__global__ void __launch_bounds__(256) reduceU() {
    size_t i = ((size_t)blockIdx.x * 256 + threadIdx.x) * 4;
    float4 s = *(const float4*)(g_Up + i);
    float4 t = *(const float4*)(g_Up + (size_t)MM * MM + i);
    s.x += t.x; s.y += t.y; s.z += t.z; s.w += t.w;
    *(uint32_t*)((char*)g_Uh + i * 2) = pkh(s.x, s.y);
    *(uint32_t*)((char*)g_Uh + i * 2 + 4) = pkh(s.z, s.w);
}

// ---------------------------------------------------------------------------
// Kernel 4: flash attention — 64-key tiles, K hi-only, 3 CTAs/SM
// GEMM1 2-term (qh,ql x kh); GEMM2 P x V_h. 128 threads, 36.9KB smem.
// ---------------------------------------------------------------------------
#define FL_SMEM 36864

__global__ void __launch_bounds__(128, 3) flashTC() {
    extern __shared__ __align__(16) char sm[];
    const uint32_t sb = (uint32_t)__cvta_generic_to_shared(sm);
    const uint32_t KH0 = 0u, KH1 = 9216u;
    const uint32_t XH = 0u, XL = 9216u, AHs = 18432u, ALs = 27648u;
    const int tid = threadIdx.x, lane = tid & 31, w = tid >> 5;
    const int t0 = blockIdx.x * 64, bh = blockIdx.y;
    const int b = bh >> 4, h = bh & 15;

    const __half* xh = g_xh + (size_t)bh * TT * 64;
    const __half* xl = g_xl + (size_t)bh * TT * 64;

    // Prologue 1: x rows (Q source) hi/lo + A hi/lo
    {
        const __half* Ah = g_Ah + (size_t)h * DD * DD;
        const __half* Al = g_Al + (size_t)h * DD * DD;
#pragma unroll
        for (int c = 0; c < 4; c++) {
            int idx = tid + c * 128;       // 0..511
            int r = idx >> 3, ch = idx & 7;
            cpa(sb + XH + r * 144 + ch * 16, xh + (size_t)(t0 + r) * 64 + ch * 8);
            cpa(sb + XL + r * 144 + ch * 16, xl + (size_t)(t0 + r) * 64 + ch * 8);
            cpa(sb + AHs + r * 144 + ch * 16, Ah + (size_t)r * 64 + ch * 8);
            cpa(sb + ALs + r * 144 + ch * 16, Al + (size_t)r * 64 + ch * 8);
        }
        CPCOMMIT();
        CPWAIT0();
        __syncthreads();
    }

    // Prologue 2: Q = x @ A (fp16x3), C-frags -> A-frags
    uint32_t qh[4][4], ql[4][4];
    {
        float QS[8][4];
#pragma unroll
        for (int j = 0; j < 8; j++) { QS[j][0] = QS[j][1] = QS[j][2] = QS[j][3] = 0.f; }
        uint32_t xro = (uint32_t)((16 * w + (lane & 15)) * 144 + ((lane >> 4) << 3) * 2);
        uint32_t aro = (uint32_t)((lane & 15) * 144 + ((lane >> 4) << 3) * 2);
#pragma unroll
        for (int kk = 0; kk < 4; kk++) {
            uint32_t xh4[4], xl4[4];
            LDSM4(xh4, sb + XH + xro + kk * 32);
            LDSM4(xl4, sb + XL + xro + kk * 32);
#pragma unroll
            for (int jp = 0; jp < 4; jp++) {
                uint32_t off = (uint32_t)(kk * 2304 + jp * 32);
                uint32_t bh4[4], bl4[4];
                LDSM4T(bh4, sb + AHs + aro + off);
                LDSM4T(bl4, sb + ALs + aro + off);
                MMAH(QS[2 * jp], xh4, bh4[0], bh4[1]);
                MMAH(QS[2 * jp], xh4, bl4[0], bl4[1]);
                MMAH(QS[2 * jp], xl4, bh4[0], bh4[1]);
                MMAH(QS[2 * jp + 1], xh4, bh4[2], bh4[3]);
                MMAH(QS[2 * jp + 1], xh4, bl4[2], bl4[3]);
                MMAH(QS[2 * jp + 1], xl4, bh4[2], bh4[3]);
            }
        }
#pragma unroll
        for (int j = 0; j < 8; j++) {
            float q0 = QS[j][0], q1 = QS[j][1], q2 = QS[j][2], q3 = QS[j][3];
            float h0 = hfh(q0), h1 = hfh(q1), h2 = hfh(q2), h3 = hfh(q3);
            int kkq = j >> 1, ps = (j & 1) << 1;
            qh[kkq][ps] = pkh(h0, h1);
            qh[kkq][ps + 1] = pkh(h2, h3);
            ql[kkq][ps] = pkh(q0 - h0, q1 - h1);
            ql[kkq][ps + 1] = pkh(q2 - h2, q3 - h3);
        }
    }
    __syncthreads();   // all warps done reading prologue regions

    // Prologue 3: K tile 0 (64 keys, hi only) -> KH0
#pragma unroll
    for (int c = 0; c < 4; c++) {
        int idx = tid + c * 128;
        int r = idx >> 3, ch = idx & 7;
        cpa(sb + KH0 + r * 144 + ch * 16, xh + (size_t)r * 64 + ch * 8);
    }
    CPCOMMIT();

    float acc[8][4];
    float mrow0 = -INFINITY, mrow1 = -INFINITY, lrow0 = 0.f, lrow1 = 0.f;
#pragma unroll
    for (int j = 0; j < 8; j++) { acc[j][0] = acc[j][1] = acc[j][2] = acc[j][3] = 0.f; }

    const uint32_t rbase1 = sb + (uint32_t)(((lane & 7) + ((lane >> 4) << 3)) * 144 +
                                            (((lane >> 3) & 1) << 3) * 2);
    const uint32_t rbase2 = sb + (uint32_t)((lane & 15) * 144 + ((lane >> 4) << 3) * 2);

    for (int it = 0; it < 32; it++) {
        const uint32_t curH = (it & 1) ? KH1 : KH0;
        const uint32_t nxtH = (it & 1) ? KH0 : KH1;

        __syncthreads();
        if (it < 31) {
            int s0 = (it + 1) * 64;
#pragma unroll
            for (int c = 0; c < 4; c++) {
                int idx = tid + c * 128;
                int r = idx >> 3, ch = idx & 7;
                cpa(sb + nxtH + r * 144 + ch * 16, xh + (size_t)(s0 + r) * 64 + ch * 8);
            }
            CPCOMMIT();
            CPWAIT1();
        } else {
            CPWAIT0();
        }
        __syncthreads();

        // GEMM1: S(16x64) = Q @ K^T, 2 terms
        float S[8][4];
#pragma unroll
        for (int j = 0; j < 8; j++) { S[j][0] = S[j][1] = S[j][2] = S[j][3] = 0.f; }
#pragma unroll
        for (int jp = 0; jp < 4; jp++) {
#pragma unroll
            for (int kk = 0; kk < 4; kk++) {
                uint32_t off = (uint32_t)(jp * 2304 + kk * 32);
                uint32_t bh4[4];
                LDSM4(bh4, rbase1 + curH + off);
                MMAH(S[2 * jp], qh[kk], bh4[0], bh4[1]);
                MMAH(S[2 * jp], ql[kk], bh4[0], bh4[1]);
                MMAH(S[2 * jp + 1], qh[kk], bh4[2], bh4[3]);
                MMAH(S[2 * jp + 1], ql[kk], bh4[2], bh4[3]);
            }
        }

        // online softmax (base-2)
        float mx0 = -INFINITY, mx1 = -INFINITY;
#pragma unroll
        for (int j = 0; j < 8; j++) {
            mx0 = fmaxf(mx0, fmaxf(S[j][0], S[j][1]));
            mx1 = fmaxf(mx1, fmaxf(S[j][2], S[j][3]));
        }
        mx0 = fmaxf(mx0, __shfl_xor_sync(0xffffffffu, mx0, 1));
        mx0 = fmaxf(mx0, __shfl_xor_sync(0xffffffffu, mx0, 2));
        mx1 = fmaxf(mx1, __shfl_xor_sync(0xffffffffu, mx1, 1));
        mx1 = fmaxf(mx1, __shfl_xor_sync(0xffffffffu, mx1, 2));
        float mn0 = fmaxf(mrow0, mx0), mn1 = fmaxf(mrow1, mx1);
        float sc0 = ex2f(mrow0 - mn0), sc1 = ex2f(mrow1 - mn1);
        mrow0 = mn0; mrow1 = mn1;

        uint32_t php[4][4];
        float rs0 = 0.f, rs1 = 0.f;
#pragma unroll
        for (int j = 0; j < 8; j++) {
            float p0 = ex2f(S[j][0] - mn0), p1 = ex2f(S[j][1] - mn0);
            float p2 = ex2f(S[j][2] - mn1), p3 = ex2f(S[j][3] - mn1);
            rs0 += p0 + p1; rs1 += p2 + p3;
            int ss = j >> 1, ps = (j & 1) << 1;
            php[ss][ps] = pkh(p0, p1);
            php[ss][ps + 1] = pkh(p2, p3);
        }
        rs0 += __shfl_xor_sync(0xffffffffu, rs0, 1);
        rs0 += __shfl_xor_sync(0xffffffffu, rs0, 2);
        rs1 += __shfl_xor_sync(0xffffffffu, rs1, 1);
        rs1 += __shfl_xor_sync(0xffffffffu, rs1, 2);
        lrow0 = lrow0 * sc0 + rs0;
        lrow1 = lrow1 * sc1 + rs1;
#pragma unroll
        for (int j = 0; j < 8; j++) {
            acc[j][0] *= sc0; acc[j][1] *= sc0; acc[j][2] *= sc1; acc[j][3] *= sc1;
        }

        // GEMM2: acc += P @ V_h (V = K tile)
#pragma unroll
        for (int ss = 0; ss < 4; ss++) {
#pragma unroll
            for (int jp = 0; jp < 4; jp++) {
                uint32_t off = (uint32_t)(ss * 2304 + jp * 32);
                uint32_t vh4[4];
                LDSM4T(vh4, rbase2 + curH + off);
                MMAH(acc[2 * jp], php[ss], vh4[0], vh4[1]);
                MMAH(acc[2 * jp + 1], php[ss], vh4[2], vh4[3]);
            }
        }
    }

    float inv0 = 1.f / lrow0, inv1 = 1.f / lrow1;
    int r0 = lane >> 2, c0 = (lane & 3) * 2;
    size_t rowA = ((size_t)b * TT + t0 + 16 * w + r0) * MM + h * 64;
    size_t rowB = rowA + 8 * MM;
#pragma unroll
    for (int j = 0; j < 8; j++) {
        float o0 = acc[j][0] * inv0, o1 = acc[j][1] * inv0;
        float o2 = acc[j][2] * inv1, o3 = acc[j][3] * inv1;
        float h0 = hfh(o0), h1 = hfh(o1), h2 = hfh(o2), h3 = hfh(o3);
        size_t ia = rowA + 8 * j + c0, ib = rowB + 8 * j + c0;
        *(uint32_t*)((char*)g_zh + ia * 2) = pkh(h0, h1);
        *(uint32_t*)((char*)g_zl + ia * 2) = pkh(o0 - h0, o1 - h1);
        *(uint32_t*)((char*)g_zh + ib * 2) = pkh(h2, h3);
        *(uint32_t*)((char*)g_zl + ib * 2) = pkh(o2 - h2, o3 - h3);
    }
}

// ---------------------------------------------------------------------------
// Kernel 5: out = z @ U + bo — z fp16-split x U fp16-single (2 MMA terms)
// 128 threads, tile 128x64, k-chunk 64, 2 CTA/SM
// ---------------------------------------------------------------------------
#define GO_SMEM 92160

__global__ void __launch_bounds__(128, 2) gemmOutTC(const float* __restrict__ bo,
                                                    float* __restrict__ out) {
    extern __shared__ __align__(16) char sm[];
    const uint32_t sb = (uint32_t)__cvta_generic_to_shared(sm);
    const uint32_t ZH[2] = {0u, 46080u}, ZL[2] = {18432u, 64512u};
    const uint32_t UH[2] = {36864u, 82944u};
    const int tid = threadIdx.x, lane = tid & 31, w = tid >> 5;
    const int col0 = blockIdx.x * 64, row0 = blockIdx.y * 128;
    const int wr = w * 32;

#pragma unroll
    for (int c = 0; c < 8; c++) {
        int idx = tid + c * 128;
        int r = idx >> 3, ch = idx & 7;
        cpa(sb + ZH[0] + r * 144 + ch * 16, g_zh + (size_t)(row0 + r) * MM + ch * 8);
        cpa(sb + ZL[0] + r * 144 + ch * 16, g_zl + (size_t)(row0 + r) * MM + ch * 8);
    }
#pragma unroll
    for (int c = 0; c < 4; c++) {
        int idx = tid + c * 128;
        int kk = idx >> 3, q = idx & 7;
        cpa(sb + UH[0] + kk * 144 + q * 16, g_Uh + (size_t)kk * MM + col0 + q * 8);
    }
    CPCOMMIT();

    float acc[2][8][4];
#pragma unroll
    for (int rb = 0; rb < 2; rb++)
#pragma unroll
        for (int j = 0; j < 8; j++)
            acc[rb][j][0] = acc[rb][j][1] = acc[rb][j][2] = acc[rb][j][3] = 0.f;

    const uint32_t aro = (uint32_t)((wr + (lane & 15)) * 144 + ((lane >> 4) << 3) * 2);
    const uint32_t bro = (uint32_t)((lane & 15) * 144 + ((lane >> 4) << 3) * 2);

    for (int it = 0; it < 16; it++) {
        const int cur = it & 1, nx = cur ^ 1;
        __syncthreads();
        if (it < 15) {
            int k0 = (it + 1) * 64;
#pragma unroll
            for (int c = 0; c < 8; c++) {
                int idx = tid + c * 128;
                int r = idx >> 3, ch = idx & 7;
                cpa(sb + ZH[nx] + r * 144 + ch * 16,
                    g_zh + (size_t)(row0 + r) * MM + k0 + ch * 8);
                cpa(sb + ZL[nx] + r * 144 + ch * 16,
                    g_zl + (size_t)(row0 + r) * MM + k0 + ch * 8);
            }
#pragma unroll
            for (int c = 0; c < 4; c++) {
                int idx = tid + c * 128;
                int kk = idx >> 3, q = idx & 7;
                cpa(sb + UH[nx] + kk * 144 + q * 16,
                    g_Uh + (size_t)(k0 + kk) * MM + col0 + q * 8);
            }
            CPCOMMIT();
            CPWAIT1();
        } else {
            CPWAIT0();
        }
        __syncthreads();

#pragma unroll
        for (int kk = 0; kk < 4; kk++) {
            uint32_t ah0[4], al0[4], ah1[4], al1[4];
            LDSM4(ah0, sb + ZH[cur] + aro + kk * 32);
            LDSM4(al0, sb + ZL[cur] + aro + kk * 32);
            LDSM4(ah1, sb + ZH[cur] + aro + 2304 + kk * 32);
            LDSM4(al1, sb + ZL[cur] + aro + 2304 + kk * 32);
#pragma unroll
            for (int jp = 0; jp < 4; jp++) {
                uint32_t off = (uint32_t)(kk * 2304 + jp * 32);
                uint32_t bh4[4];
                LDSM4T(bh4, sb + UH[cur] + bro + off);
                MMAH(acc[0][2 * jp], ah0, bh4[0], bh4[1]);
                MMAH(acc[0][2 * jp], al0, bh4[0], bh4[1]);
                MMAH(acc[0][2 * jp + 1], ah0, bh4[2], bh4[3]);
                MMAH(acc[0][2 * jp + 1], al0, bh4[2], bh4[3]);
                MMAH(acc[1][2 * jp], ah1, bh4[0], bh4[1]);
                MMAH(acc[1][2 * jp], al1, bh4[0], bh4[1]);
                MMAH(acc[1][2 * jp + 1], ah1, bh4[2], bh4[3]);
                MMAH(acc[1][2 * jp + 1], al1, bh4[2], bh4[3]);
            }
        }
    }

    int r = lane >> 2, cc = (lane & 3) * 2;
#pragma unroll
    for (int rb = 0; rb < 2; rb++) {
        int gr = row0 + wr + rb * 16 + r;
#pragma unroll
        for (int j = 0; j < 8; j++) {
            int gc = col0 + 8 * j + cc;
            float b0v = bo[gc], b1v = bo[gc + 1];
            *(float2*)(out + (size_t)gr * MM + gc) =
                make_float2(acc[rb][j][0] + b0v, acc[rb][j][1] + b1v);
            *(float2*)(out + (size_t)(gr + 8) * MM + gc) =
                make_float2(acc[rb][j][2] + b0v, acc[rb][j][3] + b1v);
        }
    }
}

// ---------------------------------------------------------------------------
extern "C" void kernel_launch(void* const* d_in, const int* in_sizes, int n_in,
                              void* d_out, int out_size) {
    const float* x  = (const float*)d_in[0];
    const float* Wq = (const float*)d_in[1];
    const float* Wk = (const float*)d_in[2];
    const float* Wv = (const float*)d_in[3];
    const float* Wo = (const float*)d_in[4];
    const float* bo = (const float*)d_in[5];
    float* out = (float*)d_out;

    cudaFuncSetAttribute(flashTC, cudaFuncAttributeMaxDynamicSharedMemorySize, FL_SMEM);
    cudaFuncSetAttribute(gemmOutTC, cudaFuncAttributeMaxDynamicSharedMemorySize, GO_SMEM);
    cudaFuncSetAttribute(computeUTC, cudaFuncAttributeMaxDynamicSharedMemorySize, CU_SMEM);

    splitX<<<4096, 256>>>(x);
    computeApart<<<dim3(16, 8), 256>>>(Wq, Wk);
    reduceA<<<256, 256>>>();
    computeUTC<<<dim3(8, 16, 2), 256, CU_SMEM>>>(Wv, Wo);
    reduceU<<<1024, 256>>>();
    flashTC<<<dim3(TT / 64, BB * HH), 128, FL_SMEM>>>();
    gemmOutTC<<<dim3(MM / 64, (BB * TT) / 128), 128, GO_SMEM>>>(bo, out);
}